// round 1
// baseline (speedup 1.0000x reference)
#include <cuda_runtime.h>

#define B_  4
#define T_  2048
#define C_  1024
#define NH_ 16
#define D_  64
#define M_  (B_*T_)

#define AS 68   // padded smem row stride (floats) for attention tiles
#define ATT_SMEM ((4*64*AS)*4 + 64*4)

// Scratch (static device globals — no allocation at runtime)
__device__ float g_q[M_*C_];
__device__ float g_k[M_*C_];
__device__ float g_v[M_*C_];
__device__ float g_a[M_*C_];

// ---------------------------------------------------------------------------
// GEMM core: out[m][n] = sum_k A[m][k] * W[n][k] + bias[n]   (x @ W^T + b)
// M tiled by blockIdx.y (128), N tiled by blockIdx.x (128). K = N = C_ = 1024.
// 256 threads, 8x8 micro-tile per thread with split 4+64 fragment layout.
// ---------------------------------------------------------------------------
__device__ __forceinline__ void gemm_tile(
    const float* __restrict__ A, const float* __restrict__ W,
    const float* __restrict__ bias, float* __restrict__ out)
{
    __shared__ float As[8][132];
    __shared__ float Bs[8][132];

    const int tid  = threadIdx.x;
    const int tx   = tid & 15;
    const int ty   = tid >> 4;
    const int row0 = blockIdx.y * 128;
    const int col0 = blockIdx.x * 128;

    const int lr = tid >> 1;          // 0..127
    const int lk = (tid & 1) << 2;    // 0 or 4

    const float* Ap = A + (row0 + lr) * C_ + lk;
    const float* Wp = W + (col0 + lr) * C_ + lk;

    float acc[8][8];
    #pragma unroll
    for (int i = 0; i < 8; i++)
        #pragma unroll
        for (int j = 0; j < 8; j++) acc[i][j] = 0.f;

    for (int k0 = 0; k0 < C_; k0 += 8) {
        float4 a = *(const float4*)(Ap + k0);
        float4 b = *(const float4*)(Wp + k0);
        As[lk+0][lr] = a.x; As[lk+1][lr] = a.y; As[lk+2][lr] = a.z; As[lk+3][lr] = a.w;
        Bs[lk+0][lr] = b.x; Bs[lk+1][lr] = b.y; Bs[lk+2][lr] = b.z; Bs[lk+3][lr] = b.w;
        __syncthreads();
        #pragma unroll
        for (int kk = 0; kk < 8; kk++) {
            float af[8], bf[8];
            *(float4*)&af[0] = *(const float4*)&As[kk][ty*4];
            *(float4*)&af[4] = *(const float4*)&As[kk][64 + ty*4];
            *(float4*)&bf[0] = *(const float4*)&Bs[kk][tx*4];
            *(float4*)&bf[4] = *(const float4*)&Bs[kk][64 + tx*4];
            #pragma unroll
            for (int i = 0; i < 8; i++)
                #pragma unroll
                for (int j = 0; j < 8; j++)
                    acc[i][j] += af[i] * bf[j];
        }
        __syncthreads();
    }

    float bb[8];
    *(float4*)&bb[0] = *(const float4*)&bias[col0 + tx*4];
    *(float4*)&bb[4] = *(const float4*)&bias[col0 + 64 + tx*4];

    #pragma unroll
    for (int i = 0; i < 8; i++) {
        const int r = row0 + ((i < 4) ? (ty*4 + i) : (64 + ty*4 + (i - 4)));
        float4 o0 = make_float4(acc[i][0]+bb[0], acc[i][1]+bb[1],
                                acc[i][2]+bb[2], acc[i][3]+bb[3]);
        float4 o1 = make_float4(acc[i][4]+bb[4], acc[i][5]+bb[5],
                                acc[i][6]+bb[6], acc[i][7]+bb[7]);
        *(float4*)&out[r * C_ + col0 + tx*4]      = o0;
        *(float4*)&out[r * C_ + col0 + 64 + tx*4] = o1;
    }
}

__global__ void __launch_bounds__(256) qkv_kernel(
    const float* __restrict__ x,
    const float* __restrict__ wq, const float* __restrict__ bq,
    const float* __restrict__ wk, const float* __restrict__ bk,
    const float* __restrict__ wv, const float* __restrict__ bv)
{
    const int sel = blockIdx.z;
    const float* W    = (sel == 0) ? wq : (sel == 1) ? wk : wv;
    const float* bias = (sel == 0) ? bq : (sel == 1) ? bk : bv;
    float* out        = (sel == 0) ? g_q : (sel == 1) ? g_k : g_v;
    gemm_tile(x, W, bias, out);
}

__global__ void __launch_bounds__(256) proj_kernel(
    const float* __restrict__ wp, const float* __restrict__ bp,
    float* __restrict__ out)
{
    gemm_tile(g_a, wp, bp, out);
}

// ---------------------------------------------------------------------------
// Attention: one CTA per (b, head, 64-row q tile). Online (flash) softmax.
// Causal + token mask. fp32. 256 threads: thread (tr,tc) owns a 4x4 micro-tile
// of the 64x64 S / O tiles (rows tr*4.., cols tc*4..).
// ---------------------------------------------------------------------------
__global__ void __launch_bounds__(256) attn_kernel(const int* __restrict__ tmask)
{
    extern __shared__ float sm[];
    float* QsT = sm;               // [64][AS]  Q^T (QsT[d*AS + r]), pre-scaled by 1/8
    float* KsT = sm + 64*AS;       // [64][AS]  K^T (KsT[d*AS + j])
    float* Vs  = sm + 2*64*AS;     // [64][AS]  V   (Vs[j*AS + d])
    float* PsT = sm + 3*64*AS;     // [64][AS]  P^T (PsT[j*AS + r])
    int*   Ms  = (int*)(sm + 4*64*AS);

    const int qt = blockIdx.x;     // q tile 0..31
    const int h  = blockIdx.y;
    const int b  = blockIdx.z;
    const int q0 = qt * 64;

    const int tid = threadIdx.x;
    const int tc  = tid & 15;
    const int tr  = tid >> 4;
    const int rowBase = b * T_;
    const int hc = h * D_;

    // Load Q tile transposed, fold in 1/sqrt(D) = 0.125
    #pragma unroll
    for (int it = 0; it < 4; it++) {
        const int idx = tid + it * 256;
        const int r  = idx >> 4;
        const int d4 = (idx & 15) << 2;
        float4 qv = *(const float4*)&g_q[(rowBase + q0 + r) * C_ + hc + d4];
        QsT[(d4+0)*AS + r] = qv.x * 0.125f;
        QsT[(d4+1)*AS + r] = qv.y * 0.125f;
        QsT[(d4+2)*AS + r] = qv.z * 0.125f;
        QsT[(d4+3)*AS + r] = qv.w * 0.125f;
    }

    float o[4][4];
    float mrow[4], lrow[4];
    #pragma unroll
    for (int i = 0; i < 4; i++) {
        mrow[i] = -1e30f; lrow[i] = 0.f;
        #pragma unroll
        for (int j = 0; j < 4; j++) o[i][j] = 0.f;
    }

    for (int kt = 0; kt <= qt; kt++) {
        const int k0 = kt * 64;
        __syncthreads();   // previous-iter PV reads done (also covers QsT on iter 0)

        // Load K^T, V, mask tile
        #pragma unroll
        for (int it = 0; it < 4; it++) {
            const int idx = tid + it * 256;
            const int r  = idx >> 4;
            const int d4 = (idx & 15) << 2;
            float4 kv = *(const float4*)&g_k[(rowBase + k0 + r) * C_ + hc + d4];
            KsT[(d4+0)*AS + r] = kv.x;
            KsT[(d4+1)*AS + r] = kv.y;
            KsT[(d4+2)*AS + r] = kv.z;
            KsT[(d4+3)*AS + r] = kv.w;
            float4 vv = *(const float4*)&g_v[(rowBase + k0 + r) * C_ + hc + d4];
            *(float4*)&Vs[r*AS + d4] = vv;
        }
        if (tid < 64) Ms[tid] = tmask[b * T_ + k0 + tid];
        __syncthreads();

        // S = (Q/8) K^T  -> s[4][4]
        float s[4][4];
        #pragma unroll
        for (int i = 0; i < 4; i++)
            #pragma unroll
            for (int j = 0; j < 4; j++) s[i][j] = 0.f;

        #pragma unroll
        for (int d0 = 0; d0 < 64; d0 += 4) {
            #pragma unroll
            for (int c = 0; c < 4; c++) {
                float a4[4], b4[4];
                *(float4*)a4 = *(const float4*)&QsT[(d0+c)*AS + tr*4];
                *(float4*)b4 = *(const float4*)&KsT[(d0+c)*AS + tc*4];
                #pragma unroll
                for (int i = 0; i < 4; i++)
                    #pragma unroll
                    for (int j = 0; j < 4; j++)
                        s[i][j] += a4[i] * b4[j];
            }
        }

        // Masking: token mask always, causal only on diagonal tile (k0 == q0)
        const bool diag = (kt == qt);
        #pragma unroll
        for (int j = 0; j < 4; j++) {
            const int kc = tc*4 + j;
            const bool mok = (Ms[kc] != 0);
            #pragma unroll
            for (int i = 0; i < 4; i++) {
                const bool ok = mok && (!diag || (kc <= tr*4 + i));
                if (!ok) s[i][j] = -1e30f;
            }
        }

        // Online softmax (row groups of 16 lanes: lane = (tr&1)*16 + tc)
        #pragma unroll
        for (int i = 0; i < 4; i++) {
            float mx = fmaxf(fmaxf(s[i][0], s[i][1]), fmaxf(s[i][2], s[i][3]));
            mx = fmaxf(mx, __shfl_xor_sync(0xffffffffu, mx, 1));
            mx = fmaxf(mx, __shfl_xor_sync(0xffffffffu, mx, 2));
            mx = fmaxf(mx, __shfl_xor_sync(0xffffffffu, mx, 4));
            mx = fmaxf(mx, __shfl_xor_sync(0xffffffffu, mx, 8));
            const float mnew = fmaxf(mrow[i], mx);
            const float corr = __expf(mrow[i] - mnew);
            mrow[i] = mnew;
            float ls = 0.f;
            #pragma unroll
            for (int j = 0; j < 4; j++) {
                s[i][j] = __expf(s[i][j] - mnew);
                ls += s[i][j];
            }
            ls += __shfl_xor_sync(0xffffffffu, ls, 1);
            ls += __shfl_xor_sync(0xffffffffu, ls, 2);
            ls += __shfl_xor_sync(0xffffffffu, ls, 4);
            ls += __shfl_xor_sync(0xffffffffu, ls, 8);
            lrow[i] = lrow[i] * corr + ls;
            #pragma unroll
            for (int j = 0; j < 4; j++) o[i][j] *= corr;
        }

        // Store P transposed: PsT[j][r]
        #pragma unroll
        for (int j = 0; j < 4; j++) {
            float4 pv = make_float4(s[0][j], s[1][j], s[2][j], s[3][j]);
            *(float4*)&PsT[(tc*4 + j)*AS + tr*4] = pv;
        }
        __syncthreads();

        // O += P V
        #pragma unroll
        for (int j0 = 0; j0 < 64; j0 += 4) {
            #pragma unroll
            for (int c = 0; c < 4; c++) {
                float a4[4], b4[4];
                *(float4*)a4 = *(const float4*)&PsT[(j0+c)*AS + tr*4];
                *(float4*)b4 = *(const float4*)&Vs[(j0+c)*AS + tc*4];
                #pragma unroll
                for (int i = 0; i < 4; i++)
                    #pragma unroll
                    for (int j = 0; j < 4; j++)
                        o[i][j] += a4[i] * b4[j];
            }
        }
    }

    // Normalize and write attn output (pre-projection) to scratch
    #pragma unroll
    for (int i = 0; i < 4; i++) {
        const float inv = 1.f / lrow[i];
        float4 ov = make_float4(o[i][0]*inv, o[i][1]*inv, o[i][2]*inv, o[i][3]*inv);
        *(float4*)&g_a[(rowBase + q0 + tr*4 + i) * C_ + hc + tc*4] = ov;
    }
}

// ---------------------------------------------------------------------------
// Launch
// ---------------------------------------------------------------------------
extern "C" void kernel_launch(void* const* d_in, const int* in_sizes, int n_in,
                              void* d_out, int out_size)
{
    const float* x  = (const float*)d_in[0];
    const int*   tm = (const int*)  d_in[1];
    const float* wq = (const float*)d_in[2];
    const float* bq = (const float*)d_in[3];
    const float* wk = (const float*)d_in[4];
    const float* bk = (const float*)d_in[5];
    const float* wv = (const float*)d_in[6];
    const float* bv = (const float*)d_in[7];
    const float* wp = (const float*)d_in[8];
    const float* bp = (const float*)d_in[9];
    float* out = (float*)d_out;

    cudaFuncSetAttribute(attn_kernel,
                         cudaFuncAttributeMaxDynamicSharedMemorySize, ATT_SMEM);

    dim3 gQKV(C_/128, M_/128, 3);
    qkv_kernel<<<gQKV, 256>>>(x, wq, bq, wk, bk, wv, bv);

    dim3 gAtt(T_/64, NH_, B_);
    attn_kernel<<<gAtt, 256, ATT_SMEM>>>(tm);

    dim3 gProj(C_/128, M_/128, 1);
    proj_kernel<<<gProj, 256>>>(wp, bp, out);
}

// round 5
// speedup vs baseline: 1.4601x; 1.4601x over previous
#include <cuda_runtime.h>
#include <cuda_fp16.h>
#include <cstdint>

#define B_  4
#define T_  2048
#define C_  1024
#define NH_ 16
#define D_  64
#define M_  (B_*T_)

#define AS 68
#define ATT_SMEM ((4*64*AS)*4 + 64*4)

// GEMM smem (halves, pitch 40): per stage 4 tiles (Ah, Al, Wh, Wl) of
// 128 rows x 40 halves x 2B = 10240B each -> 40960B/stage, 2 stages.
#define PH     40
#define TILEB  10240u
#define STAGEB 40960u
#define GSMEM  81920

extern __shared__ char dyn_smem[];

// Scratch (static device globals — no allocation at runtime)
__device__ float  g_q[M_*C_];
__device__ float  g_k[M_*C_];
__device__ float  g_v[M_*C_];
__device__ float  g_a[M_*C_];
__device__ __half g_xh[M_*C_],  g_xl[M_*C_];
__device__ __half g_ah[M_*C_],  g_al[M_*C_];
__device__ __half g_wqh[C_*C_], g_wql[C_*C_];
__device__ __half g_wkh[C_*C_], g_wkl[C_*C_];
__device__ __half g_wvh[C_*C_], g_wvl[C_*C_];
__device__ __half g_wph[C_*C_], g_wpl[C_*C_];

// ---------------------------------------------------------------------------
// helpers
// ---------------------------------------------------------------------------
__device__ __forceinline__ uint32_t smem_to_u32(const void* p) {
    uint32_t a;
    asm("{ .reg .u64 t; cvta.to.shared.u64 t, %1; cvt.u32.u64 %0, t; }"
        : "=r"(a) : "l"(p));
    return a;
}

__device__ __forceinline__ void cp_async16(uint32_t s, const void* g) {
    asm volatile("cp.async.cg.shared.global [%0], [%1], 16;" :: "r"(s), "l"(g));
}
#define CP_COMMIT() asm volatile("cp.async.commit_group;" ::: "memory")

__device__ __forceinline__ void ldmx4(uint32_t& r0, uint32_t& r1,
                                      uint32_t& r2, uint32_t& r3, uint32_t a) {
    asm volatile("ldmatrix.sync.aligned.m8n8.x4.shared.b16 {%0,%1,%2,%3}, [%4];"
                 : "=r"(r0), "=r"(r1), "=r"(r2), "=r"(r3) : "r"(a));
}
__device__ __forceinline__ void ldmx2(uint32_t& r0, uint32_t& r1, uint32_t a) {
    asm volatile("ldmatrix.sync.aligned.m8n8.x2.shared.b16 {%0,%1}, [%2];"
                 : "=r"(r0), "=r"(r1) : "r"(a));
}

__device__ __forceinline__ void mma_f16(float& c0, float& c1, float& c2, float& c3,
                                        uint32_t a0, uint32_t a1, uint32_t a2, uint32_t a3,
                                        uint32_t b0, uint32_t b1) {
    asm volatile(
        "mma.sync.aligned.m16n8k16.row.col.f32.f16.f16.f32 "
        "{%0,%1,%2,%3}, {%4,%5,%6,%7}, {%8,%9}, {%0,%1,%2,%3};\n"
        : "+f"(c0), "+f"(c1), "+f"(c2), "+f"(c3)
        : "r"(a0), "r"(a1), "r"(a2), "r"(a3), "r"(b0), "r"(b1));
}

// ---------------------------------------------------------------------------
// split prepass: src fp32 -> (hi fp16, lo fp16), lo = fp16(x - fp32(hi))
// sel: 0=x 1=wq 2=wk 3=wv 4=wp 5=g_a
// ---------------------------------------------------------------------------
__global__ void __launch_bounds__(256) split_kernel(const float* __restrict__ src,
                                                    int sel, int n)
{
    __half* dh; __half* dl;
    switch (sel) {
        case 0: dh = g_xh;  dl = g_xl;  break;
        case 1: dh = g_wqh; dl = g_wql; break;
        case 2: dh = g_wkh; dl = g_wkl; break;
        case 3: dh = g_wvh; dl = g_wvl; break;
        case 4: dh = g_wph; dl = g_wpl; break;
        default: dh = g_ah; dl = g_al; src = g_a; break;
    }
    const int i4 = (blockIdx.x * 256 + threadIdx.x) * 4;
    if (i4 >= n) return;
    float4 v = *(const float4*)(src + i4);
    __half h0 = __float2half_rn(v.x), h1 = __float2half_rn(v.y);
    __half h2 = __float2half_rn(v.z), h3 = __float2half_rn(v.w);
    __half l0 = __float2half_rn(v.x - __half2float(h0));
    __half l1 = __float2half_rn(v.y - __half2float(h1));
    __half l2 = __float2half_rn(v.z - __half2float(h2));
    __half l3 = __float2half_rn(v.w - __half2float(h3));
    *(__half2*)(dh + i4)     = __halves2half2(h0, h1);
    *(__half2*)(dh + i4 + 2) = __halves2half2(h2, h3);
    *(__half2*)(dl + i4)     = __halves2half2(l0, l1);
    *(__half2*)(dl + i4 + 2) = __halves2half2(l2, l3);
}

// ---------------------------------------------------------------------------
// fp16x3 GEMM: out[128x128] = A[.,1024] @ W[.,1024]^T + bias (fp32 result)
// A,W given as hi/lo fp16 pairs. acc += Ah*Wh + Ah*Wl + Al*Wh (fp32 acc).
// 256 threads = 8 warps (2m x 4n), warp tile 64x32, K-chunk 32, cp.async x2.
// ---------------------------------------------------------------------------
__device__ __forceinline__ void tc_gemm_tile(
    const __half* __restrict__ Ah, const __half* __restrict__ Al,
    const __half* __restrict__ Wh, const __half* __restrict__ Wl,
    const float* __restrict__ bias, float* __restrict__ out)
{
    const uint32_t sb = smem_to_u32(dyn_smem);

    const int tid  = threadIdx.x;
    const int wid  = tid >> 5;
    const int lane = tid & 31;
    const int g    = lane >> 2;
    const int tig  = lane & 3;

    const int row0 = blockIdx.y * 128;
    const int col0 = blockIdx.x * 128;
    const int warpM = (wid & 1) * 64;
    const int warpN = (wid >> 1) * 32;

    // fill: 512 granules (128 rows x 4 x 16B) per tile, 2 per thread
    auto issue_chunk = [&](int st, uint32_t stage) {
        const int k0 = st * 32;
        #pragma unroll
        for (int p = 0; p < 2; ++p) {
            const int gid = tid + p * 256;
            const int r = gid >> 2, c = gid & 3;
            const uint32_t d = stage + (uint32_t)(r * PH + c * 8) * 2u;
            const size_t so = (size_t)(row0 + r) * C_ + k0 + c * 8;
            const size_t wo = (size_t)(col0 + r) * C_ + k0 + c * 8;
            cp_async16(d,                 Ah + so);
            cp_async16(d + TILEB,         Al + so);
            cp_async16(d + 2 * TILEB,     Wh + wo);
            cp_async16(d + 3 * TILEB,     Wl + wo);
        }
        CP_COMMIT();
    };

    float acc[4][4][4];
    #pragma unroll
    for (int mf = 0; mf < 4; ++mf)
        #pragma unroll
        for (int nf = 0; nf < 4; ++nf)
            #pragma unroll
            for (int r = 0; r < 4; ++r) acc[mf][nf][r] = 0.f;

    issue_chunk(0, sb);
    issue_chunk(1, sb + STAGEB);

    // per-lane ldmatrix half-index offsets (col k16 added in loop)
    const int aRow = (lane & 15);            // + warpM + mf*16
    const int aCol = (lane >> 4) << 3;
    const int bRow = (lane & 7);             // + warpN + nf*8
    const int bCol = ((lane >> 3) & 1) << 3;

    for (int st = 0; st < 32; ++st) {
        if (st < 31) { asm volatile("cp.async.wait_group 1;" ::: "memory"); }
        else         { asm volatile("cp.async.wait_group 0;" ::: "memory"); }
        __syncthreads();

        const uint32_t stage = sb + (st & 1) * STAGEB;

        #pragma unroll
        for (int kk = 0; kk < 2; ++kk) {
            const int k16 = kk * 16;

            uint32_t afh[4][4], bfh[4][2];
            #pragma unroll
            for (int mf = 0; mf < 4; ++mf) {
                const uint32_t a = stage +
                    (uint32_t)((warpM + mf * 16 + aRow) * PH + k16 + aCol) * 2u;
                ldmx4(afh[mf][0], afh[mf][1], afh[mf][2], afh[mf][3], a);
            }
            #pragma unroll
            for (int nf = 0; nf < 4; ++nf) {
                const uint32_t a = stage + 2 * TILEB +
                    (uint32_t)((warpN + nf * 8 + bRow) * PH + k16 + bCol) * 2u;
                ldmx2(bfh[nf][0], bfh[nf][1], a);
            }
            // hi x hi
            #pragma unroll
            for (int mf = 0; mf < 4; ++mf)
                #pragma unroll
                for (int nf = 0; nf < 4; ++nf)
                    mma_f16(acc[mf][nf][0], acc[mf][nf][1], acc[mf][nf][2], acc[mf][nf][3],
                            afh[mf][0], afh[mf][1], afh[mf][2], afh[mf][3],
                            bfh[nf][0], bfh[nf][1]);
            // hi x lo
            uint32_t bfl[4][2];
            #pragma unroll
            for (int nf = 0; nf < 4; ++nf) {
                const uint32_t a = stage + 3 * TILEB +
                    (uint32_t)((warpN + nf * 8 + bRow) * PH + k16 + bCol) * 2u;
                ldmx2(bfl[nf][0], bfl[nf][1], a);
            }
            #pragma unroll
            for (int mf = 0; mf < 4; ++mf)
                #pragma unroll
                for (int nf = 0; nf < 4; ++nf)
                    mma_f16(acc[mf][nf][0], acc[mf][nf][1], acc[mf][nf][2], acc[mf][nf][3],
                            afh[mf][0], afh[mf][1], afh[mf][2], afh[mf][3],
                            bfl[nf][0], bfl[nf][1]);
            // lo x hi
            uint32_t afl[4][4];
            #pragma unroll
            for (int mf = 0; mf < 4; ++mf) {
                const uint32_t a = stage + TILEB +
                    (uint32_t)((warpM + mf * 16 + aRow) * PH + k16 + aCol) * 2u;
                ldmx4(afl[mf][0], afl[mf][1], afl[mf][2], afl[mf][3], a);
            }
            #pragma unroll
            for (int mf = 0; mf < 4; ++mf)
                #pragma unroll
                for (int nf = 0; nf < 4; ++nf)
                    mma_f16(acc[mf][nf][0], acc[mf][nf][1], acc[mf][nf][2], acc[mf][nf][3],
                            afl[mf][0], afl[mf][1], afl[mf][2], afl[mf][3],
                            bfh[nf][0], bfh[nf][1]);
        }
        __syncthreads();
        if (st + 2 < 32) issue_chunk(st + 2, sb + (st & 1) * STAGEB);
    }

    // epilogue: + bias, float2 stores
    #pragma unroll
    for (int nf = 0; nf < 4; ++nf) {
        const int colg = col0 + warpN + nf * 8 + tig * 2;
        const float2 bb = *(const float2*)&bias[colg];
        #pragma unroll
        for (int mf = 0; mf < 4; ++mf) {
            const int rowg = row0 + warpM + mf * 16 + g;
            float2 o0 = make_float2(acc[mf][nf][0] + bb.x, acc[mf][nf][1] + bb.y);
            float2 o1 = make_float2(acc[mf][nf][2] + bb.x, acc[mf][nf][3] + bb.y);
            *(float2*)&out[(size_t)rowg * C_ + colg]       = o0;
            *(float2*)&out[(size_t)(rowg + 8) * C_ + colg] = o1;
        }
    }
}

__global__ void __launch_bounds__(256) qkv_kernel(
    const float* __restrict__ bq, const float* __restrict__ bk,
    const float* __restrict__ bv)
{
    const int sel = blockIdx.z;
    const __half* Wh   = (sel == 0) ? g_wqh : (sel == 1) ? g_wkh : g_wvh;
    const __half* Wl   = (sel == 0) ? g_wql : (sel == 1) ? g_wkl : g_wvl;
    const float*  bias = (sel == 0) ? bq    : (sel == 1) ? bk    : bv;
    float* out         = (sel == 0) ? g_q   : (sel == 1) ? g_k   : g_v;
    tc_gemm_tile(g_xh, g_xl, Wh, Wl, bias, out);
}

__global__ void __launch_bounds__(256) proj_kernel(
    const float* __restrict__ bp, float* __restrict__ out)
{
    tc_gemm_tile(g_ah, g_al, g_wph, g_wpl, bp, out);
}

// ---------------------------------------------------------------------------
// Attention (unchanged, proven): fp32 flash attention, CTA per (b,h,64-row tile)
// ---------------------------------------------------------------------------
__global__ void __launch_bounds__(256) attn_kernel(const int* __restrict__ tmask)
{
    float* sm = (float*)dyn_smem;
    float* QsT = sm;
    float* KsT = sm + 64*AS;
    float* Vs  = sm + 2*64*AS;
    float* PsT = sm + 3*64*AS;
    int*   Ms  = (int*)(sm + 4*64*AS);

    const int qt = blockIdx.x;
    const int h  = blockIdx.y;
    const int b  = blockIdx.z;
    const int q0 = qt * 64;

    const int tid = threadIdx.x;
    const int tc  = tid & 15;
    const int tr  = tid >> 4;
    const int rowBase = b * T_;
    const int hc = h * D_;

    #pragma unroll
    for (int it = 0; it < 4; it++) {
        const int idx = tid + it * 256;
        const int r  = idx >> 4;
        const int d4 = (idx & 15) << 2;
        float4 qv = *(const float4*)&g_q[(rowBase + q0 + r) * C_ + hc + d4];
        QsT[(d4+0)*AS + r] = qv.x * 0.125f;
        QsT[(d4+1)*AS + r] = qv.y * 0.125f;
        QsT[(d4+2)*AS + r] = qv.z * 0.125f;
        QsT[(d4+3)*AS + r] = qv.w * 0.125f;
    }

    float o[4][4];
    float mrow[4], lrow[4];
    #pragma unroll
    for (int i = 0; i < 4; i++) {
        mrow[i] = -1e30f; lrow[i] = 0.f;
        #pragma unroll
        for (int j = 0; j < 4; j++) o[i][j] = 0.f;
    }

    for (int kt = 0; kt <= qt; kt++) {
        const int k0 = kt * 64;
        __syncthreads();

        #pragma unroll
        for (int it = 0; it < 4; it++) {
            const int idx = tid + it * 256;
            const int r  = idx >> 4;
            const int d4 = (idx & 15) << 2;
            float4 kv = *(const float4*)&g_k[(rowBase + k0 + r) * C_ + hc + d4];
            KsT[(d4+0)*AS + r] = kv.x;
            KsT[(d4+1)*AS + r] = kv.y;
            KsT[(d4+2)*AS + r] = kv.z;
            KsT[(d4+3)*AS + r] = kv.w;
            float4 vv = *(const float4*)&g_v[(rowBase + k0 + r) * C_ + hc + d4];
            *(float4*)&Vs[r*AS + d4] = vv;
        }
        if (tid < 64) Ms[tid] = tmask[b * T_ + k0 + tid];
        __syncthreads();

        float s[4][4];
        #pragma unroll
        for (int i = 0; i < 4; i++)
            #pragma unroll
            for (int j = 0; j < 4; j++) s[i][j] = 0.f;

        #pragma unroll
        for (int d0 = 0; d0 < 64; d0 += 4) {
            #pragma unroll
            for (int c = 0; c < 4; c++) {
                float a4[4], b4[4];
                *(float4*)a4 = *(const float4*)&QsT[(d0+c)*AS + tr*4];
                *(float4*)b4 = *(const float4*)&KsT[(d0+c)*AS + tc*4];
                #pragma unroll
                for (int i = 0; i < 4; i++)
                    #pragma unroll
                    for (int j = 0; j < 4; j++)
                        s[i][j] += a4[i] * b4[j];
            }
        }

        const bool diag = (kt == qt);
        #pragma unroll
        for (int j = 0; j < 4; j++) {
            const int kc = tc*4 + j;
            const bool mok = (Ms[kc] != 0);
            #pragma unroll
            for (int i = 0; i < 4; i++) {
                const bool ok = mok && (!diag || (kc <= tr*4 + i));
                if (!ok) s[i][j] = -1e30f;
            }
        }

        #pragma unroll
        for (int i = 0; i < 4; i++) {
            float mx = fmaxf(fmaxf(s[i][0], s[i][1]), fmaxf(s[i][2], s[i][3]));
            mx = fmaxf(mx, __shfl_xor_sync(0xffffffffu, mx, 1));
            mx = fmaxf(mx, __shfl_xor_sync(0xffffffffu, mx, 2));
            mx = fmaxf(mx, __shfl_xor_sync(0xffffffffu, mx, 4));
            mx = fmaxf(mx, __shfl_xor_sync(0xffffffffu, mx, 8));
            const float mnew = fmaxf(mrow[i], mx);
            const float corr = __expf(mrow[i] - mnew);
            mrow[i] = mnew;
            float ls = 0.f;
            #pragma unroll
            for (int j = 0; j < 4; j++) {
                s[i][j] = __expf(s[i][j] - mnew);
                ls += s[i][j];
            }
            ls += __shfl_xor_sync(0xffffffffu, ls, 1);
            ls += __shfl_xor_sync(0xffffffffu, ls, 2);
            ls += __shfl_xor_sync(0xffffffffu, ls, 4);
            ls += __shfl_xor_sync(0xffffffffu, ls, 8);
            lrow[i] = lrow[i] * corr + ls;
            #pragma unroll
            for (int j = 0; j < 4; j++) o[i][j] *= corr;
        }

        #pragma unroll
        for (int j = 0; j < 4; j++) {
            float4 pv = make_float4(s[0][j], s[1][j], s[2][j], s[3][j]);
            *(float4*)&PsT[(tc*4 + j)*AS + tr*4] = pv;
        }
        __syncthreads();

        #pragma unroll
        for (int j0 = 0; j0 < 64; j0 += 4) {
            #pragma unroll
            for (int c = 0; c < 4; c++) {
                float a4[4], b4[4];
                *(float4*)a4 = *(const float4*)&PsT[(j0+c)*AS + tr*4];
                *(float4*)b4 = *(const float4*)&Vs[(j0+c)*AS + tc*4];
                #pragma unroll
                for (int i = 0; i < 4; i++)
                    #pragma unroll
                    for (int j = 0; j < 4; j++)
                        o[i][j] += a4[i] * b4[j];
            }
        }
    }

    #pragma unroll
    for (int i = 0; i < 4; i++) {
        const float inv = 1.f / lrow[i];
        float4 ov = make_float4(o[i][0]*inv, o[i][1]*inv, o[i][2]*inv, o[i][3]*inv);
        *(float4*)&g_a[(rowBase + q0 + tr*4 + i) * C_ + hc + tc*4] = ov;
    }
}

// ---------------------------------------------------------------------------
// Launch
// ---------------------------------------------------------------------------
extern "C" void kernel_launch(void* const* d_in, const int* in_sizes, int n_in,
                              void* d_out, int out_size)
{
    const float* x  = (const float*)d_in[0];
    const int*   tm = (const int*)  d_in[1];
    const float* wq = (const float*)d_in[2];
    const float* bq = (const float*)d_in[3];
    const float* wk = (const float*)d_in[4];
    const float* bk = (const float*)d_in[5];
    const float* wv = (const float*)d_in[6];
    const float* bv = (const float*)d_in[7];
    const float* wp = (const float*)d_in[8];
    const float* bp = (const float*)d_in[9];
    float* out = (float*)d_out;

    cudaFuncSetAttribute(qkv_kernel,  cudaFuncAttributeMaxDynamicSharedMemorySize, GSMEM);
    cudaFuncSetAttribute(proj_kernel, cudaFuncAttributeMaxDynamicSharedMemorySize, GSMEM);
    cudaFuncSetAttribute(attn_kernel, cudaFuncAttributeMaxDynamicSharedMemorySize, ATT_SMEM);

    const int nX = M_ * C_;
    const int nW = C_ * C_;
    split_kernel<<<nX / 1024, 256>>>(x,  0, nX);
    split_kernel<<<nW / 1024, 256>>>(wq, 1, nW);
    split_kernel<<<nW / 1024, 256>>>(wk, 2, nW);
    split_kernel<<<nW / 1024, 256>>>(wv, 3, nW);
    split_kernel<<<nW / 1024, 256>>>(wp, 4, nW);

    dim3 gQKV(C_/128, M_/128, 3);
    qkv_kernel<<<gQKV, 256, GSMEM>>>(bq, bk, bv);

    dim3 gAtt(T_/64, NH_, B_);
    attn_kernel<<<gAtt, 256, ATT_SMEM>>>(tm);

    split_kernel<<<nX / 1024, 256>>>(nullptr, 5, nX);

    dim3 gProj(C_/128, M_/128, 1);
    proj_kernel<<<gProj, 256, GSMEM>>>(bp, out);
}

// round 6
// speedup vs baseline: 1.9958x; 1.3669x over previous
#include <cuda_runtime.h>
#include <cuda_fp16.h>
#include <cstdint>

#define B_  4
#define T_  2048
#define C_  1024
#define NH_ 16
#define D_  64
#define M_  (B_*T_)

// ---- GEMM smem (halves, pitch 40): 4 tiles/stage, 2 stages ----
#define PH     40
#define TILEB  10240u
#define STAGEB 40960u
#define GSMEM  81920

// ---- Attention smem ----
#define PQ 72     // pitch (halves) for Q,K tiles (64 cols)
#define PK 136    // pitch (halves) for V^T tiles (128 cols)
#define QH_OFF  0u
#define QL_OFF  18432u
#define KH_OFF  36864u
#define KL_OFF  55296u
#define VTH_OFF 73728u
#define VTL_OFF 91136u
#define MSK_OFF 108544u
#define ATT_SMEM 109056

extern __shared__ char dyn_smem[];

// Scratch (static device globals — no allocation at runtime)
__device__ __half g_qh[M_*C_],  g_ql[M_*C_];
__device__ __half g_kh[M_*C_],  g_kl[M_*C_];
__device__ __half g_vh[M_*C_],  g_vl[M_*C_];
__device__ __half g_ah[M_*C_],  g_al[M_*C_];
__device__ __half g_xh[M_*C_],  g_xl[M_*C_];
__device__ __half g_wqh[C_*C_], g_wql[C_*C_];
__device__ __half g_wkh[C_*C_], g_wkl[C_*C_];
__device__ __half g_wvh[C_*C_], g_wvl[C_*C_];
__device__ __half g_wph[C_*C_], g_wpl[C_*C_];

// ---------------------------------------------------------------------------
// helpers
// ---------------------------------------------------------------------------
__device__ __forceinline__ uint32_t smem_to_u32(const void* p) {
    uint32_t a;
    asm("{ .reg .u64 t; cvta.to.shared.u64 t, %1; cvt.u32.u64 %0, t; }"
        : "=r"(a) : "l"(p));
    return a;
}

__device__ __forceinline__ void cp_async16(uint32_t s, const void* g) {
    asm volatile("cp.async.cg.shared.global [%0], [%1], 16;" :: "r"(s), "l"(g));
}
#define CP_COMMIT() asm volatile("cp.async.commit_group;" ::: "memory")

__device__ __forceinline__ void ldmx4(uint32_t& r0, uint32_t& r1,
                                      uint32_t& r2, uint32_t& r3, uint32_t a) {
    asm volatile("ldmatrix.sync.aligned.m8n8.x4.shared.b16 {%0,%1,%2,%3}, [%4];"
                 : "=r"(r0), "=r"(r1), "=r"(r2), "=r"(r3) : "r"(a));
}
__device__ __forceinline__ void ldmx2(uint32_t& r0, uint32_t& r1, uint32_t a) {
    asm volatile("ldmatrix.sync.aligned.m8n8.x2.shared.b16 {%0,%1}, [%2];"
                 : "=r"(r0), "=r"(r1) : "r"(a));
}

__device__ __forceinline__ void mma_f16(float& c0, float& c1, float& c2, float& c3,
                                        uint32_t a0, uint32_t a1, uint32_t a2, uint32_t a3,
                                        uint32_t b0, uint32_t b1) {
    asm volatile(
        "mma.sync.aligned.m16n8k16.row.col.f32.f16.f16.f32 "
        "{%0,%1,%2,%3}, {%4,%5,%6,%7}, {%8,%9}, {%0,%1,%2,%3};\n"
        : "+f"(c0), "+f"(c1), "+f"(c2), "+f"(c3)
        : "r"(a0), "r"(a1), "r"(a2), "r"(a3), "r"(b0), "r"(b1));
}

// split one float pair into packed hi-half2 and lo-half2
__device__ __forceinline__ void pack_hl(float x, float y, uint32_t& hh, uint32_t& ll) {
    __half hx = __float2half_rn(x), hy = __float2half_rn(y);
    __half lx = __float2half_rn(x - __half2float(hx));
    __half ly = __float2half_rn(y - __half2float(hy));
    __half2 H = __halves2half2(hx, hy), L = __halves2half2(lx, ly);
    hh = *(uint32_t*)&H; ll = *(uint32_t*)&L;
}

// ---------------------------------------------------------------------------
// split prepass: fp32 -> (hi fp16, lo fp16).  sel: 0=x 1=wq 2=wk 3=wv 4=wp
// ---------------------------------------------------------------------------
__global__ void __launch_bounds__(256) split_kernel(const float* __restrict__ src,
                                                    int sel, int n)
{
    __half* dh; __half* dl;
    switch (sel) {
        case 0: dh = g_xh;  dl = g_xl;  break;
        case 1: dh = g_wqh; dl = g_wql; break;
        case 2: dh = g_wkh; dl = g_wkl; break;
        case 3: dh = g_wvh; dl = g_wvl; break;
        default: dh = g_wph; dl = g_wpl; break;
    }
    const int i4 = (blockIdx.x * 256 + threadIdx.x) * 4;
    if (i4 >= n) return;
    float4 v = *(const float4*)(src + i4);
    uint32_t h0, l0, h1, l1;
    pack_hl(v.x, v.y, h0, l0);
    pack_hl(v.z, v.w, h1, l1);
    *(uint32_t*)(dh + i4)     = h0;
    *(uint32_t*)(dh + i4 + 2) = h1;
    *(uint32_t*)(dl + i4)     = l0;
    *(uint32_t*)(dl + i4 + 2) = l1;
}

// ---------------------------------------------------------------------------
// fp16x3 GEMM: 128x128 tile of A[.,1024] @ W[.,1024]^T + bias
// epilogue: outF != nullptr -> fp32 store; else split-fp16 (outH,outL) * scale
// ---------------------------------------------------------------------------
__device__ __forceinline__ void tc_gemm_tile(
    const __half* __restrict__ Ah, const __half* __restrict__ Al,
    const __half* __restrict__ Wh, const __half* __restrict__ Wl,
    const float* __restrict__ bias,
    float* __restrict__ outF, __half* __restrict__ outH,
    __half* __restrict__ outL, float scale)
{
    const uint32_t sb = smem_to_u32(dyn_smem);

    const int tid  = threadIdx.x;
    const int wid  = tid >> 5;
    const int lane = tid & 31;
    const int g    = lane >> 2;
    const int tig  = lane & 3;

    const int row0 = blockIdx.y * 128;
    const int col0 = blockIdx.x * 128;
    const int warpM = (wid & 1) * 64;
    const int warpN = (wid >> 1) * 32;

    auto issue_chunk = [&](int st, uint32_t stage) {
        const int k0 = st * 32;
        #pragma unroll
        for (int p = 0; p < 2; ++p) {
            const int gid = tid + p * 256;
            const int r = gid >> 2, c = gid & 3;
            const uint32_t d = stage + (uint32_t)(r * PH + c * 8) * 2u;
            const size_t so = (size_t)(row0 + r) * C_ + k0 + c * 8;
            const size_t wo = (size_t)(col0 + r) * C_ + k0 + c * 8;
            cp_async16(d,             Ah + so);
            cp_async16(d + TILEB,     Al + so);
            cp_async16(d + 2 * TILEB, Wh + wo);
            cp_async16(d + 3 * TILEB, Wl + wo);
        }
        CP_COMMIT();
    };

    float acc[4][4][4];
    #pragma unroll
    for (int mf = 0; mf < 4; ++mf)
        #pragma unroll
        for (int nf = 0; nf < 4; ++nf)
            #pragma unroll
            for (int r = 0; r < 4; ++r) acc[mf][nf][r] = 0.f;

    issue_chunk(0, sb);
    issue_chunk(1, sb + STAGEB);

    const int aRow = (lane & 15);
    const int aCol = (lane >> 4) << 3;
    const int bRow = (lane & 7);
    const int bCol = ((lane >> 3) & 1) << 3;

    for (int st = 0; st < 32; ++st) {
        if (st < 31) { asm volatile("cp.async.wait_group 1;" ::: "memory"); }
        else         { asm volatile("cp.async.wait_group 0;" ::: "memory"); }
        __syncthreads();

        const uint32_t stage = sb + (st & 1) * STAGEB;

        #pragma unroll
        for (int kk = 0; kk < 2; ++kk) {
            const int k16 = kk * 16;

            uint32_t afh[4][4], bfh[4][2];
            #pragma unroll
            for (int mf = 0; mf < 4; ++mf) {
                const uint32_t a = stage +
                    (uint32_t)((warpM + mf * 16 + aRow) * PH + k16 + aCol) * 2u;
                ldmx4(afh[mf][0], afh[mf][1], afh[mf][2], afh[mf][3], a);
            }
            #pragma unroll
            for (int nf = 0; nf < 4; ++nf) {
                const uint32_t a = stage + 2 * TILEB +
                    (uint32_t)((warpN + nf * 8 + bRow) * PH + k16 + bCol) * 2u;
                ldmx2(bfh[nf][0], bfh[nf][1], a);
            }
            #pragma unroll
            for (int mf = 0; mf < 4; ++mf)
                #pragma unroll
                for (int nf = 0; nf < 4; ++nf)
                    mma_f16(acc[mf][nf][0], acc[mf][nf][1], acc[mf][nf][2], acc[mf][nf][3],
                            afh[mf][0], afh[mf][1], afh[mf][2], afh[mf][3],
                            bfh[nf][0], bfh[nf][1]);
            uint32_t bfl[4][2];
            #pragma unroll
            for (int nf = 0; nf < 4; ++nf) {
                const uint32_t a = stage + 3 * TILEB +
                    (uint32_t)((warpN + nf * 8 + bRow) * PH + k16 + bCol) * 2u;
                ldmx2(bfl[nf][0], bfl[nf][1], a);
            }
            #pragma unroll
            for (int mf = 0; mf < 4; ++mf)
                #pragma unroll
                for (int nf = 0; nf < 4; ++nf)
                    mma_f16(acc[mf][nf][0], acc[mf][nf][1], acc[mf][nf][2], acc[mf][nf][3],
                            afh[mf][0], afh[mf][1], afh[mf][2], afh[mf][3],
                            bfl[nf][0], bfl[nf][1]);
            uint32_t afl[4][4];
            #pragma unroll
            for (int mf = 0; mf < 4; ++mf) {
                const uint32_t a = stage + TILEB +
                    (uint32_t)((warpM + mf * 16 + aRow) * PH + k16 + aCol) * 2u;
                ldmx4(afl[mf][0], afl[mf][1], afl[mf][2], afl[mf][3], a);
            }
            #pragma unroll
            for (int mf = 0; mf < 4; ++mf)
                #pragma unroll
                for (int nf = 0; nf < 4; ++nf)
                    mma_f16(acc[mf][nf][0], acc[mf][nf][1], acc[mf][nf][2], acc[mf][nf][3],
                            afl[mf][0], afl[mf][1], afl[mf][2], afl[mf][3],
                            bfh[nf][0], bfh[nf][1]);
        }
        __syncthreads();
        if (st + 2 < 32) issue_chunk(st + 2, sb + (st & 1) * STAGEB);
    }

    #pragma unroll
    for (int nf = 0; nf < 4; ++nf) {
        const int colg = col0 + warpN + nf * 8 + tig * 2;
        const float2 bb = *(const float2*)&bias[colg];
        #pragma unroll
        for (int mf = 0; mf < 4; ++mf) {
            const int rowg = row0 + warpM + mf * 16 + g;
            const float v00 = acc[mf][nf][0] + bb.x, v01 = acc[mf][nf][1] + bb.y;
            const float v10 = acc[mf][nf][2] + bb.x, v11 = acc[mf][nf][3] + bb.y;
            if (outF) {
                *(float2*)&outF[(size_t)rowg * C_ + colg]       = make_float2(v00, v01);
                *(float2*)&outF[(size_t)(rowg + 8) * C_ + colg] = make_float2(v10, v11);
            } else {
                uint32_t hh, ll;
                pack_hl(v00 * scale, v01 * scale, hh, ll);
                *(uint32_t*)&outH[(size_t)rowg * C_ + colg] = hh;
                *(uint32_t*)&outL[(size_t)rowg * C_ + colg] = ll;
                pack_hl(v10 * scale, v11 * scale, hh, ll);
                *(uint32_t*)&outH[(size_t)(rowg + 8) * C_ + colg] = hh;
                *(uint32_t*)&outL[(size_t)(rowg + 8) * C_ + colg] = ll;
            }
        }
    }
}

__global__ void __launch_bounds__(256) qkv_kernel(
    const float* __restrict__ bq, const float* __restrict__ bk,
    const float* __restrict__ bv)
{
    const int sel = blockIdx.z;
    const __half* Wh   = (sel == 0) ? g_wqh : (sel == 1) ? g_wkh : g_wvh;
    const __half* Wl   = (sel == 0) ? g_wql : (sel == 1) ? g_wkl : g_wvl;
    const float*  bias = (sel == 0) ? bq    : (sel == 1) ? bk    : bv;
    __half* outH       = (sel == 0) ? g_qh  : (sel == 1) ? g_kh  : g_vh;
    __half* outL       = (sel == 0) ? g_ql  : (sel == 1) ? g_kl  : g_vl;
    const float scale  = (sel == 0) ? 0.125f : 1.0f;   // fold 1/sqrt(D) into Q
    tc_gemm_tile(g_xh, g_xl, Wh, Wl, bias, nullptr, outH, outL, scale);
}

__global__ void __launch_bounds__(256) proj_kernel(
    const float* __restrict__ bp, float* __restrict__ out)
{
    tc_gemm_tile(g_ah, g_al, g_wph, g_wpl, bp, out, nullptr, nullptr, 1.0f);
}

// ---------------------------------------------------------------------------
// fp16x3 flash attention: CTA per (b, h, 128-row q tile). 8 warps x 16 rows.
// S = Qh Kh^T + Qh Kl^T + Ql Kh^T ; online softmax in regs (rows in-warp);
// P repacked hi/lo in regs (S acc layout == PV A-frag layout);
// O += Ph Vh + Ph Vl + Pl Vh with V transposed in smem.
// ---------------------------------------------------------------------------
__global__ void __launch_bounds__(256) attn_kernel(const int* __restrict__ tmask)
{
    __half* Qh  = (__half*)(dyn_smem + QH_OFF);
    __half* Ql  = (__half*)(dyn_smem + QL_OFF);
    __half* Kh  = (__half*)(dyn_smem + KH_OFF);
    __half* Kl  = (__half*)(dyn_smem + KL_OFF);
    __half* VTh = (__half*)(dyn_smem + VTH_OFF);
    __half* VTl = (__half*)(dyn_smem + VTL_OFF);
    int*    Ms  = (int*)   (dyn_smem + MSK_OFF);
    const uint32_t sb = smem_to_u32(dyn_smem);

    const int qt = blockIdx.x, h = blockIdx.y, b = blockIdx.z;
    const int q0 = qt * 128;
    const int tid = threadIdx.x, w = tid >> 5, lane = tid & 31;
    const int g = lane >> 2, tig = lane & 3;
    const int rowBase = b * T_;
    const int hc = h * D_;

    // load Q tile (hi/lo), 128 x 64 halves each
    #pragma unroll
    for (int it = 0; it < 4; ++it) {
        const int gr = tid + it * 256;
        const int r = gr >> 3, c8 = (gr & 7) * 8;
        const size_t src = (size_t)(rowBase + q0 + r) * C_ + hc + c8;
        *(float4*)&Qh[r * PQ + c8] = *(const float4*)&g_qh[src];
        *(float4*)&Ql[r * PQ + c8] = *(const float4*)&g_ql[src];
    }

    float o[8][4];
    #pragma unroll
    for (int nf = 0; nf < 8; ++nf)
        #pragma unroll
        for (int c = 0; c < 4; ++c) o[nf][c] = 0.f;
    float mA = -1e30f, mB = -1e30f, lA = 0.f, lB = 0.f;

    const int rA = q0 + w * 16 + g;   // this thread's first row (in batch-local coords)
    const int rB = rA + 8;

    const int aRow = lane & 15, aCol = (lane >> 4) << 3;
    const int bRow = lane & 7,  bCol = ((lane >> 3) & 1) << 3;

    for (int kt = 0; kt <= qt; ++kt) {
        const int k0 = kt * 128;
        __syncthreads();   // prior-tile smem reads done (also covers Q load, iter 0)

        // load K tile (hi/lo) + V tile transposed (hi/lo) + mask
        #pragma unroll
        for (int it = 0; it < 4; ++it) {
            const int gr = tid + it * 256;
            const int r = gr >> 3, c8 = (gr & 7) * 8;
            const size_t src = (size_t)(rowBase + k0 + r) * C_ + hc + c8;
            *(float4*)&Kh[r * PQ + c8] = *(const float4*)&g_kh[src];
            *(float4*)&Kl[r * PQ + c8] = *(const float4*)&g_kl[src];
            __half tv[8];
            *(float4*)tv = *(const float4*)&g_vh[src];
            #pragma unroll
            for (int i = 0; i < 8; ++i) VTh[(c8 + i) * PK + r] = tv[i];
            *(float4*)tv = *(const float4*)&g_vl[src];
            #pragma unroll
            for (int i = 0; i < 8; ++i) VTl[(c8 + i) * PK + r] = tv[i];
        }
        if (tid < 128) Ms[tid] = tmask[b * T_ + k0 + tid];
        __syncthreads();

        // ---- S = Q K^T (fp16x3) ----
        float s[16][4];
        #pragma unroll
        for (int nf = 0; nf < 16; ++nf)
            #pragma unroll
            for (int c = 0; c < 4; ++c) s[nf][c] = 0.f;

        #pragma unroll
        for (int kk = 0; kk < 4; ++kk) {
            const int k16 = kk * 16;
            uint32_t aqh[4], aql[4];
            ldmx4(aqh[0], aqh[1], aqh[2], aqh[3],
                  sb + QH_OFF + (uint32_t)((w * 16 + aRow) * PQ + k16 + aCol) * 2u);
            ldmx4(aql[0], aql[1], aql[2], aql[3],
                  sb + QL_OFF + (uint32_t)((w * 16 + aRow) * PQ + k16 + aCol) * 2u);
            #pragma unroll
            for (int nf = 0; nf < 16; ++nf) {
                uint32_t bh0, bh1, bl0, bl1;
                const uint32_t off = (uint32_t)((nf * 8 + bRow) * PQ + k16 + bCol) * 2u;
                ldmx2(bh0, bh1, sb + KH_OFF + off);
                ldmx2(bl0, bl1, sb + KL_OFF + off);
                mma_f16(s[nf][0], s[nf][1], s[nf][2], s[nf][3],
                        aqh[0], aqh[1], aqh[2], aqh[3], bh0, bh1);
                mma_f16(s[nf][0], s[nf][1], s[nf][2], s[nf][3],
                        aqh[0], aqh[1], aqh[2], aqh[3], bl0, bl1);
                mma_f16(s[nf][0], s[nf][1], s[nf][2], s[nf][3],
                        aql[0], aql[1], aql[2], aql[3], bh0, bh1);
            }
        }

        // ---- mask (token always; causal on diagonal tile) ----
        const bool diag = (kt == qt);
        #pragma unroll
        for (int nf = 0; nf < 16; ++nf) {
            #pragma unroll
            for (int c = 0; c < 4; ++c) {
                const int cl = nf * 8 + tig * 2 + (c & 1);
                bool ok = (Ms[cl] != 0);
                if (diag) ok = ok && (k0 + cl <= ((c < 2) ? rA : rB));
                if (!ok) s[nf][c] = -1e30f;
            }
        }

        // ---- online softmax (rows g and g+8, reduced over tig lanes) ----
        float mxA = -1e30f, mxB = -1e30f;
        #pragma unroll
        for (int nf = 0; nf < 16; ++nf) {
            mxA = fmaxf(mxA, fmaxf(s[nf][0], s[nf][1]));
            mxB = fmaxf(mxB, fmaxf(s[nf][2], s[nf][3]));
        }
        mxA = fmaxf(mxA, __shfl_xor_sync(0xffffffffu, mxA, 1));
        mxA = fmaxf(mxA, __shfl_xor_sync(0xffffffffu, mxA, 2));
        mxB = fmaxf(mxB, __shfl_xor_sync(0xffffffffu, mxB, 1));
        mxB = fmaxf(mxB, __shfl_xor_sync(0xffffffffu, mxB, 2));
        const float mnA = fmaxf(mA, mxA), mnB = fmaxf(mB, mxB);
        const float cA = __expf(mA - mnA), cB = __expf(mB - mnB);
        mA = mnA; mB = mnB;
        float sA = 0.f, sB = 0.f;
        #pragma unroll
        for (int nf = 0; nf < 16; ++nf) {
            s[nf][0] = __expf(s[nf][0] - mnA);
            s[nf][1] = __expf(s[nf][1] - mnA);
            s[nf][2] = __expf(s[nf][2] - mnB);
            s[nf][3] = __expf(s[nf][3] - mnB);
            sA += s[nf][0] + s[nf][1];
            sB += s[nf][2] + s[nf][3];
        }
        sA += __shfl_xor_sync(0xffffffffu, sA, 1);
        sA += __shfl_xor_sync(0xffffffffu, sA, 2);
        sB += __shfl_xor_sync(0xffffffffu, sB, 1);
        sB += __shfl_xor_sync(0xffffffffu, sB, 2);
        lA = lA * cA + sA;
        lB = lB * cB + sB;
        #pragma unroll
        for (int nf = 0; nf < 8; ++nf) {
            o[nf][0] *= cA; o[nf][1] *= cA;
            o[nf][2] *= cB; o[nf][3] *= cB;
        }

        // ---- O += P V (fp16x3), P packed from regs ----
        #pragma unroll
        for (int j = 0; j < 8; ++j) {
            uint32_t ph[4], pl[4];
            pack_hl(s[2*j][0],   s[2*j][1],   ph[0], pl[0]);
            pack_hl(s[2*j][2],   s[2*j][3],   ph[1], pl[1]);
            pack_hl(s[2*j+1][0], s[2*j+1][1], ph[2], pl[2]);
            pack_hl(s[2*j+1][2], s[2*j+1][3], ph[3], pl[3]);
            #pragma unroll
            for (int nf = 0; nf < 8; ++nf) {
                uint32_t bh0, bh1, bl0, bl1;
                const uint32_t off = (uint32_t)((nf * 8 + bRow) * PK + j * 16 + bCol) * 2u;
                ldmx2(bh0, bh1, sb + VTH_OFF + off);
                ldmx2(bl0, bl1, sb + VTL_OFF + off);
                mma_f16(o[nf][0], o[nf][1], o[nf][2], o[nf][3],
                        ph[0], ph[1], ph[2], ph[3], bh0, bh1);
                mma_f16(o[nf][0], o[nf][1], o[nf][2], o[nf][3],
                        ph[0], ph[1], ph[2], ph[3], bl0, bl1);
                mma_f16(o[nf][0], o[nf][1], o[nf][2], o[nf][3],
                        pl[0], pl[1], pl[2], pl[3], bh0, bh1);
            }
        }
    }

    // ---- normalize, split-fp16 output for proj GEMM ----
    const float invA = 1.f / lA, invB = 1.f / lB;
    #pragma unroll
    for (int nf = 0; nf < 8; ++nf) {
        const int col = hc + nf * 8 + tig * 2;
        const size_t iA = (size_t)(rowBase + rA) * C_ + col;
        const size_t iB = iA + (size_t)8 * C_;
        uint32_t hh, ll;
        pack_hl(o[nf][0] * invA, o[nf][1] * invA, hh, ll);
        *(uint32_t*)&g_ah[iA] = hh; *(uint32_t*)&g_al[iA] = ll;
        pack_hl(o[nf][2] * invB, o[nf][3] * invB, hh, ll);
        *(uint32_t*)&g_ah[iB] = hh; *(uint32_t*)&g_al[iB] = ll;
    }
}

// ---------------------------------------------------------------------------
// Launch
// ---------------------------------------------------------------------------
extern "C" void kernel_launch(void* const* d_in, const int* in_sizes, int n_in,
                              void* d_out, int out_size)
{
    const float* x  = (const float*)d_in[0];
    const int*   tm = (const int*)  d_in[1];
    const float* wq = (const float*)d_in[2];
    const float* bq = (const float*)d_in[3];
    const float* wk = (const float*)d_in[4];
    const float* bk = (const float*)d_in[5];
    const float* wv = (const float*)d_in[6];
    const float* bv = (const float*)d_in[7];
    const float* wp = (const float*)d_in[8];
    const float* bp = (const float*)d_in[9];
    float* out = (float*)d_out;

    cudaFuncSetAttribute(qkv_kernel,  cudaFuncAttributeMaxDynamicSharedMemorySize, GSMEM);
    cudaFuncSetAttribute(proj_kernel, cudaFuncAttributeMaxDynamicSharedMemorySize, GSMEM);
    cudaFuncSetAttribute(attn_kernel, cudaFuncAttributeMaxDynamicSharedMemorySize, ATT_SMEM);

    const int nX = M_ * C_;
    const int nW = C_ * C_;
    split_kernel<<<nX / 1024, 256>>>(x,  0, nX);
    split_kernel<<<nW / 1024, 256>>>(wq, 1, nW);
    split_kernel<<<nW / 1024, 256>>>(wk, 2, nW);
    split_kernel<<<nW / 1024, 256>>>(wv, 3, nW);
    split_kernel<<<nW / 1024, 256>>>(wp, 4, nW);

    dim3 gQKV(C_/128, M_/128, 3);
    qkv_kernel<<<gQKV, 256, GSMEM>>>(bq, bk, bv);

    dim3 gAtt(T_/128, NH_, B_);
    attn_kernel<<<gAtt, 256, ATT_SMEM>>>(tm);

    dim3 gProj(C_/128, M_/128, 1);
    proj_kernel<<<gProj, 256, GSMEM>>>(bp, out);
}

// round 7
// speedup vs baseline: 2.1448x; 1.0747x over previous
#include <cuda_runtime.h>
#include <cuda_fp16.h>
#include <cstdint>

#define B_  4
#define T_  2048
#define C_  1024
#define NH_ 16
#define D_  64
#define M_  (B_*T_)

// ---- GEMM smem (halves, pitch 40): 4 tiles/stage, 2 stages ----
#define PH     40
#define TILEB  10240u
#define STAGEB 40960u
#define GSMEM  81920

// ---- Attention smem: Q(h,l) + 2 stages x (Kh,Kl,Vh,Vl) + masks ----
#define PQ 72                      // pitch (halves) for all 128x64 tiles
#define TILEA  18432u              // 128*PQ*2
#define STAGEA 73728u              // 4 tiles
#define QH_OFF 0u
#define QL_OFF 18432u
#define ST_OFF 36864u              // stage base (buf*STAGEA)
#define MSK_OFF 184320u            // 2 x 512B
#define ATT_SMEM 185600

extern __shared__ char dyn_smem[];

// Scratch (static device globals — no allocation at runtime)
__device__ __half g_qh[M_*C_],  g_ql[M_*C_];
__device__ __half g_kh[M_*C_],  g_kl[M_*C_];
__device__ __half g_vh[M_*C_],  g_vl[M_*C_];
__device__ __half g_ah[M_*C_],  g_al[M_*C_];
__device__ __half g_xh[M_*C_],  g_xl[M_*C_];
__device__ __half g_wqh[C_*C_], g_wql[C_*C_];
__device__ __half g_wkh[C_*C_], g_wkl[C_*C_];
__device__ __half g_wvh[C_*C_], g_wvl[C_*C_];
__device__ __half g_wph[C_*C_], g_wpl[C_*C_];

// ---------------------------------------------------------------------------
// helpers
// ---------------------------------------------------------------------------
__device__ __forceinline__ uint32_t smem_to_u32(const void* p) {
    uint32_t a;
    asm("{ .reg .u64 t; cvta.to.shared.u64 t, %1; cvt.u32.u64 %0, t; }"
        : "=r"(a) : "l"(p));
    return a;
}

__device__ __forceinline__ void cp_async16(uint32_t s, const void* g) {
    asm volatile("cp.async.cg.shared.global [%0], [%1], 16;" :: "r"(s), "l"(g));
}
#define CP_COMMIT() asm volatile("cp.async.commit_group;" ::: "memory")

__device__ __forceinline__ void ldmx4(uint32_t& r0, uint32_t& r1,
                                      uint32_t& r2, uint32_t& r3, uint32_t a) {
    asm volatile("ldmatrix.sync.aligned.m8n8.x4.shared.b16 {%0,%1,%2,%3}, [%4];"
                 : "=r"(r0), "=r"(r1), "=r"(r2), "=r"(r3) : "r"(a));
}
__device__ __forceinline__ void ldmx2(uint32_t& r0, uint32_t& r1, uint32_t a) {
    asm volatile("ldmatrix.sync.aligned.m8n8.x2.shared.b16 {%0,%1}, [%2];"
                 : "=r"(r0), "=r"(r1) : "r"(a));
}
__device__ __forceinline__ void ldmx2t(uint32_t& r0, uint32_t& r1, uint32_t a) {
    asm volatile("ldmatrix.sync.aligned.m8n8.x2.trans.shared.b16 {%0,%1}, [%2];"
                 : "=r"(r0), "=r"(r1) : "r"(a));
}

__device__ __forceinline__ void mma_f16(float& c0, float& c1, float& c2, float& c3,
                                        uint32_t a0, uint32_t a1, uint32_t a2, uint32_t a3,
                                        uint32_t b0, uint32_t b1) {
    asm volatile(
        "mma.sync.aligned.m16n8k16.row.col.f32.f16.f16.f32 "
        "{%0,%1,%2,%3}, {%4,%5,%6,%7}, {%8,%9}, {%0,%1,%2,%3};\n"
        : "+f"(c0), "+f"(c1), "+f"(c2), "+f"(c3)
        : "r"(a0), "r"(a1), "r"(a2), "r"(a3), "r"(b0), "r"(b1));
}

__device__ __forceinline__ float ex2f(float x) {
    float r;
    asm("ex2.approx.f32 %0, %1;" : "=f"(r) : "f"(x));
    return r;
}

__device__ __forceinline__ void pack_hl(float x, float y, uint32_t& hh, uint32_t& ll) {
    __half hx = __float2half_rn(x), hy = __float2half_rn(y);
    __half lx = __float2half_rn(x - __half2float(hx));
    __half ly = __float2half_rn(y - __half2float(hy));
    __half2 H = __halves2half2(hx, hy), L = __halves2half2(lx, ly);
    hh = *(uint32_t*)&H; ll = *(uint32_t*)&L;
}

// ---------------------------------------------------------------------------
// split prepass: fp32 -> (hi fp16, lo fp16).  sel: 0=x 1=wq 2=wk 3=wv 4=wp
// ---------------------------------------------------------------------------
__global__ void __launch_bounds__(256) split_kernel(const float* __restrict__ src,
                                                    int sel, int n)
{
    __half* dh; __half* dl;
    switch (sel) {
        case 0: dh = g_xh;  dl = g_xl;  break;
        case 1: dh = g_wqh; dl = g_wql; break;
        case 2: dh = g_wkh; dl = g_wkl; break;
        case 3: dh = g_wvh; dl = g_wvl; break;
        default: dh = g_wph; dl = g_wpl; break;
    }
    const int i4 = (blockIdx.x * 256 + threadIdx.x) * 4;
    if (i4 >= n) return;
    float4 v = *(const float4*)(src + i4);
    uint32_t h0, l0, h1, l1;
    pack_hl(v.x, v.y, h0, l0);
    pack_hl(v.z, v.w, h1, l1);
    *(uint32_t*)(dh + i4)     = h0;
    *(uint32_t*)(dh + i4 + 2) = h1;
    *(uint32_t*)(dl + i4)     = l0;
    *(uint32_t*)(dl + i4 + 2) = l1;
}

// ---------------------------------------------------------------------------
// fp16x3 GEMM: 128x128 tile of A[.,1024] @ W[.,1024]^T + bias
// ---------------------------------------------------------------------------
__device__ __forceinline__ void tc_gemm_tile(
    const __half* __restrict__ Ah, const __half* __restrict__ Al,
    const __half* __restrict__ Wh, const __half* __restrict__ Wl,
    const float* __restrict__ bias,
    float* __restrict__ outF, __half* __restrict__ outH,
    __half* __restrict__ outL, float scale)
{
    const uint32_t sb = smem_to_u32(dyn_smem);

    const int tid  = threadIdx.x;
    const int wid  = tid >> 5;
    const int lane = tid & 31;
    const int g    = lane >> 2;
    const int tig  = lane & 3;

    const int row0 = blockIdx.y * 128;
    const int col0 = blockIdx.x * 128;
    const int warpM = (wid & 1) * 64;
    const int warpN = (wid >> 1) * 32;

    auto issue_chunk = [&](int st, uint32_t stage) {
        const int k0 = st * 32;
        #pragma unroll
        for (int p = 0; p < 2; ++p) {
            const int gid = tid + p * 256;
            const int r = gid >> 2, c = gid & 3;
            const uint32_t d = stage + (uint32_t)(r * PH + c * 8) * 2u;
            const size_t so = (size_t)(row0 + r) * C_ + k0 + c * 8;
            const size_t wo = (size_t)(col0 + r) * C_ + k0 + c * 8;
            cp_async16(d,             Ah + so);
            cp_async16(d + TILEB,     Al + so);
            cp_async16(d + 2 * TILEB, Wh + wo);
            cp_async16(d + 3 * TILEB, Wl + wo);
        }
        CP_COMMIT();
    };

    float acc[4][4][4];
    #pragma unroll
    for (int mf = 0; mf < 4; ++mf)
        #pragma unroll
        for (int nf = 0; nf < 4; ++nf)
            #pragma unroll
            for (int r = 0; r < 4; ++r) acc[mf][nf][r] = 0.f;

    issue_chunk(0, sb);
    issue_chunk(1, sb + STAGEB);

    const int aRow = (lane & 15);
    const int aCol = (lane >> 4) << 3;
    const int bRow = (lane & 7);
    const int bCol = ((lane >> 3) & 1) << 3;

    for (int st = 0; st < 32; ++st) {
        if (st < 31) { asm volatile("cp.async.wait_group 1;" ::: "memory"); }
        else         { asm volatile("cp.async.wait_group 0;" ::: "memory"); }
        __syncthreads();

        const uint32_t stage = sb + (st & 1) * STAGEB;

        #pragma unroll
        for (int kk = 0; kk < 2; ++kk) {
            const int k16 = kk * 16;

            uint32_t afh[4][4], bfh[4][2];
            #pragma unroll
            for (int mf = 0; mf < 4; ++mf) {
                const uint32_t a = stage +
                    (uint32_t)((warpM + mf * 16 + aRow) * PH + k16 + aCol) * 2u;
                ldmx4(afh[mf][0], afh[mf][1], afh[mf][2], afh[mf][3], a);
            }
            #pragma unroll
            for (int nf = 0; nf < 4; ++nf) {
                const uint32_t a = stage + 2 * TILEB +
                    (uint32_t)((warpN + nf * 8 + bRow) * PH + k16 + bCol) * 2u;
                ldmx2(bfh[nf][0], bfh[nf][1], a);
            }
            #pragma unroll
            for (int mf = 0; mf < 4; ++mf)
                #pragma unroll
                for (int nf = 0; nf < 4; ++nf)
                    mma_f16(acc[mf][nf][0], acc[mf][nf][1], acc[mf][nf][2], acc[mf][nf][3],
                            afh[mf][0], afh[mf][1], afh[mf][2], afh[mf][3],
                            bfh[nf][0], bfh[nf][1]);
            uint32_t bfl[4][2];
            #pragma unroll
            for (int nf = 0; nf < 4; ++nf) {
                const uint32_t a = stage + 3 * TILEB +
                    (uint32_t)((warpN + nf * 8 + bRow) * PH + k16 + bCol) * 2u;
                ldmx2(bfl[nf][0], bfl[nf][1], a);
            }
            #pragma unroll
            for (int mf = 0; mf < 4; ++mf)
                #pragma unroll
                for (int nf = 0; nf < 4; ++nf)
                    mma_f16(acc[mf][nf][0], acc[mf][nf][1], acc[mf][nf][2], acc[mf][nf][3],
                            afh[mf][0], afh[mf][1], afh[mf][2], afh[mf][3],
                            bfl[nf][0], bfl[nf][1]);
            uint32_t afl[4][4];
            #pragma unroll
            for (int mf = 0; mf < 4; ++mf) {
                const uint32_t a = stage + TILEB +
                    (uint32_t)((warpM + mf * 16 + aRow) * PH + k16 + aCol) * 2u;
                ldmx4(afl[mf][0], afl[mf][1], afl[mf][2], afl[mf][3], a);
            }
            #pragma unroll
            for (int mf = 0; mf < 4; ++mf)
                #pragma unroll
                for (int nf = 0; nf < 4; ++nf)
                    mma_f16(acc[mf][nf][0], acc[mf][nf][1], acc[mf][nf][2], acc[mf][nf][3],
                            afl[mf][0], afl[mf][1], afl[mf][2], afl[mf][3],
                            bfh[nf][0], bfh[nf][1]);
        }
        __syncthreads();
        if (st + 2 < 32) issue_chunk(st + 2, sb + (st & 1) * STAGEB);
    }

    #pragma unroll
    for (int nf = 0; nf < 4; ++nf) {
        const int colg = col0 + warpN + nf * 8 + tig * 2;
        const float2 bb = *(const float2*)&bias[colg];
        #pragma unroll
        for (int mf = 0; mf < 4; ++mf) {
            const int rowg = row0 + warpM + mf * 16 + g;
            const float v00 = acc[mf][nf][0] + bb.x, v01 = acc[mf][nf][1] + bb.y;
            const float v10 = acc[mf][nf][2] + bb.x, v11 = acc[mf][nf][3] + bb.y;
            if (outF) {
                *(float2*)&outF[(size_t)rowg * C_ + colg]       = make_float2(v00, v01);
                *(float2*)&outF[(size_t)(rowg + 8) * C_ + colg] = make_float2(v10, v11);
            } else {
                uint32_t hh, ll;
                pack_hl(v00 * scale, v01 * scale, hh, ll);
                *(uint32_t*)&outH[(size_t)rowg * C_ + colg] = hh;
                *(uint32_t*)&outL[(size_t)rowg * C_ + colg] = ll;
                pack_hl(v10 * scale, v11 * scale, hh, ll);
                *(uint32_t*)&outH[(size_t)(rowg + 8) * C_ + colg] = hh;
                *(uint32_t*)&outL[(size_t)(rowg + 8) * C_ + colg] = ll;
            }
        }
    }
}

// Q scaled by (1/sqrt(D)) * log2(e) so softmax runs in exp2 domain
#define QSCALE (0.125f * 1.4426950408889634f)

__global__ void __launch_bounds__(256) qkv_kernel(
    const float* __restrict__ bq, const float* __restrict__ bk,
    const float* __restrict__ bv)
{
    const int sel = blockIdx.z;
    const __half* Wh   = (sel == 0) ? g_wqh : (sel == 1) ? g_wkh : g_wvh;
    const __half* Wl   = (sel == 0) ? g_wql : (sel == 1) ? g_wkl : g_wvl;
    const float*  bias = (sel == 0) ? bq    : (sel == 1) ? bk    : bv;
    __half* outH       = (sel == 0) ? g_qh  : (sel == 1) ? g_kh  : g_vh;
    __half* outL       = (sel == 0) ? g_ql  : (sel == 1) ? g_kl  : g_vl;
    const float scale  = (sel == 0) ? QSCALE : 1.0f;
    tc_gemm_tile(g_xh, g_xl, Wh, Wl, bias, nullptr, outH, outL, scale);
}

__global__ void __launch_bounds__(256) proj_kernel(
    const float* __restrict__ bp, float* __restrict__ out)
{
    tc_gemm_tile(g_ah, g_al, g_wph, g_wpl, bp, out, nullptr, nullptr, 1.0f);
}

// ---------------------------------------------------------------------------
// fp16x3 flash attention, cp.async double-buffered K/V, V via ldmatrix.trans.
// CTA per (b, h, 128-row q tile), heavy tiles launched first.
// ---------------------------------------------------------------------------
__global__ void __launch_bounds__(256) attn_kernel(const int* __restrict__ tmask)
{
    const uint32_t sb = smem_to_u32(dyn_smem);

    const int qt = (T_ / 128 - 1) - blockIdx.x;   // reversed: heavy CTAs first
    const int h = blockIdx.y, b = blockIdx.z;
    const int q0 = qt * 128;
    const int tid = threadIdx.x, w = tid >> 5, lane = tid & 31;
    const int g = lane >> 2, tig = lane & 3;
    const int rowBase = b * T_;
    const int hc = h * D_;

    // async-load Q tile (hi/lo)
    #pragma unroll
    for (int it = 0; it < 4; ++it) {
        const int gr = tid + it * 256;
        const int r = gr >> 3, c8 = (gr & 7) * 8;
        const size_t src = (size_t)(rowBase + q0 + r) * C_ + hc + c8;
        const uint32_t d = sb + (uint32_t)(r * PQ + c8) * 2u;
        cp_async16(d + QH_OFF, g_qh + src);
        cp_async16(d + QL_OFF, g_ql + src);
    }

    auto issueKV = [&](int kt, int buf) {
        const int k0 = kt * 128;
        const uint32_t base = sb + ST_OFF + (uint32_t)buf * STAGEA;
        #pragma unroll
        for (int it = 0; it < 4; ++it) {
            const int gr = tid + it * 256;
            const int r = gr >> 3, c8 = (gr & 7) * 8;
            const size_t src = (size_t)(rowBase + k0 + r) * C_ + hc + c8;
            const uint32_t d = base + (uint32_t)(r * PQ + c8) * 2u;
            cp_async16(d,              g_kh + src);
            cp_async16(d + TILEA,      g_kl + src);
            cp_async16(d + 2 * TILEA,  g_vh + src);
            cp_async16(d + 3 * TILEA,  g_vl + src);
        }
        if (tid < 32)
            cp_async16(sb + MSK_OFF + (uint32_t)buf * 512u + tid * 16,
                       tmask + b * T_ + k0 + tid * 4);
        CP_COMMIT();
    };

    issueKV(0, 0);   // group 0 = Q + KV(0)

    float o[8][4];
    #pragma unroll
    for (int nf = 0; nf < 8; ++nf)
        #pragma unroll
        for (int c = 0; c < 4; ++c) o[nf][c] = 0.f;
    float mA = -1e30f, mB = -1e30f, lA = 0.f, lB = 0.f;

    const int rA = q0 + w * 16 + g;
    const int rB = rA + 8;

    const int aRow = lane & 15, aCol = (lane >> 4) << 3;
    const int bRow = lane & 7,  bCol = ((lane >> 3) & 1) << 3;
    const int vRow = lane & 15;

    for (int kt = 0; kt <= qt; ++kt) {
        const int buf = kt & 1;
        if (kt < qt) {
            issueKV(kt + 1, buf ^ 1);
            asm volatile("cp.async.wait_group 1;" ::: "memory");
        } else {
            asm volatile("cp.async.wait_group 0;" ::: "memory");
        }
        __syncthreads();

        const int k0 = kt * 128;
        const uint32_t KH = sb + ST_OFF + (uint32_t)buf * STAGEA;
        const uint32_t KL = KH + TILEA;
        const uint32_t VH = KH + 2 * TILEA;
        const uint32_t VL = KH + 3 * TILEA;
        const int* Ms = (const int*)(dyn_smem + MSK_OFF + buf * 512);

        // ---- S = Q K^T (fp16x3) ----
        float s[16][4];
        #pragma unroll
        for (int nf = 0; nf < 16; ++nf)
            #pragma unroll
            for (int c = 0; c < 4; ++c) s[nf][c] = 0.f;

        #pragma unroll
        for (int kk = 0; kk < 4; ++kk) {
            const int k16 = kk * 16;
            uint32_t aqh[4], aql[4];
            ldmx4(aqh[0], aqh[1], aqh[2], aqh[3],
                  sb + QH_OFF + (uint32_t)((w * 16 + aRow) * PQ + k16 + aCol) * 2u);
            ldmx4(aql[0], aql[1], aql[2], aql[3],
                  sb + QL_OFF + (uint32_t)((w * 16 + aRow) * PQ + k16 + aCol) * 2u);
            #pragma unroll
            for (int nf = 0; nf < 16; ++nf) {
                uint32_t bh0, bh1, bl0, bl1;
                const uint32_t off = (uint32_t)((nf * 8 + bRow) * PQ + k16 + bCol) * 2u;
                ldmx2(bh0, bh1, KH + off);
                ldmx2(bl0, bl1, KL + off);
                mma_f16(s[nf][0], s[nf][1], s[nf][2], s[nf][3],
                        aqh[0], aqh[1], aqh[2], aqh[3], bh0, bh1);
                mma_f16(s[nf][0], s[nf][1], s[nf][2], s[nf][3],
                        aqh[0], aqh[1], aqh[2], aqh[3], bl0, bl1);
                mma_f16(s[nf][0], s[nf][1], s[nf][2], s[nf][3],
                        aql[0], aql[1], aql[2], aql[3], bh0, bh1);
            }
        }

        // ---- mask ----
        const bool diag = (kt == qt);
        #pragma unroll
        for (int nf = 0; nf < 16; ++nf) {
            #pragma unroll
            for (int c = 0; c < 4; ++c) {
                const int cl = nf * 8 + tig * 2 + (c & 1);
                bool ok = (Ms[cl] != 0);
                if (diag) ok = ok && (k0 + cl <= ((c < 2) ? rA : rB));
                if (!ok) s[nf][c] = -1e30f;
            }
        }

        // ---- online softmax (exp2 domain; Q pre-scaled by log2e/8) ----
        float mxA = -1e30f, mxB = -1e30f;
        #pragma unroll
        for (int nf = 0; nf < 16; ++nf) {
            mxA = fmaxf(mxA, fmaxf(s[nf][0], s[nf][1]));
            mxB = fmaxf(mxB, fmaxf(s[nf][2], s[nf][3]));
        }
        mxA = fmaxf(mxA, __shfl_xor_sync(0xffffffffu, mxA, 1));
        mxA = fmaxf(mxA, __shfl_xor_sync(0xffffffffu, mxA, 2));
        mxB = fmaxf(mxB, __shfl_xor_sync(0xffffffffu, mxB, 1));
        mxB = fmaxf(mxB, __shfl_xor_sync(0xffffffffu, mxB, 2));
        const float mnA = fmaxf(mA, mxA), mnB = fmaxf(mB, mxB);
        const float cA = ex2f(mA - mnA), cB = ex2f(mB - mnB);
        mA = mnA; mB = mnB;
        float sA = 0.f, sB = 0.f;
        #pragma unroll
        for (int nf = 0; nf < 16; ++nf) {
            s[nf][0] = ex2f(s[nf][0] - mnA);
            s[nf][1] = ex2f(s[nf][1] - mnA);
            s[nf][2] = ex2f(s[nf][2] - mnB);
            s[nf][3] = ex2f(s[nf][3] - mnB);
            sA += s[nf][0] + s[nf][1];
            sB += s[nf][2] + s[nf][3];
        }
        sA += __shfl_xor_sync(0xffffffffu, sA, 1);
        sA += __shfl_xor_sync(0xffffffffu, sA, 2);
        sB += __shfl_xor_sync(0xffffffffu, sB, 1);
        sB += __shfl_xor_sync(0xffffffffu, sB, 2);
        lA = lA * cA + sA;
        lB = lB * cB + sB;
        #pragma unroll
        for (int nf = 0; nf < 8; ++nf) {
            o[nf][0] *= cA; o[nf][1] *= cA;
            o[nf][2] *= cB; o[nf][3] *= cB;
        }

        // ---- O += P V (fp16x3), V row-major via ldmatrix.trans ----
        #pragma unroll
        for (int j = 0; j < 8; ++j) {
            uint32_t ph[4], pl[4];
            pack_hl(s[2*j][0],   s[2*j][1],   ph[0], pl[0]);
            pack_hl(s[2*j][2],   s[2*j][3],   ph[1], pl[1]);
            pack_hl(s[2*j+1][0], s[2*j+1][1], ph[2], pl[2]);
            pack_hl(s[2*j+1][2], s[2*j+1][3], ph[3], pl[3]);
            #pragma unroll
            for (int nf = 0; nf < 8; ++nf) {
                uint32_t bh0, bh1, bl0, bl1;
                const uint32_t off = (uint32_t)((j * 16 + vRow) * PQ + nf * 8) * 2u;
                ldmx2t(bh0, bh1, VH + off);
                ldmx2t(bl0, bl1, VL + off);
                mma_f16(o[nf][0], o[nf][1], o[nf][2], o[nf][3],
                        ph[0], ph[1], ph[2], ph[3], bh0, bh1);
                mma_f16(o[nf][0], o[nf][1], o[nf][2], o[nf][3],
                        ph[0], ph[1], ph[2], ph[3], bl0, bl1);
                mma_f16(o[nf][0], o[nf][1], o[nf][2], o[nf][3],
                        pl[0], pl[1], pl[2], pl[3], bh0, bh1);
            }
        }
        __syncthreads();   // all reads of buf done before it is refilled
    }

    // ---- normalize, split-fp16 output for proj GEMM ----
    const float invA = 1.f / lA, invB = 1.f / lB;
    #pragma unroll
    for (int nf = 0; nf < 8; ++nf) {
        const int col = hc + nf * 8 + tig * 2;
        const size_t iA = (size_t)(rowBase + rA) * C_ + col;
        const size_t iB = iA + (size_t)8 * C_;
        uint32_t hh, ll;
        pack_hl(o[nf][0] * invA, o[nf][1] * invA, hh, ll);
        *(uint32_t*)&g_ah[iA] = hh; *(uint32_t*)&g_al[iA] = ll;
        pack_hl(o[nf][2] * invB, o[nf][3] * invB, hh, ll);
        *(uint32_t*)&g_ah[iB] = hh; *(uint32_t*)&g_al[iB] = ll;
    }
}

// ---------------------------------------------------------------------------
// Launch
// ---------------------------------------------------------------------------
extern "C" void kernel_launch(void* const* d_in, const int* in_sizes, int n_in,
                              void* d_out, int out_size)
{
    const float* x  = (const float*)d_in[0];
    const int*   tm = (const int*)  d_in[1];
    const float* wq = (const float*)d_in[2];
    const float* bq = (const float*)d_in[3];
    const float* wk = (const float*)d_in[4];
    const float* bk = (const float*)d_in[5];
    const float* wv = (const float*)d_in[6];
    const float* bv = (const float*)d_in[7];
    const float* wp = (const float*)d_in[8];
    const float* bp = (const float*)d_in[9];
    float* out = (float*)d_out;

    cudaFuncSetAttribute(qkv_kernel,  cudaFuncAttributeMaxDynamicSharedMemorySize, GSMEM);
    cudaFuncSetAttribute(proj_kernel, cudaFuncAttributeMaxDynamicSharedMemorySize, GSMEM);
    cudaFuncSetAttribute(attn_kernel, cudaFuncAttributeMaxDynamicSharedMemorySize, ATT_SMEM);

    const int nX = M_ * C_;
    const int nW = C_ * C_;
    split_kernel<<<nX / 1024, 256>>>(x,  0, nX);
    split_kernel<<<nW / 1024, 256>>>(wq, 1, nW);
    split_kernel<<<nW / 1024, 256>>>(wk, 2, nW);
    split_kernel<<<nW / 1024, 256>>>(wv, 3, nW);
    split_kernel<<<nW / 1024, 256>>>(wp, 4, nW);

    dim3 gQKV(C_/128, M_/128, 3);
    qkv_kernel<<<gQKV, 256, GSMEM>>>(bq, bk, bv);

    dim3 gAtt(T_/128, NH_, B_);
    attn_kernel<<<gAtt, 256, ATT_SMEM>>>(tm);

    dim3 gProj(C_/128, M_/128, 1);
    proj_kernel<<<gProj, 256, GSMEM>>>(bp, out);
}

// round 8
// speedup vs baseline: 2.6688x; 1.2443x over previous
#include <cuda_runtime.h>
#include <cuda_fp16.h>
#include <cstdint>

#define B_  4
#define T_  2048
#define C_  1024
#define NH_ 16
#define D_  64
#define M_  (B_*T_)

// ---- GEMM smem (halves, pitch 40): 4 tiles/stage, 2 stages ----
#define PH     40
#define TILEB  10240u
#define STAGEB 40960u
#define GSMEM  81920

// ---- Attention smem: Q(h,l) 128x64 + 2 stages x (Kh,Kl,Vh,Vl) 64x64 + masks ----
#define PQ 72
#define QTILE  18432u              // 128*PQ*2
#define KVTILE 9216u               // 64*PQ*2
#define STAGEA 36864u              // 4 KV tiles
#define QH_OFF 0u
#define QL_OFF 18432u
#define ST_OFF 36864u
#define MSK_OFF 110592u            // 2 x 256B
#define ATT_SMEM 111104

extern __shared__ char dyn_smem[];

// Scratch (static device globals — no allocation at runtime)
__device__ __half g_qh[M_*C_],  g_ql[M_*C_];
__device__ __half g_kh[M_*C_],  g_kl[M_*C_];
__device__ __half g_vh[M_*C_],  g_vl[M_*C_];
__device__ __half g_ah[M_*C_],  g_al[M_*C_];
__device__ __half g_xh[M_*C_],  g_xl[M_*C_];
__device__ __half g_wqh[C_*C_], g_wql[C_*C_];
__device__ __half g_wkh[C_*C_], g_wkl[C_*C_];
__device__ __half g_wvh[C_*C_], g_wvl[C_*C_];
__device__ __half g_wph[C_*C_], g_wpl[C_*C_];

// ---------------------------------------------------------------------------
// helpers
// ---------------------------------------------------------------------------
__device__ __forceinline__ uint32_t smem_to_u32(const void* p) {
    uint32_t a;
    asm("{ .reg .u64 t; cvta.to.shared.u64 t, %1; cvt.u32.u64 %0, t; }"
        : "=r"(a) : "l"(p));
    return a;
}

__device__ __forceinline__ void cp_async16(uint32_t s, const void* g) {
    asm volatile("cp.async.cg.shared.global [%0], [%1], 16;" :: "r"(s), "l"(g));
}
#define CP_COMMIT() asm volatile("cp.async.commit_group;" ::: "memory")

__device__ __forceinline__ void ldmx4(uint32_t& r0, uint32_t& r1,
                                      uint32_t& r2, uint32_t& r3, uint32_t a) {
    asm volatile("ldmatrix.sync.aligned.m8n8.x4.shared.b16 {%0,%1,%2,%3}, [%4];"
                 : "=r"(r0), "=r"(r1), "=r"(r2), "=r"(r3) : "r"(a));
}
__device__ __forceinline__ void ldmx2(uint32_t& r0, uint32_t& r1, uint32_t a) {
    asm volatile("ldmatrix.sync.aligned.m8n8.x2.shared.b16 {%0,%1}, [%2];"
                 : "=r"(r0), "=r"(r1) : "r"(a));
}
__device__ __forceinline__ void ldmx2t(uint32_t& r0, uint32_t& r1, uint32_t a) {
    asm volatile("ldmatrix.sync.aligned.m8n8.x2.trans.shared.b16 {%0,%1}, [%2];"
                 : "=r"(r0), "=r"(r1) : "r"(a));
}

__device__ __forceinline__ void mma_f16(float& c0, float& c1, float& c2, float& c3,
                                        uint32_t a0, uint32_t a1, uint32_t a2, uint32_t a3,
                                        uint32_t b0, uint32_t b1) {
    asm volatile(
        "mma.sync.aligned.m16n8k16.row.col.f32.f16.f16.f32 "
        "{%0,%1,%2,%3}, {%4,%5,%6,%7}, {%8,%9}, {%0,%1,%2,%3};\n"
        : "+f"(c0), "+f"(c1), "+f"(c2), "+f"(c3)
        : "r"(a0), "r"(a1), "r"(a2), "r"(a3), "r"(b0), "r"(b1));
}

__device__ __forceinline__ float ex2f(float x) {
    float r;
    asm("ex2.approx.f32 %0, %1;" : "=f"(r) : "f"(x));
    return r;
}

// pack two fp32 -> one fp16x2 register (single cvt)
__device__ __forceinline__ uint32_t pack_h2(float x, float y) {
    uint32_t r;
    asm("cvt.rn.f16x2.f32 %0, %1, %2;" : "=r"(r) : "f"(y), "f"(x));
    return r;
}

__device__ __forceinline__ void pack_hl(float x, float y, uint32_t& hh, uint32_t& ll) {
    __half hx = __float2half_rn(x), hy = __float2half_rn(y);
    __half lx = __float2half_rn(x - __half2float(hx));
    __half ly = __float2half_rn(y - __half2float(hy));
    __half2 H = __halves2half2(hx, hy), L = __halves2half2(lx, ly);
    hh = *(uint32_t*)&H; ll = *(uint32_t*)&L;
}

// ---------------------------------------------------------------------------
// split prepass: fp32 -> (hi fp16, lo fp16).  sel: 0=x 1=wq 2=wk 3=wv 4=wp
// ---------------------------------------------------------------------------
__global__ void __launch_bounds__(256) split_kernel(const float* __restrict__ src,
                                                    int sel, int n)
{
    __half* dh; __half* dl;
    switch (sel) {
        case 0: dh = g_xh;  dl = g_xl;  break;
        case 1: dh = g_wqh; dl = g_wql; break;
        case 2: dh = g_wkh; dl = g_wkl; break;
        case 3: dh = g_wvh; dl = g_wvl; break;
        default: dh = g_wph; dl = g_wpl; break;
    }
    const int i4 = (blockIdx.x * 256 + threadIdx.x) * 4;
    if (i4 >= n) return;
    float4 v = *(const float4*)(src + i4);
    uint32_t h0, l0, h1, l1;
    pack_hl(v.x, v.y, h0, l0);
    pack_hl(v.z, v.w, h1, l1);
    *(uint32_t*)(dh + i4)     = h0;
    *(uint32_t*)(dh + i4 + 2) = h1;
    *(uint32_t*)(dl + i4)     = l0;
    *(uint32_t*)(dl + i4 + 2) = l1;
}

// ---------------------------------------------------------------------------
// fp16x3 GEMM: 128x128 tile of A[.,1024] @ W[.,1024]^T + bias  (unchanged)
// ---------------------------------------------------------------------------
__device__ __forceinline__ void tc_gemm_tile(
    const __half* __restrict__ Ah, const __half* __restrict__ Al,
    const __half* __restrict__ Wh, const __half* __restrict__ Wl,
    const float* __restrict__ bias,
    float* __restrict__ outF, __half* __restrict__ outH,
    __half* __restrict__ outL, float scale)
{
    const uint32_t sb = smem_to_u32(dyn_smem);

    const int tid  = threadIdx.x;
    const int wid  = tid >> 5;
    const int lane = tid & 31;
    const int g    = lane >> 2;
    const int tig  = lane & 3;

    const int row0 = blockIdx.y * 128;
    const int col0 = blockIdx.x * 128;
    const int warpM = (wid & 1) * 64;
    const int warpN = (wid >> 1) * 32;

    auto issue_chunk = [&](int st, uint32_t stage) {
        const int k0 = st * 32;
        #pragma unroll
        for (int p = 0; p < 2; ++p) {
            const int gid = tid + p * 256;
            const int r = gid >> 2, c = gid & 3;
            const uint32_t d = stage + (uint32_t)(r * PH + c * 8) * 2u;
            const size_t so = (size_t)(row0 + r) * C_ + k0 + c * 8;
            const size_t wo = (size_t)(col0 + r) * C_ + k0 + c * 8;
            cp_async16(d,             Ah + so);
            cp_async16(d + TILEB,     Al + so);
            cp_async16(d + 2 * TILEB, Wh + wo);
            cp_async16(d + 3 * TILEB, Wl + wo);
        }
        CP_COMMIT();
    };

    float acc[4][4][4];
    #pragma unroll
    for (int mf = 0; mf < 4; ++mf)
        #pragma unroll
        for (int nf = 0; nf < 4; ++nf)
            #pragma unroll
            for (int r = 0; r < 4; ++r) acc[mf][nf][r] = 0.f;

    issue_chunk(0, sb);
    issue_chunk(1, sb + STAGEB);

    const int aRow = (lane & 15);
    const int aCol = (lane >> 4) << 3;
    const int bRow = (lane & 7);
    const int bCol = ((lane >> 3) & 1) << 3;

    for (int st = 0; st < 32; ++st) {
        if (st < 31) { asm volatile("cp.async.wait_group 1;" ::: "memory"); }
        else         { asm volatile("cp.async.wait_group 0;" ::: "memory"); }
        __syncthreads();

        const uint32_t stage = sb + (st & 1) * STAGEB;

        #pragma unroll
        for (int kk = 0; kk < 2; ++kk) {
            const int k16 = kk * 16;

            uint32_t afh[4][4], bfh[4][2];
            #pragma unroll
            for (int mf = 0; mf < 4; ++mf) {
                const uint32_t a = stage +
                    (uint32_t)((warpM + mf * 16 + aRow) * PH + k16 + aCol) * 2u;
                ldmx4(afh[mf][0], afh[mf][1], afh[mf][2], afh[mf][3], a);
            }
            #pragma unroll
            for (int nf = 0; nf < 4; ++nf) {
                const uint32_t a = stage + 2 * TILEB +
                    (uint32_t)((warpN + nf * 8 + bRow) * PH + k16 + bCol) * 2u;
                ldmx2(bfh[nf][0], bfh[nf][1], a);
            }
            #pragma unroll
            for (int mf = 0; mf < 4; ++mf)
                #pragma unroll
                for (int nf = 0; nf < 4; ++nf)
                    mma_f16(acc[mf][nf][0], acc[mf][nf][1], acc[mf][nf][2], acc[mf][nf][3],
                            afh[mf][0], afh[mf][1], afh[mf][2], afh[mf][3],
                            bfh[nf][0], bfh[nf][1]);
            uint32_t bfl[4][2];
            #pragma unroll
            for (int nf = 0; nf < 4; ++nf) {
                const uint32_t a = stage + 3 * TILEB +
                    (uint32_t)((warpN + nf * 8 + bRow) * PH + k16 + bCol) * 2u;
                ldmx2(bfl[nf][0], bfl[nf][1], a);
            }
            #pragma unroll
            for (int mf = 0; mf < 4; ++mf)
                #pragma unroll
                for (int nf = 0; nf < 4; ++nf)
                    mma_f16(acc[mf][nf][0], acc[mf][nf][1], acc[mf][nf][2], acc[mf][nf][3],
                            afh[mf][0], afh[mf][1], afh[mf][2], afh[mf][3],
                            bfl[nf][0], bfl[nf][1]);
            uint32_t afl[4][4];
            #pragma unroll
            for (int mf = 0; mf < 4; ++mf) {
                const uint32_t a = stage + TILEB +
                    (uint32_t)((warpM + mf * 16 + aRow) * PH + k16 + aCol) * 2u;
                ldmx4(afl[mf][0], afl[mf][1], afl[mf][2], afl[mf][3], a);
            }
            #pragma unroll
            for (int mf = 0; mf < 4; ++mf)
                #pragma unroll
                for (int nf = 0; nf < 4; ++nf)
                    mma_f16(acc[mf][nf][0], acc[mf][nf][1], acc[mf][nf][2], acc[mf][nf][3],
                            afl[mf][0], afl[mf][1], afl[mf][2], afl[mf][3],
                            bfh[nf][0], bfh[nf][1]);
        }
        __syncthreads();
        if (st + 2 < 32) issue_chunk(st + 2, sb + (st & 1) * STAGEB);
    }

    #pragma unroll
    for (int nf = 0; nf < 4; ++nf) {
        const int colg = col0 + warpN + nf * 8 + tig * 2;
        const float2 bb = *(const float2*)&bias[colg];
        #pragma unroll
        for (int mf = 0; mf < 4; ++mf) {
            const int rowg = row0 + warpM + mf * 16 + g;
            const float v00 = acc[mf][nf][0] + bb.x, v01 = acc[mf][nf][1] + bb.y;
            const float v10 = acc[mf][nf][2] + bb.x, v11 = acc[mf][nf][3] + bb.y;
            if (outF) {
                *(float2*)&outF[(size_t)rowg * C_ + colg]       = make_float2(v00, v01);
                *(float2*)&outF[(size_t)(rowg + 8) * C_ + colg] = make_float2(v10, v11);
            } else {
                uint32_t hh, ll;
                pack_hl(v00 * scale, v01 * scale, hh, ll);
                *(uint32_t*)&outH[(size_t)rowg * C_ + colg] = hh;
                *(uint32_t*)&outL[(size_t)rowg * C_ + colg] = ll;
                pack_hl(v10 * scale, v11 * scale, hh, ll);
                *(uint32_t*)&outH[(size_t)(rowg + 8) * C_ + colg] = hh;
                *(uint32_t*)&outL[(size_t)(rowg + 8) * C_ + colg] = ll;
            }
        }
    }
}

// Q scaled by (1/sqrt(D)) * log2(e) so softmax runs in exp2 domain
#define QSCALE (0.125f * 1.4426950408889634f)

__global__ void __launch_bounds__(256) qkv_kernel(
    const float* __restrict__ bq, const float* __restrict__ bk,
    const float* __restrict__ bv)
{
    const int sel = blockIdx.z;
    const __half* Wh   = (sel == 0) ? g_wqh : (sel == 1) ? g_wkh : g_wvh;
    const __half* Wl   = (sel == 0) ? g_wql : (sel == 1) ? g_wkl : g_wvl;
    const float*  bias = (sel == 0) ? bq    : (sel == 1) ? bk    : bv;
    __half* outH       = (sel == 0) ? g_qh  : (sel == 1) ? g_kh  : g_vh;
    __half* outL       = (sel == 0) ? g_ql  : (sel == 1) ? g_kl  : g_vl;
    const float scale  = (sel == 0) ? QSCALE : 1.0f;
    tc_gemm_tile(g_xh, g_xl, Wh, Wl, bias, nullptr, outH, outL, scale);
}

__global__ void __launch_bounds__(256) proj_kernel(
    const float* __restrict__ bp, float* __restrict__ out)
{
    tc_gemm_tile(g_ah, g_al, g_wph, g_wpl, bp, out, nullptr, nullptr, 1.0f);
}

// ---------------------------------------------------------------------------
// fp16x3 flash attention, 64-col k-tiles (2 CTAs/SM), ballot bitmask token
// mask, PV = Ph(Vh+Vl) with single-cvt P packing. Heavy q-tiles first.
// ---------------------------------------------------------------------------
__global__ void __launch_bounds__(256, 2) attn_kernel(const int* __restrict__ tmask)
{
    const uint32_t sb = smem_to_u32(dyn_smem);

    const int qt = (T_ / 128 - 1) - blockIdx.x;
    const int h = blockIdx.y, b = blockIdx.z;
    const int q0 = qt * 128;
    const int tid = threadIdx.x, w = tid >> 5, lane = tid & 31;
    const int g = lane >> 2, tig = lane & 3;
    const int rowBase = b * T_;
    const int hc = h * D_;

    // async-load Q tile (hi/lo), 128 x 64 halves each
    #pragma unroll
    for (int it = 0; it < 4; ++it) {
        const int gr = tid + it * 256;
        const int r = gr >> 3, c8 = (gr & 7) * 8;
        const size_t src = (size_t)(rowBase + q0 + r) * C_ + hc + c8;
        const uint32_t d = sb + (uint32_t)(r * PQ + c8) * 2u;
        cp_async16(d + QH_OFF, g_qh + src);
        cp_async16(d + QL_OFF, g_ql + src);
    }

    auto issueKV = [&](int kt, int buf) {
        const int k0 = kt * 64;
        const uint32_t base = sb + ST_OFF + (uint32_t)buf * STAGEA;
        #pragma unroll
        for (int it = 0; it < 2; ++it) {
            const int gr = tid + it * 256;
            const int r = gr >> 3, c8 = (gr & 7) * 8;
            const size_t src = (size_t)(rowBase + k0 + r) * C_ + hc + c8;
            const uint32_t d = base + (uint32_t)(r * PQ + c8) * 2u;
            cp_async16(d,              g_kh + src);
            cp_async16(d + KVTILE,     g_kl + src);
            cp_async16(d + 2 * KVTILE, g_vh + src);
            cp_async16(d + 3 * KVTILE, g_vl + src);
        }
        if (tid < 16)
            cp_async16(sb + MSK_OFF + (uint32_t)buf * 256u + tid * 16,
                       tmask + b * T_ + k0 + tid * 4);
        CP_COMMIT();
    };

    issueKV(0, 0);

    float o[8][4];
    #pragma unroll
    for (int nf = 0; nf < 8; ++nf)
        #pragma unroll
        for (int c = 0; c < 4; ++c) o[nf][c] = 0.f;
    float mA = -1e30f, mB = -1e30f, lA = 0.f, lB = 0.f;

    const int rA = q0 + w * 16 + g;
    const int rB = rA + 8;

    const int aRow = lane & 15, aCol = (lane >> 4) << 3;
    const int bRow = lane & 7,  bCol = ((lane >> 3) & 1) << 3;
    const int vRow = lane & 15;

    const int nkt = 2 * qt + 2;
    for (int kt = 0; kt < nkt; ++kt) {
        const int buf = kt & 1;
        if (kt + 1 < nkt) {
            issueKV(kt + 1, buf ^ 1);
            asm volatile("cp.async.wait_group 1;" ::: "memory");
        } else {
            asm volatile("cp.async.wait_group 0;" ::: "memory");
        }
        __syncthreads();

        const int k0 = kt * 64;
        const uint32_t KH = sb + ST_OFF + (uint32_t)buf * STAGEA;
        const uint32_t KL = KH + KVTILE;
        const uint32_t VH = KH + 2 * KVTILE;
        const uint32_t VL = KH + 3 * KVTILE;
        const int* Ms = (const int*)(dyn_smem + MSK_OFF + buf * 256);

        // token mask -> 64-bit ballot mask (2 x uint32, warp-uniform)
        const uint32_t msk0 = __ballot_sync(0xffffffffu, Ms[lane] != 0);
        const uint32_t msk1 = __ballot_sync(0xffffffffu, Ms[lane + 32] != 0);

        // ---- S = Q K^T (fp16x3) ----
        float s[8][4];
        #pragma unroll
        for (int nf = 0; nf < 8; ++nf)
            #pragma unroll
            for (int c = 0; c < 4; ++c) s[nf][c] = 0.f;

        #pragma unroll
        for (int kk = 0; kk < 4; ++kk) {
            const int k16 = kk * 16;
            uint32_t aqh[4], aql[4];
            ldmx4(aqh[0], aqh[1], aqh[2], aqh[3],
                  sb + QH_OFF + (uint32_t)((w * 16 + aRow) * PQ + k16 + aCol) * 2u);
            ldmx4(aql[0], aql[1], aql[2], aql[3],
                  sb + QL_OFF + (uint32_t)((w * 16 + aRow) * PQ + k16 + aCol) * 2u);
            #pragma unroll
            for (int nf = 0; nf < 8; ++nf) {
                uint32_t bh0, bh1, bl0, bl1;
                const uint32_t off = (uint32_t)((nf * 8 + bRow) * PQ + k16 + bCol) * 2u;
                ldmx2(bh0, bh1, KH + off);
                ldmx2(bl0, bl1, KL + off);
                mma_f16(s[nf][0], s[nf][1], s[nf][2], s[nf][3],
                        aqh[0], aqh[1], aqh[2], aqh[3], bh0, bh1);
                mma_f16(s[nf][0], s[nf][1], s[nf][2], s[nf][3],
                        aqh[0], aqh[1], aqh[2], aqh[3], bl0, bl1);
                mma_f16(s[nf][0], s[nf][1], s[nf][2], s[nf][3],
                        aql[0], aql[1], aql[2], aql[3], bh0, bh1);
            }
        }

        // ---- mask: token bitmask + causal on last two tiles ----
        const bool diag = (kt >= 2 * qt);
        #pragma unroll
        for (int nf = 0; nf < 8; ++nf) {
            const uint32_t word = (nf < 4) ? msk0 : msk1;
            const uint32_t pr = (word >> (((nf & 3) << 3) + tig * 2)) & 3u;
            bool ok0 = (pr & 1u), ok1 = (pr & 2u);
            const int c0 = k0 + nf * 8 + tig * 2;
            if (diag) {
                s[nf][0] = (ok0 && c0     <= rA) ? s[nf][0] : -1e30f;
                s[nf][1] = (ok1 && c0 + 1 <= rA) ? s[nf][1] : -1e30f;
                s[nf][2] = (ok0 && c0     <= rB) ? s[nf][2] : -1e30f;
                s[nf][3] = (ok1 && c0 + 1 <= rB) ? s[nf][3] : -1e30f;
            } else {
                if (!ok0) { s[nf][0] = -1e30f; s[nf][2] = -1e30f; }
                if (!ok1) { s[nf][1] = -1e30f; s[nf][3] = -1e30f; }
            }
        }

        // ---- online softmax (exp2 domain) ----
        float mxA = -1e30f, mxB = -1e30f;
        #pragma unroll
        for (int nf = 0; nf < 8; ++nf) {
            mxA = fmaxf(mxA, fmaxf(s[nf][0], s[nf][1]));
            mxB = fmaxf(mxB, fmaxf(s[nf][2], s[nf][3]));
        }
        mxA = fmaxf(mxA, __shfl_xor_sync(0xffffffffu, mxA, 1));
        mxA = fmaxf(mxA, __shfl_xor_sync(0xffffffffu, mxA, 2));
        mxB = fmaxf(mxB, __shfl_xor_sync(0xffffffffu, mxB, 1));
        mxB = fmaxf(mxB, __shfl_xor_sync(0xffffffffu, mxB, 2));
        const float mnA = fmaxf(mA, mxA), mnB = fmaxf(mB, mxB);
        const float cA = ex2f(mA - mnA), cB = ex2f(mB - mnB);
        mA = mnA; mB = mnB;
        float sA = 0.f, sB = 0.f;
        #pragma unroll
        for (int nf = 0; nf < 8; ++nf) {
            s[nf][0] = ex2f(s[nf][0] - mnA);
            s[nf][1] = ex2f(s[nf][1] - mnA);
            s[nf][2] = ex2f(s[nf][2] - mnB);
            s[nf][3] = ex2f(s[nf][3] - mnB);
            sA += s[nf][0] + s[nf][1];
            sB += s[nf][2] + s[nf][3];
        }
        sA += __shfl_xor_sync(0xffffffffu, sA, 1);
        sA += __shfl_xor_sync(0xffffffffu, sA, 2);
        sB += __shfl_xor_sync(0xffffffffu, sB, 1);
        sB += __shfl_xor_sync(0xffffffffu, sB, 2);
        lA = lA * cA + sA;
        lB = lB * cB + sB;
        #pragma unroll
        for (int nf = 0; nf < 8; ++nf) {
            o[nf][0] *= cA; o[nf][1] *= cA;
            o[nf][2] *= cB; o[nf][3] *= cB;
        }

        // ---- O += Ph (Vh + Vl): P hi-only, single-cvt packing ----
        #pragma unroll
        for (int j = 0; j < 4; ++j) {
            uint32_t ph[4];
            ph[0] = pack_h2(s[2*j][0],   s[2*j][1]);
            ph[1] = pack_h2(s[2*j][2],   s[2*j][3]);
            ph[2] = pack_h2(s[2*j+1][0], s[2*j+1][1]);
            ph[3] = pack_h2(s[2*j+1][2], s[2*j+1][3]);
            #pragma unroll
            for (int nf = 0; nf < 8; ++nf) {
                uint32_t bh0, bh1, bl0, bl1;
                const uint32_t off = (uint32_t)((j * 16 + vRow) * PQ + nf * 8) * 2u;
                ldmx2t(bh0, bh1, VH + off);
                ldmx2t(bl0, bl1, VL + off);
                mma_f16(o[nf][0], o[nf][1], o[nf][2], o[nf][3],
                        ph[0], ph[1], ph[2], ph[3], bh0, bh1);
                mma_f16(o[nf][0], o[nf][1], o[nf][2], o[nf][3],
                        ph[0], ph[1], ph[2], ph[3], bl0, bl1);
            }
        }
        __syncthreads();
    }

    // ---- normalize, split-fp16 output for proj GEMM ----
    const float invA = 1.f / lA, invB = 1.f / lB;
    #pragma unroll
    for (int nf = 0; nf < 8; ++nf) {
        const int col = hc + nf * 8 + tig * 2;
        const size_t iA = (size_t)(rowBase + rA) * C_ + col;
        const size_t iB = iA + (size_t)8 * C_;
        uint32_t hh, ll;
        pack_hl(o[nf][0] * invA, o[nf][1] * invA, hh, ll);
        *(uint32_t*)&g_ah[iA] = hh; *(uint32_t*)&g_al[iA] = ll;
        pack_hl(o[nf][2] * invB, o[nf][3] * invB, hh, ll);
        *(uint32_t*)&g_ah[iB] = hh; *(uint32_t*)&g_al[iB] = ll;
    }
}

// ---------------------------------------------------------------------------
// Launch
// ---------------------------------------------------------------------------
extern "C" void kernel_launch(void* const* d_in, const int* in_sizes, int n_in,
                              void* d_out, int out_size)
{
    const float* x  = (const float*)d_in[0];
    const int*   tm = (const int*)  d_in[1];
    const float* wq = (const float*)d_in[2];
    const float* bq = (const float*)d_in[3];
    const float* wk = (const float*)d_in[4];
    const float* bk = (const float*)d_in[5];
    const float* wv = (const float*)d_in[6];
    const float* bv = (const float*)d_in[7];
    const float* wp = (const float*)d_in[8];
    const float* bp = (const float*)d_in[9];
    float* out = (float*)d_out;

    cudaFuncSetAttribute(qkv_kernel,  cudaFuncAttributeMaxDynamicSharedMemorySize, GSMEM);
    cudaFuncSetAttribute(proj_kernel, cudaFuncAttributeMaxDynamicSharedMemorySize, GSMEM);
    cudaFuncSetAttribute(attn_kernel, cudaFuncAttributeMaxDynamicSharedMemorySize, ATT_SMEM);

    const int nX = M_ * C_;
    const int nW = C_ * C_;
    split_kernel<<<nX / 1024, 256>>>(x,  0, nX);
    split_kernel<<<nW / 1024, 256>>>(wq, 1, nW);
    split_kernel<<<nW / 1024, 256>>>(wk, 2, nW);
    split_kernel<<<nW / 1024, 256>>>(wv, 3, nW);
    split_kernel<<<nW / 1024, 256>>>(wp, 4, nW);

    dim3 gQKV(C_/128, M_/128, 3);
    qkv_kernel<<<gQKV, 256, GSMEM>>>(bq, bk, bv);

    dim3 gAtt(T_/128, NH_, B_);
    attn_kernel<<<gAtt, 256, ATT_SMEM>>>(tm);

    dim3 gProj(C_/128, M_/128, 1);
    proj_kernel<<<gProj, 256, GSMEM>>>(bp, out);
}

// round 9
// speedup vs baseline: 3.0528x; 1.1439x over previous
#include <cuda_runtime.h>
#include <cuda_fp16.h>
#include <cstdint>

#define B_  4
#define T_  2048
#define C_  1024
#define NH_ 16
#define D_  64
#define M_  (B_*T_)

// ---- GEMM smem (halves, pitch 40): 4 tiles/stage, 2 stages ----
#define PH     40
#define TILEB  10240u
#define STAGEB 40960u
#define GSMEM  81920

// ---- Attention smem: Q(h,l) 128x64 + 2 stages x (Kh,Kl,Vh,Vl) 64x64 ----
#define PQ 72
#define KVTILE 9216u               // 64*PQ*2
#define STAGEA 36864u              // 4 KV tiles
#define QH_OFF 0u
#define QL_OFF 18432u
#define ST_OFF 36864u
#define ATT_SMEM 110592

extern __shared__ char dyn_smem[];

// Scratch (static device globals — no allocation at runtime)
__device__ __half g_qh[M_*C_],  g_ql[M_*C_];
__device__ __half g_kh[M_*C_],  g_kl[M_*C_];
__device__ __half g_vh[M_*C_],  g_vl[M_*C_];
__device__ __half g_ah[M_*C_],  g_al[M_*C_];
__device__ __half g_xh[M_*C_],  g_xl[M_*C_];
__device__ __half g_wqh[C_*C_], g_wql[C_*C_];
__device__ __half g_wkh[C_*C_], g_wkl[C_*C_];
__device__ __half g_wvh[C_*C_], g_wvl[C_*C_];
__device__ __half g_wph[C_*C_], g_wpl[C_*C_];
// mask compaction
__device__ int    g_cnt[B_*T_];            // inclusive count of valid tokens <= t
__device__ int    g_pos[B_*T_];            // compact index j -> original position
__device__ __half g_kch[M_*C_], g_kcl[M_*C_];
__device__ __half g_vch[M_*C_], g_vcl[M_*C_];

// ---------------------------------------------------------------------------
// helpers
// ---------------------------------------------------------------------------
__device__ __forceinline__ uint32_t smem_to_u32(const void* p) {
    uint32_t a;
    asm("{ .reg .u64 t; cvta.to.shared.u64 t, %1; cvt.u32.u64 %0, t; }"
        : "=r"(a) : "l"(p));
    return a;
}

__device__ __forceinline__ void cp_async16(uint32_t s, const void* g) {
    asm volatile("cp.async.cg.shared.global [%0], [%1], 16;" :: "r"(s), "l"(g));
}
#define CP_COMMIT() asm volatile("cp.async.commit_group;" ::: "memory")

__device__ __forceinline__ void ldmx4(uint32_t& r0, uint32_t& r1,
                                      uint32_t& r2, uint32_t& r3, uint32_t a) {
    asm volatile("ldmatrix.sync.aligned.m8n8.x4.shared.b16 {%0,%1,%2,%3}, [%4];"
                 : "=r"(r0), "=r"(r1), "=r"(r2), "=r"(r3) : "r"(a));
}
__device__ __forceinline__ void ldmx2(uint32_t& r0, uint32_t& r1, uint32_t a) {
    asm volatile("ldmatrix.sync.aligned.m8n8.x2.shared.b16 {%0,%1}, [%2];"
                 : "=r"(r0), "=r"(r1) : "r"(a));
}
__device__ __forceinline__ void ldmx2t(uint32_t& r0, uint32_t& r1, uint32_t a) {
    asm volatile("ldmatrix.sync.aligned.m8n8.x2.trans.shared.b16 {%0,%1}, [%2];"
                 : "=r"(r0), "=r"(r1) : "r"(a));
}

__device__ __forceinline__ void mma_f16(float& c0, float& c1, float& c2, float& c3,
                                        uint32_t a0, uint32_t a1, uint32_t a2, uint32_t a3,
                                        uint32_t b0, uint32_t b1) {
    asm volatile(
        "mma.sync.aligned.m16n8k16.row.col.f32.f16.f16.f32 "
        "{%0,%1,%2,%3}, {%4,%5,%6,%7}, {%8,%9}, {%0,%1,%2,%3};\n"
        : "+f"(c0), "+f"(c1), "+f"(c2), "+f"(c3)
        : "r"(a0), "r"(a1), "r"(a2), "r"(a3), "r"(b0), "r"(b1));
}

__device__ __forceinline__ float ex2f(float x) {
    float r;
    asm("ex2.approx.f32 %0, %1;" : "=f"(r) : "f"(x));
    return r;
}

__device__ __forceinline__ uint32_t pack_h2(float x, float y) {
    uint32_t r;
    asm("cvt.rn.f16x2.f32 %0, %1, %2;" : "=r"(r) : "f"(y), "f"(x));
    return r;
}

__device__ __forceinline__ void pack_hl(float x, float y, uint32_t& hh, uint32_t& ll) {
    __half hx = __float2half_rn(x), hy = __float2half_rn(y);
    __half lx = __float2half_rn(x - __half2float(hx));
    __half ly = __float2half_rn(y - __half2float(hy));
    __half2 H = __halves2half2(hx, hy), L = __halves2half2(lx, ly);
    hh = *(uint32_t*)&H; ll = *(uint32_t*)&L;
}

// ---------------------------------------------------------------------------
// split prepass: fp32 -> (hi fp16, lo fp16).  sel: 0=x 1=wq 2=wk 3=wv 4=wp
// ---------------------------------------------------------------------------
__global__ void __launch_bounds__(256) split_kernel(const float* __restrict__ src,
                                                    int sel, int n)
{
    __half* dh; __half* dl;
    switch (sel) {
        case 0: dh = g_xh;  dl = g_xl;  break;
        case 1: dh = g_wqh; dl = g_wql; break;
        case 2: dh = g_wkh; dl = g_wkl; break;
        case 3: dh = g_wvh; dl = g_wvl; break;
        default: dh = g_wph; dl = g_wpl; break;
    }
    const int i4 = (blockIdx.x * 256 + threadIdx.x) * 4;
    if (i4 >= n) return;
    float4 v = *(const float4*)(src + i4);
    uint32_t h0, l0, h1, l1;
    pack_hl(v.x, v.y, h0, l0);
    pack_hl(v.z, v.w, h1, l1);
    *(uint32_t*)(dh + i4)     = h0;
    *(uint32_t*)(dh + i4 + 2) = h1;
    *(uint32_t*)(dl + i4)     = l0;
    *(uint32_t*)(dl + i4 + 2) = l1;
}

// ---------------------------------------------------------------------------
// token-mask scan: per batch, inclusive counts + compact position list
// ---------------------------------------------------------------------------
__global__ void __launch_bounds__(256) mask_scan_kernel(const int* __restrict__ tmask)
{
    __shared__ int wsum[8];
    const int b = blockIdx.x;
    const int tid = threadIdx.x;
    const int lane = tid & 31, wid = tid >> 5;
    const int t0 = tid * 8;

    int v[8]; int s = 0;
    #pragma unroll
    for (int i = 0; i < 8; ++i) { v[i] = (tmask[b*T_ + t0 + i] != 0) ? 1 : 0; s += v[i]; }

    int sc = s;
    #pragma unroll
    for (int off = 1; off < 32; off <<= 1) {
        int n = __shfl_up_sync(0xffffffffu, sc, off);
        if (lane >= off) sc += n;
    }
    if (lane == 31) wsum[wid] = sc;
    __syncthreads();
    if (tid == 0) {
        int acc = 0;
        #pragma unroll
        for (int i = 0; i < 8; ++i) { acc += wsum[i]; wsum[i] = acc; }
    }
    __syncthreads();
    const int wbase = (wid > 0) ? wsum[wid - 1] : 0;
    int run = wbase + sc - s;   // exclusive prefix for this thread's first element
    #pragma unroll
    for (int i = 0; i < 8; ++i) {
        run += v[i];
        g_cnt[b*T_ + t0 + i] = run;
        if (v[i]) g_pos[b*T_ + run - 1] = t0 + i;
    }
}

// ---------------------------------------------------------------------------
// gather valid K/V rows into compacted buffers
// ---------------------------------------------------------------------------
__global__ void __launch_bounds__(256) gather_kv_kernel()
{
    const int j = blockIdx.x, b = blockIdx.y;
    if (j >= g_cnt[b*T_ + T_ - 1]) return;
    const int src = g_pos[b*T_ + j];
    const size_t so = (size_t)(b*T_ + src) * C_;
    const size_t dofs = (size_t)(b*T_ + j) * C_;
    for (int u = threadIdx.x; u < 512; u += 256) {
        const int arr = u >> 7, i = u & 127;
        const __half* sa = (arr == 0) ? g_kh : (arr == 1) ? g_kl
                         : (arr == 2) ? g_vh : g_vl;
        __half* da       = (arr == 0) ? g_kch : (arr == 1) ? g_kcl
                         : (arr == 2) ? g_vch : g_vcl;
        ((float4*)(da + dofs))[i] = ((const float4*)(sa + so))[i];
    }
}

// ---------------------------------------------------------------------------
// fp16x3 GEMM: 128x128 tile of A[.,1024] @ W[.,1024]^T + bias  (unchanged)
// ---------------------------------------------------------------------------
__device__ __forceinline__ void tc_gemm_tile(
    const __half* __restrict__ Ah, const __half* __restrict__ Al,
    const __half* __restrict__ Wh, const __half* __restrict__ Wl,
    const float* __restrict__ bias,
    float* __restrict__ outF, __half* __restrict__ outH,
    __half* __restrict__ outL, float scale)
{
    const uint32_t sb = smem_to_u32(dyn_smem);

    const int tid  = threadIdx.x;
    const int wid  = tid >> 5;
    const int lane = tid & 31;
    const int g    = lane >> 2;
    const int tig  = lane & 3;

    const int row0 = blockIdx.y * 128;
    const int col0 = blockIdx.x * 128;
    const int warpM = (wid & 1) * 64;
    const int warpN = (wid >> 1) * 32;

    auto issue_chunk = [&](int st, uint32_t stage) {
        const int k0 = st * 32;
        #pragma unroll
        for (int p = 0; p < 2; ++p) {
            const int gid = tid + p * 256;
            const int r = gid >> 2, c = gid & 3;
            const uint32_t d = stage + (uint32_t)(r * PH + c * 8) * 2u;
            const size_t so = (size_t)(row0 + r) * C_ + k0 + c * 8;
            const size_t wo = (size_t)(col0 + r) * C_ + k0 + c * 8;
            cp_async16(d,             Ah + so);
            cp_async16(d + TILEB,     Al + so);
            cp_async16(d + 2 * TILEB, Wh + wo);
            cp_async16(d + 3 * TILEB, Wl + wo);
        }
        CP_COMMIT();
    };

    float acc[4][4][4];
    #pragma unroll
    for (int mf = 0; mf < 4; ++mf)
        #pragma unroll
        for (int nf = 0; nf < 4; ++nf)
            #pragma unroll
            for (int r = 0; r < 4; ++r) acc[mf][nf][r] = 0.f;

    issue_chunk(0, sb);
    issue_chunk(1, sb + STAGEB);

    const int aRow = (lane & 15);
    const int aCol = (lane >> 4) << 3;
    const int bRow = (lane & 7);
    const int bCol = ((lane >> 3) & 1) << 3;

    for (int st = 0; st < 32; ++st) {
        if (st < 31) { asm volatile("cp.async.wait_group 1;" ::: "memory"); }
        else         { asm volatile("cp.async.wait_group 0;" ::: "memory"); }
        __syncthreads();

        const uint32_t stage = sb + (st & 1) * STAGEB;

        #pragma unroll
        for (int kk = 0; kk < 2; ++kk) {
            const int k16 = kk * 16;

            uint32_t afh[4][4], bfh[4][2];
            #pragma unroll
            for (int mf = 0; mf < 4; ++mf) {
                const uint32_t a = stage +
                    (uint32_t)((warpM + mf * 16 + aRow) * PH + k16 + aCol) * 2u;
                ldmx4(afh[mf][0], afh[mf][1], afh[mf][2], afh[mf][3], a);
            }
            #pragma unroll
            for (int nf = 0; nf < 4; ++nf) {
                const uint32_t a = stage + 2 * TILEB +
                    (uint32_t)((warpN + nf * 8 + bRow) * PH + k16 + bCol) * 2u;
                ldmx2(bfh[nf][0], bfh[nf][1], a);
            }
            #pragma unroll
            for (int mf = 0; mf < 4; ++mf)
                #pragma unroll
                for (int nf = 0; nf < 4; ++nf)
                    mma_f16(acc[mf][nf][0], acc[mf][nf][1], acc[mf][nf][2], acc[mf][nf][3],
                            afh[mf][0], afh[mf][1], afh[mf][2], afh[mf][3],
                            bfh[nf][0], bfh[nf][1]);
            uint32_t bfl[4][2];
            #pragma unroll
            for (int nf = 0; nf < 4; ++nf) {
                const uint32_t a = stage + 3 * TILEB +
                    (uint32_t)((warpN + nf * 8 + bRow) * PH + k16 + bCol) * 2u;
                ldmx2(bfl[nf][0], bfl[nf][1], a);
            }
            #pragma unroll
            for (int mf = 0; mf < 4; ++mf)
                #pragma unroll
                for (int nf = 0; nf < 4; ++nf)
                    mma_f16(acc[mf][nf][0], acc[mf][nf][1], acc[mf][nf][2], acc[mf][nf][3],
                            afh[mf][0], afh[mf][1], afh[mf][2], afh[mf][3],
                            bfl[nf][0], bfl[nf][1]);
            uint32_t afl[4][4];
            #pragma unroll
            for (int mf = 0; mf < 4; ++mf) {
                const uint32_t a = stage + TILEB +
                    (uint32_t)((warpM + mf * 16 + aRow) * PH + k16 + aCol) * 2u;
                ldmx4(afl[mf][0], afl[mf][1], afl[mf][2], afl[mf][3], a);
            }
            #pragma unroll
            for (int mf = 0; mf < 4; ++mf)
                #pragma unroll
                for (int nf = 0; nf < 4; ++nf)
                    mma_f16(acc[mf][nf][0], acc[mf][nf][1], acc[mf][nf][2], acc[mf][nf][3],
                            afl[mf][0], afl[mf][1], afl[mf][2], afl[mf][3],
                            bfh[nf][0], bfh[nf][1]);
        }
        __syncthreads();
        if (st + 2 < 32) issue_chunk(st + 2, sb + (st & 1) * STAGEB);
    }

    #pragma unroll
    for (int nf = 0; nf < 4; ++nf) {
        const int colg = col0 + warpN + nf * 8 + tig * 2;
        const float2 bb = *(const float2*)&bias[colg];
        #pragma unroll
        for (int mf = 0; mf < 4; ++mf) {
            const int rowg = row0 + warpM + mf * 16 + g;
            const float v00 = acc[mf][nf][0] + bb.x, v01 = acc[mf][nf][1] + bb.y;
            const float v10 = acc[mf][nf][2] + bb.x, v11 = acc[mf][nf][3] + bb.y;
            if (outF) {
                *(float2*)&outF[(size_t)rowg * C_ + colg]       = make_float2(v00, v01);
                *(float2*)&outF[(size_t)(rowg + 8) * C_ + colg] = make_float2(v10, v11);
            } else {
                uint32_t hh, ll;
                pack_hl(v00 * scale, v01 * scale, hh, ll);
                *(uint32_t*)&outH[(size_t)rowg * C_ + colg] = hh;
                *(uint32_t*)&outL[(size_t)rowg * C_ + colg] = ll;
                pack_hl(v10 * scale, v11 * scale, hh, ll);
                *(uint32_t*)&outH[(size_t)(rowg + 8) * C_ + colg] = hh;
                *(uint32_t*)&outL[(size_t)(rowg + 8) * C_ + colg] = ll;
            }
        }
    }
}

// Q scaled by (1/sqrt(D)) * log2(e) so softmax runs in exp2 domain
#define QSCALE (0.125f * 1.4426950408889634f)

__global__ void __launch_bounds__(256) qkv_kernel(
    const float* __restrict__ bq, const float* __restrict__ bk,
    const float* __restrict__ bv)
{
    const int sel = blockIdx.z;
    const __half* Wh   = (sel == 0) ? g_wqh : (sel == 1) ? g_wkh : g_wvh;
    const __half* Wl   = (sel == 0) ? g_wql : (sel == 1) ? g_wkl : g_wvl;
    const float*  bias = (sel == 0) ? bq    : (sel == 1) ? bk    : bv;
    __half* outH       = (sel == 0) ? g_qh  : (sel == 1) ? g_kh  : g_vh;
    __half* outL       = (sel == 0) ? g_ql  : (sel == 1) ? g_kl  : g_vl;
    const float scale  = (sel == 0) ? QSCALE : 1.0f;
    tc_gemm_tile(g_xh, g_xl, Wh, Wl, bias, nullptr, outH, outL, scale);
}

__global__ void __launch_bounds__(256) proj_kernel(
    const float* __restrict__ bp, float* __restrict__ out)
{
    tc_gemm_tile(g_ah, g_al, g_wph, g_wpl, bp, out, nullptr, nullptr, 1.0f);
}

// ---------------------------------------------------------------------------
// fp16x3 flash attention over COMPACTED K/V: only valid token columns.
// Causal+token mask folds into one compare: compact index j < cnt(row).
// 64-col k-tiles (2 CTAs/SM), heavy q-tiles first.
// ---------------------------------------------------------------------------
__global__ void __launch_bounds__(256, 2) attn_kernel()
{
    const uint32_t sb = smem_to_u32(dyn_smem);

    const int qt = (T_ / 128 - 1) - blockIdx.x;
    const int h = blockIdx.y, b = blockIdx.z;
    const int q0 = qt * 128;
    const int tid = threadIdx.x, w = tid >> 5, lane = tid & 31;
    const int g = lane >> 2, tig = lane & 3;
    const int rowBase = b * T_;
    const int hc = h * D_;

    // async-load Q tile (hi/lo)
    #pragma unroll
    for (int it = 0; it < 4; ++it) {
        const int gr = tid + it * 256;
        const int r = gr >> 3, c8 = (gr & 7) * 8;
        const size_t src = (size_t)(rowBase + q0 + r) * C_ + hc + c8;
        const uint32_t d = sb + (uint32_t)(r * PQ + c8) * 2u;
        cp_async16(d + QH_OFF, g_qh + src);
        cp_async16(d + QL_OFF, g_ql + src);
    }

    auto issueKV = [&](int kt, int buf) {
        const int k0 = kt * 64;
        const uint32_t base = sb + ST_OFF + (uint32_t)buf * STAGEA;
        #pragma unroll
        for (int it = 0; it < 2; ++it) {
            const int gr = tid + it * 256;
            const int r = gr >> 3, c8 = (gr & 7) * 8;
            const size_t src = (size_t)(rowBase + k0 + r) * C_ + hc + c8;
            const uint32_t d = base + (uint32_t)(r * PQ + c8) * 2u;
            cp_async16(d,              g_kch + src);
            cp_async16(d + KVTILE,     g_kcl + src);
            cp_async16(d + 2 * KVTILE, g_vch + src);
            cp_async16(d + 3 * KVTILE, g_vcl + src);
        }
        CP_COMMIT();
    };

    issueKV(0, 0);

    const int rA = q0 + w * 16 + g;
    const int rB = rA + 8;
    const int cntA = g_cnt[rowBase + rA];          // valid cols for row rA
    const int cntB = g_cnt[rowBase + rB];
    const int NVq  = g_cnt[rowBase + q0 + 127];    // max over CTA rows
    const int nkt  = (NVq + 63) >> 6;

    float o[8][4];
    #pragma unroll
    for (int nf = 0; nf < 8; ++nf)
        #pragma unroll
        for (int c = 0; c < 4; ++c) o[nf][c] = 0.f;
    float mA = -1e30f, mB = -1e30f, lA = 0.f, lB = 0.f;

    const int aRow = lane & 15, aCol = (lane >> 4) << 3;
    const int bRow = lane & 7,  bCol = ((lane >> 3) & 1) << 3;
    const int vRow = lane & 15;

    for (int kt = 0; kt < nkt; ++kt) {
        const int buf = kt & 1;
        if (kt + 1 < nkt) {
            issueKV(kt + 1, buf ^ 1);
            asm volatile("cp.async.wait_group 1;" ::: "memory");
        } else {
            asm volatile("cp.async.wait_group 0;" ::: "memory");
        }
        __syncthreads();

        const int k0 = kt * 64;
        const uint32_t KH = sb + ST_OFF + (uint32_t)buf * STAGEA;
        const uint32_t KL = KH + KVTILE;
        const uint32_t VH = KH + 2 * KVTILE;
        const uint32_t VL = KH + 3 * KVTILE;

        // ---- S = Q K^T (fp16x3) ----
        float s[8][4];
        #pragma unroll
        for (int nf = 0; nf < 8; ++nf)
            #pragma unroll
            for (int c = 0; c < 4; ++c) s[nf][c] = 0.f;

        #pragma unroll
        for (int kk = 0; kk < 4; ++kk) {
            const int k16 = kk * 16;
            uint32_t aqh[4], aql[4];
            ldmx4(aqh[0], aqh[1], aqh[2], aqh[3],
                  sb + QH_OFF + (uint32_t)((w * 16 + aRow) * PQ + k16 + aCol) * 2u);
            ldmx4(aql[0], aql[1], aql[2], aql[3],
                  sb + QL_OFF + (uint32_t)((w * 16 + aRow) * PQ + k16 + aCol) * 2u);
            #pragma unroll
            for (int nf = 0; nf < 8; ++nf) {
                uint32_t bh0, bh1, bl0, bl1;
                const uint32_t off = (uint32_t)((nf * 8 + bRow) * PQ + k16 + bCol) * 2u;
                ldmx2(bh0, bh1, KH + off);
                ldmx2(bl0, bl1, KL + off);
                mma_f16(s[nf][0], s[nf][1], s[nf][2], s[nf][3],
                        aqh[0], aqh[1], aqh[2], aqh[3], bh0, bh1);
                mma_f16(s[nf][0], s[nf][1], s[nf][2], s[nf][3],
                        aqh[0], aqh[1], aqh[2], aqh[3], bl0, bl1);
                mma_f16(s[nf][0], s[nf][1], s[nf][2], s[nf][3],
                        aql[0], aql[1], aql[2], aql[3], bh0, bh1);
            }
        }

        // ---- unified mask: compact column index < cnt(row) ----
        #pragma unroll
        for (int nf = 0; nf < 8; ++nf) {
            const int c0 = k0 + nf * 8 + tig * 2;
            s[nf][0] = (c0     < cntA) ? s[nf][0] : -1e30f;
            s[nf][1] = (c0 + 1 < cntA) ? s[nf][1] : -1e30f;
            s[nf][2] = (c0     < cntB) ? s[nf][2] : -1e30f;
            s[nf][3] = (c0 + 1 < cntB) ? s[nf][3] : -1e30f;
        }

        // ---- online softmax (exp2 domain) ----
        float mxA = -1e30f, mxB = -1e30f;
        #pragma unroll
        for (int nf = 0; nf < 8; ++nf) {
            mxA = fmaxf(mxA, fmaxf(s[nf][0], s[nf][1]));
            mxB = fmaxf(mxB, fmaxf(s[nf][2], s[nf][3]));
        }
        mxA = fmaxf(mxA, __shfl_xor_sync(0xffffffffu, mxA, 1));
        mxA = fmaxf(mxA, __shfl_xor_sync(0xffffffffu, mxA, 2));
        mxB = fmaxf(mxB, __shfl_xor_sync(0xffffffffu, mxB, 1));
        mxB = fmaxf(mxB, __shfl_xor_sync(0xffffffffu, mxB, 2));
        const float mnA = fmaxf(mA, mxA), mnB = fmaxf(mB, mxB);
        const float cA = ex2f(mA - mnA), cB = ex2f(mB - mnB);
        mA = mnA; mB = mnB;
        float sA = 0.f, sB = 0.f;
        #pragma unroll
        for (int nf = 0; nf < 8; ++nf) {
            s[nf][0] = ex2f(s[nf][0] - mnA);
            s[nf][1] = ex2f(s[nf][1] - mnA);
            s[nf][2] = ex2f(s[nf][2] - mnB);
            s[nf][3] = ex2f(s[nf][3] - mnB);
            sA += s[nf][0] + s[nf][1];
            sB += s[nf][2] + s[nf][3];
        }
        sA += __shfl_xor_sync(0xffffffffu, sA, 1);
        sA += __shfl_xor_sync(0xffffffffu, sA, 2);
        sB += __shfl_xor_sync(0xffffffffu, sB, 1);
        sB += __shfl_xor_sync(0xffffffffu, sB, 2);
        lA = lA * cA + sA;
        lB = lB * cB + sB;
        #pragma unroll
        for (int nf = 0; nf < 8; ++nf) {
            o[nf][0] *= cA; o[nf][1] *= cA;
            o[nf][2] *= cB; o[nf][3] *= cB;
        }

        // ---- O += Ph (Vh + Vl) ----
        #pragma unroll
        for (int j = 0; j < 4; ++j) {
            uint32_t ph[4];
            ph[0] = pack_h2(s[2*j][0],   s[2*j][1]);
            ph[1] = pack_h2(s[2*j][2],   s[2*j][3]);
            ph[2] = pack_h2(s[2*j+1][0], s[2*j+1][1]);
            ph[3] = pack_h2(s[2*j+1][2], s[2*j+1][3]);
            #pragma unroll
            for (int nf = 0; nf < 8; ++nf) {
                uint32_t bh0, bh1, bl0, bl1;
                const uint32_t off = (uint32_t)((j * 16 + vRow) * PQ + nf * 8) * 2u;
                ldmx2t(bh0, bh1, VH + off);
                ldmx2t(bl0, bl1, VL + off);
                mma_f16(o[nf][0], o[nf][1], o[nf][2], o[nf][3],
                        ph[0], ph[1], ph[2], ph[3], bh0, bh1);
                mma_f16(o[nf][0], o[nf][1], o[nf][2], o[nf][3],
                        ph[0], ph[1], ph[2], ph[3], bl0, bl1);
            }
        }
        __syncthreads();
    }

    // ---- normalize, split-fp16 output for proj GEMM ----
    const float invA = 1.f / lA, invB = 1.f / lB;
    #pragma unroll
    for (int nf = 0; nf < 8; ++nf) {
        const int col = hc + nf * 8 + tig * 2;
        const size_t iA = (size_t)(rowBase + rA) * C_ + col;
        const size_t iB = iA + (size_t)8 * C_;
        uint32_t hh, ll;
        pack_hl(o[nf][0] * invA, o[nf][1] * invA, hh, ll);
        *(uint32_t*)&g_ah[iA] = hh; *(uint32_t*)&g_al[iA] = ll;
        pack_hl(o[nf][2] * invB, o[nf][3] * invB, hh, ll);
        *(uint32_t*)&g_ah[iB] = hh; *(uint32_t*)&g_al[iB] = ll;
    }
}

// ---------------------------------------------------------------------------
// Launch
// ---------------------------------------------------------------------------
extern "C" void kernel_launch(void* const* d_in, const int* in_sizes, int n_in,
                              void* d_out, int out_size)
{
    const float* x  = (const float*)d_in[0];
    const int*   tm = (const int*)  d_in[1];
    const float* wq = (const float*)d_in[2];
    const float* bq = (const float*)d_in[3];
    const float* wk = (const float*)d_in[4];
    const float* bk = (const float*)d_in[5];
    const float* wv = (const float*)d_in[6];
    const float* bv = (const float*)d_in[7];
    const float* wp = (const float*)d_in[8];
    const float* bp = (const float*)d_in[9];
    float* out = (float*)d_out;

    cudaFuncSetAttribute(qkv_kernel,  cudaFuncAttributeMaxDynamicSharedMemorySize, GSMEM);
    cudaFuncSetAttribute(proj_kernel, cudaFuncAttributeMaxDynamicSharedMemorySize, GSMEM);
    cudaFuncSetAttribute(attn_kernel, cudaFuncAttributeMaxDynamicSharedMemorySize, ATT_SMEM);

    const int nX = M_ * C_;
    const int nW = C_ * C_;
    split_kernel<<<nX / 1024, 256>>>(x,  0, nX);
    split_kernel<<<nW / 1024, 256>>>(wq, 1, nW);
    split_kernel<<<nW / 1024, 256>>>(wk, 2, nW);
    split_kernel<<<nW / 1024, 256>>>(wv, 3, nW);
    split_kernel<<<nW / 1024, 256>>>(wp, 4, nW);
    mask_scan_kernel<<<B_, 256>>>(tm);

    dim3 gQKV(C_/128, M_/128, 3);
    qkv_kernel<<<gQKV, 256, GSMEM>>>(bq, bk, bv);

    dim3 gGather(T_, B_);
    gather_kv_kernel<<<gGather, 256>>>();

    dim3 gAtt(T_/128, NH_, B_);
    attn_kernel<<<gAtt, 256, ATT_SMEM>>>();

    dim3 gProj(C_/128, M_/128, 1);
    proj_kernel<<<gProj, 256, GSMEM>>>(bp, out);
}

// round 10
// speedup vs baseline: 3.6398x; 1.1923x over previous
#include <cuda_runtime.h>
#include <cuda_fp16.h>
#include <cstdint>

#define B_  4
#define T_  2048
#define C_  1024
#define NH_ 16
#define D_  64
#define M_  (B_*T_)

// ---- GEMM smem (halves, pitch 40): 4 tiles/stage, 2 stages ----
#define PH     40
#define TILEB  10240u
#define STAGEB 40960u
#define GSMEM  81920

// ---- Attention smem: Q(h,l) 128x64 + 2 stages x (Kh,Kl,Vh,Vl) 64x64 ----
#define PQ 72
#define KVTILE 9216u               // 64*PQ*2
#define STAGEA 36864u              // 4 KV tiles
#define QH_OFF 0u
#define QL_OFF 18432u
#define ST_OFF 36864u
#define ATT_SMEM 110592

extern __shared__ char dyn_smem[];

// Scratch (static device globals — no allocation at runtime)
__device__ __half g_qh[M_*C_],  g_ql[M_*C_];
__device__ __half g_ah[M_*C_],  g_al[M_*C_];
__device__ __half g_xh[M_*C_],  g_xl[M_*C_];
__device__ __half g_xch[M_*C_], g_xcl[M_*C_];   // compacted x (valid rows)
__device__ __half g_wqh[C_*C_], g_wql[C_*C_];
__device__ __half g_wkh[C_*C_], g_wkl[C_*C_];
__device__ __half g_wvh[C_*C_], g_wvl[C_*C_];
__device__ __half g_wph[C_*C_], g_wpl[C_*C_];
// mask compaction
__device__ int    g_cnt[B_*T_];            // inclusive count of valid tokens <= t
__device__ int    g_pos[B_*T_];            // compact index j -> original position
// compacted K/V (written directly by K/V GEMM epilogue)
__device__ __half g_kch[M_*C_], g_kcl[M_*C_];
__device__ __half g_vch[M_*C_], g_vcl[M_*C_];

// ---------------------------------------------------------------------------
// helpers
// ---------------------------------------------------------------------------
__device__ __forceinline__ uint32_t smem_to_u32(const void* p) {
    uint32_t a;
    asm("{ .reg .u64 t; cvta.to.shared.u64 t, %1; cvt.u32.u64 %0, t; }"
        : "=r"(a) : "l"(p));
    return a;
}

__device__ __forceinline__ void cp_async16(uint32_t s, const void* g) {
    asm volatile("cp.async.cg.shared.global [%0], [%1], 16;" :: "r"(s), "l"(g));
}
#define CP_COMMIT() asm volatile("cp.async.commit_group;" ::: "memory")

__device__ __forceinline__ void ldmx4(uint32_t& r0, uint32_t& r1,
                                      uint32_t& r2, uint32_t& r3, uint32_t a) {
    asm volatile("ldmatrix.sync.aligned.m8n8.x4.shared.b16 {%0,%1,%2,%3}, [%4];"
                 : "=r"(r0), "=r"(r1), "=r"(r2), "=r"(r3) : "r"(a));
}
__device__ __forceinline__ void ldmx2(uint32_t& r0, uint32_t& r1, uint32_t a) {
    asm volatile("ldmatrix.sync.aligned.m8n8.x2.shared.b16 {%0,%1}, [%2];"
                 : "=r"(r0), "=r"(r1) : "r"(a));
}
__device__ __forceinline__ void ldmx2t(uint32_t& r0, uint32_t& r1, uint32_t a) {
    asm volatile("ldmatrix.sync.aligned.m8n8.x2.trans.shared.b16 {%0,%1}, [%2];"
                 : "=r"(r0), "=r"(r1) : "r"(a));
}

__device__ __forceinline__ void mma_f16(float& c0, float& c1, float& c2, float& c3,
                                        uint32_t a0, uint32_t a1, uint32_t a2, uint32_t a3,
                                        uint32_t b0, uint32_t b1) {
    asm volatile(
        "mma.sync.aligned.m16n8k16.row.col.f32.f16.f16.f32 "
        "{%0,%1,%2,%3}, {%4,%5,%6,%7}, {%8,%9}, {%0,%1,%2,%3};\n"
        : "+f"(c0), "+f"(c1), "+f"(c2), "+f"(c3)
        : "r"(a0), "r"(a1), "r"(a2), "r"(a3), "r"(b0), "r"(b1));
}

__device__ __forceinline__ float ex2f(float x) {
    float r;
    asm("ex2.approx.f32 %0, %1;" : "=f"(r) : "f"(x));
    return r;
}

__device__ __forceinline__ uint32_t pack_h2(float x, float y) {
    uint32_t r;
    asm("cvt.rn.f16x2.f32 %0, %1, %2;" : "=r"(r) : "f"(y), "f"(x));
    return r;
}

__device__ __forceinline__ void pack_hl(float x, float y, uint32_t& hh, uint32_t& ll) {
    __half hx = __float2half_rn(x), hy = __float2half_rn(y);
    __half lx = __float2half_rn(x - __half2float(hx));
    __half ly = __float2half_rn(y - __half2float(hy));
    __half2 H = __halves2half2(hx, hy), L = __halves2half2(lx, ly);
    hh = *(uint32_t*)&H; ll = *(uint32_t*)&L;
}

// ---------------------------------------------------------------------------
// split prepass: fp32 -> (hi fp16, lo fp16).  sel: 0=x 1=wq 2=wk 3=wv 4=wp
// ---------------------------------------------------------------------------
__global__ void __launch_bounds__(256) split_kernel(const float* __restrict__ src,
                                                    int sel, int n)
{
    __half* dh; __half* dl;
    switch (sel) {
        case 0: dh = g_xh;  dl = g_xl;  break;
        case 1: dh = g_wqh; dl = g_wql; break;
        case 2: dh = g_wkh; dl = g_wkl; break;
        case 3: dh = g_wvh; dl = g_wvl; break;
        default: dh = g_wph; dl = g_wpl; break;
    }
    const int i4 = (blockIdx.x * 256 + threadIdx.x) * 4;
    if (i4 >= n) return;
    float4 v = *(const float4*)(src + i4);
    uint32_t h0, l0, h1, l1;
    pack_hl(v.x, v.y, h0, l0);
    pack_hl(v.z, v.w, h1, l1);
    *(uint32_t*)(dh + i4)     = h0;
    *(uint32_t*)(dh + i4 + 2) = h1;
    *(uint32_t*)(dl + i4)     = l0;
    *(uint32_t*)(dl + i4 + 2) = l1;
}

// ---------------------------------------------------------------------------
// token-mask scan: per batch, inclusive counts + compact position list
// ---------------------------------------------------------------------------
__global__ void __launch_bounds__(256) mask_scan_kernel(const int* __restrict__ tmask)
{
    __shared__ int wsum[8];
    const int b = blockIdx.x;
    const int tid = threadIdx.x;
    const int lane = tid & 31, wid = tid >> 5;
    const int t0 = tid * 8;

    int v[8]; int s = 0;
    #pragma unroll
    for (int i = 0; i < 8; ++i) { v[i] = (tmask[b*T_ + t0 + i] != 0) ? 1 : 0; s += v[i]; }

    int sc = s;
    #pragma unroll
    for (int off = 1; off < 32; off <<= 1) {
        int n = __shfl_up_sync(0xffffffffu, sc, off);
        if (lane >= off) sc += n;
    }
    if (lane == 31) wsum[wid] = sc;
    __syncthreads();
    if (tid == 0) {
        int acc = 0;
        #pragma unroll
        for (int i = 0; i < 8; ++i) { acc += wsum[i]; wsum[i] = acc; }
    }
    __syncthreads();
    const int wbase = (wid > 0) ? wsum[wid - 1] : 0;
    int run = wbase + sc - s;
    #pragma unroll
    for (int i = 0; i < 8; ++i) {
        run += v[i];
        g_cnt[b*T_ + t0 + i] = run;
        if (v[i]) g_pos[b*T_ + run - 1] = t0 + i;
    }
}

// ---------------------------------------------------------------------------
// gather valid x rows into compacted buffers (input to K/V GEMMs)
// ---------------------------------------------------------------------------
__global__ void __launch_bounds__(256) gather_x_kernel()
{
    const int j = blockIdx.x, b = blockIdx.y;
    if (j >= g_cnt[b*T_ + T_ - 1]) return;
    const int src = g_pos[b*T_ + j];
    const size_t so = (size_t)(b*T_ + src) * C_;
    const size_t dofs = (size_t)(b*T_ + j) * C_;
    for (int u = threadIdx.x; u < 256; u += 256) {
        const int arr = u >> 7, i = u & 127;
        const __half* sa = (arr == 0) ? g_xh : g_xl;
        __half* da       = (arr == 0) ? g_xch : g_xcl;
        ((float4*)(da + dofs))[i] = ((const float4*)(sa + so))[i];
    }
}

// ---------------------------------------------------------------------------
// fp16x3 GEMM: 128x128 tile of A[.,1024] @ W[.,1024]^T + bias
// ---------------------------------------------------------------------------
__device__ __forceinline__ void tc_gemm_tile(
    const __half* __restrict__ Ah, const __half* __restrict__ Al,
    const __half* __restrict__ Wh, const __half* __restrict__ Wl,
    const float* __restrict__ bias,
    float* __restrict__ outF, __half* __restrict__ outH,
    __half* __restrict__ outL, float scale)
{
    const uint32_t sb = smem_to_u32(dyn_smem);

    const int tid  = threadIdx.x;
    const int wid  = tid >> 5;
    const int lane = tid & 31;
    const int g    = lane >> 2;
    const int tig  = lane & 3;

    const int row0 = blockIdx.y * 128;
    const int col0 = blockIdx.x * 128;
    const int warpM = (wid & 1) * 64;
    const int warpN = (wid >> 1) * 32;

    auto issue_chunk = [&](int st, uint32_t stage) {
        const int k0 = st * 32;
        #pragma unroll
        for (int p = 0; p < 2; ++p) {
            const int gid = tid + p * 256;
            const int r = gid >> 2, c = gid & 3;
            const uint32_t d = stage + (uint32_t)(r * PH + c * 8) * 2u;
            const size_t so = (size_t)(row0 + r) * C_ + k0 + c * 8;
            const size_t wo = (size_t)(col0 + r) * C_ + k0 + c * 8;
            cp_async16(d,             Ah + so);
            cp_async16(d + TILEB,     Al + so);
            cp_async16(d + 2 * TILEB, Wh + wo);
            cp_async16(d + 3 * TILEB, Wl + wo);
        }
        CP_COMMIT();
    };

    float acc[4][4][4];
    #pragma unroll
    for (int mf = 0; mf < 4; ++mf)
        #pragma unroll
        for (int nf = 0; nf < 4; ++nf)
            #pragma unroll
            for (int r = 0; r < 4; ++r) acc[mf][nf][r] = 0.f;

    issue_chunk(0, sb);
    issue_chunk(1, sb + STAGEB);

    const int aRow = (lane & 15);
    const int aCol = (lane >> 4) << 3;
    const int bRow = (lane & 7);
    const int bCol = ((lane >> 3) & 1) << 3;

    for (int st = 0; st < 32; ++st) {
        if (st < 31) { asm volatile("cp.async.wait_group 1;" ::: "memory"); }
        else         { asm volatile("cp.async.wait_group 0;" ::: "memory"); }
        __syncthreads();

        const uint32_t stage = sb + (st & 1) * STAGEB;

        #pragma unroll
        for (int kk = 0; kk < 2; ++kk) {
            const int k16 = kk * 16;

            uint32_t afh[4][4], bfh[4][2];
            #pragma unroll
            for (int mf = 0; mf < 4; ++mf) {
                const uint32_t a = stage +
                    (uint32_t)((warpM + mf * 16 + aRow) * PH + k16 + aCol) * 2u;
                ldmx4(afh[mf][0], afh[mf][1], afh[mf][2], afh[mf][3], a);
            }
            #pragma unroll
            for (int nf = 0; nf < 4; ++nf) {
                const uint32_t a = stage + 2 * TILEB +
                    (uint32_t)((warpN + nf * 8 + bRow) * PH + k16 + bCol) * 2u;
                ldmx2(bfh[nf][0], bfh[nf][1], a);
            }
            #pragma unroll
            for (int mf = 0; mf < 4; ++mf)
                #pragma unroll
                for (int nf = 0; nf < 4; ++nf)
                    mma_f16(acc[mf][nf][0], acc[mf][nf][1], acc[mf][nf][2], acc[mf][nf][3],
                            afh[mf][0], afh[mf][1], afh[mf][2], afh[mf][3],
                            bfh[nf][0], bfh[nf][1]);
            uint32_t bfl[4][2];
            #pragma unroll
            for (int nf = 0; nf < 4; ++nf) {
                const uint32_t a = stage + 3 * TILEB +
                    (uint32_t)((warpN + nf * 8 + bRow) * PH + k16 + bCol) * 2u;
                ldmx2(bfl[nf][0], bfl[nf][1], a);
            }
            #pragma unroll
            for (int mf = 0; mf < 4; ++mf)
                #pragma unroll
                for (int nf = 0; nf < 4; ++nf)
                    mma_f16(acc[mf][nf][0], acc[mf][nf][1], acc[mf][nf][2], acc[mf][nf][3],
                            afh[mf][0], afh[mf][1], afh[mf][2], afh[mf][3],
                            bfl[nf][0], bfl[nf][1]);
            uint32_t afl[4][4];
            #pragma unroll
            for (int mf = 0; mf < 4; ++mf) {
                const uint32_t a = stage + TILEB +
                    (uint32_t)((warpM + mf * 16 + aRow) * PH + k16 + aCol) * 2u;
                ldmx4(afl[mf][0], afl[mf][1], afl[mf][2], afl[mf][3], a);
            }
            #pragma unroll
            for (int mf = 0; mf < 4; ++mf)
                #pragma unroll
                for (int nf = 0; nf < 4; ++nf)
                    mma_f16(acc[mf][nf][0], acc[mf][nf][1], acc[mf][nf][2], acc[mf][nf][3],
                            afl[mf][0], afl[mf][1], afl[mf][2], afl[mf][3],
                            bfh[nf][0], bfh[nf][1]);
        }
        __syncthreads();
        if (st + 2 < 32) issue_chunk(st + 2, sb + (st & 1) * STAGEB);
    }

    #pragma unroll
    for (int nf = 0; nf < 4; ++nf) {
        const int colg = col0 + warpN + nf * 8 + tig * 2;
        const float2 bb = *(const float2*)&bias[colg];
        #pragma unroll
        for (int mf = 0; mf < 4; ++mf) {
            const int rowg = row0 + warpM + mf * 16 + g;
            const float v00 = acc[mf][nf][0] + bb.x, v01 = acc[mf][nf][1] + bb.y;
            const float v10 = acc[mf][nf][2] + bb.x, v11 = acc[mf][nf][3] + bb.y;
            if (outF) {
                *(float2*)&outF[(size_t)rowg * C_ + colg]       = make_float2(v00, v01);
                *(float2*)&outF[(size_t)(rowg + 8) * C_ + colg] = make_float2(v10, v11);
            } else {
                uint32_t hh, ll;
                pack_hl(v00 * scale, v01 * scale, hh, ll);
                *(uint32_t*)&outH[(size_t)rowg * C_ + colg] = hh;
                *(uint32_t*)&outL[(size_t)rowg * C_ + colg] = ll;
                pack_hl(v10 * scale, v11 * scale, hh, ll);
                *(uint32_t*)&outH[(size_t)(rowg + 8) * C_ + colg] = hh;
                *(uint32_t*)&outL[(size_t)(rowg + 8) * C_ + colg] = ll;
            }
        }
    }
}

// Q scaled by (1/sqrt(D)) * log2(e) so softmax runs in exp2 domain
#define QSCALE (0.125f * 1.4426950408889634f)

// sel 0: Q (full rows, from x); sel 1: K, sel 2: V (compacted rows, from xc)
__global__ void __launch_bounds__(256) qkv_kernel(
    const float* __restrict__ bq, const float* __restrict__ bk,
    const float* __restrict__ bv)
{
    const int sel = blockIdx.z;
    if (sel != 0) {
        // skip CTAs entirely beyond this batch's valid-row count
        const int row0 = blockIdx.y * 128;
        const int b = row0 / T_;
        const int local = row0 - b * T_;
        if (local >= g_cnt[b*T_ + T_ - 1]) return;
    }
    const __half* Ah   = (sel == 0) ? g_xh  : g_xch;
    const __half* Al   = (sel == 0) ? g_xl  : g_xcl;
    const __half* Wh   = (sel == 0) ? g_wqh : (sel == 1) ? g_wkh : g_wvh;
    const __half* Wl   = (sel == 0) ? g_wql : (sel == 1) ? g_wkl : g_wvl;
    const float*  bias = (sel == 0) ? bq    : (sel == 1) ? bk    : bv;
    __half* outH       = (sel == 0) ? g_qh  : (sel == 1) ? g_kch : g_vch;
    __half* outL       = (sel == 0) ? g_ql  : (sel == 1) ? g_kcl : g_vcl;
    const float scale  = (sel == 0) ? QSCALE : 1.0f;
    tc_gemm_tile(Ah, Al, Wh, Wl, bias, nullptr, outH, outL, scale);
}

__global__ void __launch_bounds__(256) proj_kernel(
    const float* __restrict__ bp, float* __restrict__ out)
{
    tc_gemm_tile(g_ah, g_al, g_wph, g_wpl, bp, out, nullptr, nullptr, 1.0f);
}

// ---------------------------------------------------------------------------
// fp16x3 flash attention over COMPACTED K/V (unchanged from R8)
// ---------------------------------------------------------------------------
__global__ void __launch_bounds__(256, 2) attn_kernel()
{
    const uint32_t sb = smem_to_u32(dyn_smem);

    const int qt = (T_ / 128 - 1) - blockIdx.x;
    const int h = blockIdx.y, b = blockIdx.z;
    const int q0 = qt * 128;
    const int tid = threadIdx.x, w = tid >> 5, lane = tid & 31;
    const int g = lane >> 2, tig = lane & 3;
    const int rowBase = b * T_;
    const int hc = h * D_;

    #pragma unroll
    for (int it = 0; it < 4; ++it) {
        const int gr = tid + it * 256;
        const int r = gr >> 3, c8 = (gr & 7) * 8;
        const size_t src = (size_t)(rowBase + q0 + r) * C_ + hc + c8;
        const uint32_t d = sb + (uint32_t)(r * PQ + c8) * 2u;
        cp_async16(d + QH_OFF, g_qh + src);
        cp_async16(d + QL_OFF, g_ql + src);
    }

    auto issueKV = [&](int kt, int buf) {
        const int k0 = kt * 64;
        const uint32_t base = sb + ST_OFF + (uint32_t)buf * STAGEA;
        #pragma unroll
        for (int it = 0; it < 2; ++it) {
            const int gr = tid + it * 256;
            const int r = gr >> 3, c8 = (gr & 7) * 8;
            const size_t src = (size_t)(rowBase + k0 + r) * C_ + hc + c8;
            const uint32_t d = base + (uint32_t)(r * PQ + c8) * 2u;
            cp_async16(d,              g_kch + src);
            cp_async16(d + KVTILE,     g_kcl + src);
            cp_async16(d + 2 * KVTILE, g_vch + src);
            cp_async16(d + 3 * KVTILE, g_vcl + src);
        }
        CP_COMMIT();
    };

    issueKV(0, 0);

    const int rA = q0 + w * 16 + g;
    const int rB = rA + 8;
    const int cntA = g_cnt[rowBase + rA];
    const int cntB = g_cnt[rowBase + rB];
    const int NVq  = g_cnt[rowBase + q0 + 127];
    const int nkt  = (NVq + 63) >> 6;

    float o[8][4];
    #pragma unroll
    for (int nf = 0; nf < 8; ++nf)
        #pragma unroll
        for (int c = 0; c < 4; ++c) o[nf][c] = 0.f;
    float mA = -1e30f, mB = -1e30f, lA = 0.f, lB = 0.f;

    const int aRow = lane & 15, aCol = (lane >> 4) << 3;
    const int bRow = lane & 7,  bCol = ((lane >> 3) & 1) << 3;
    const int vRow = lane & 15;

    for (int kt = 0; kt < nkt; ++kt) {
        const int buf = kt & 1;
        if (kt + 1 < nkt) {
            issueKV(kt + 1, buf ^ 1);
            asm volatile("cp.async.wait_group 1;" ::: "memory");
        } else {
            asm volatile("cp.async.wait_group 0;" ::: "memory");
        }
        __syncthreads();

        const int k0 = kt * 64;
        const uint32_t KH = sb + ST_OFF + (uint32_t)buf * STAGEA;
        const uint32_t KL = KH + KVTILE;
        const uint32_t VH = KH + 2 * KVTILE;
        const uint32_t VL = KH + 3 * KVTILE;

        float s[8][4];
        #pragma unroll
        for (int nf = 0; nf < 8; ++nf)
            #pragma unroll
            for (int c = 0; c < 4; ++c) s[nf][c] = 0.f;

        #pragma unroll
        for (int kk = 0; kk < 4; ++kk) {
            const int k16 = kk * 16;
            uint32_t aqh[4], aql[4];
            ldmx4(aqh[0], aqh[1], aqh[2], aqh[3],
                  sb + QH_OFF + (uint32_t)((w * 16 + aRow) * PQ + k16 + aCol) * 2u);
            ldmx4(aql[0], aql[1], aql[2], aql[3],
                  sb + QL_OFF + (uint32_t)((w * 16 + aRow) * PQ + k16 + aCol) * 2u);
            #pragma unroll
            for (int nf = 0; nf < 8; ++nf) {
                uint32_t bh0, bh1, bl0, bl1;
                const uint32_t off = (uint32_t)((nf * 8 + bRow) * PQ + k16 + bCol) * 2u;
                ldmx2(bh0, bh1, KH + off);
                ldmx2(bl0, bl1, KL + off);
                mma_f16(s[nf][0], s[nf][1], s[nf][2], s[nf][3],
                        aqh[0], aqh[1], aqh[2], aqh[3], bh0, bh1);
                mma_f16(s[nf][0], s[nf][1], s[nf][2], s[nf][3],
                        aqh[0], aqh[1], aqh[2], aqh[3], bl0, bl1);
                mma_f16(s[nf][0], s[nf][1], s[nf][2], s[nf][3],
                        aql[0], aql[1], aql[2], aql[3], bh0, bh1);
            }
        }

        #pragma unroll
        for (int nf = 0; nf < 8; ++nf) {
            const int c0 = k0 + nf * 8 + tig * 2;
            s[nf][0] = (c0     < cntA) ? s[nf][0] : -1e30f;
            s[nf][1] = (c0 + 1 < cntA) ? s[nf][1] : -1e30f;
            s[nf][2] = (c0     < cntB) ? s[nf][2] : -1e30f;
            s[nf][3] = (c0 + 1 < cntB) ? s[nf][3] : -1e30f;
        }

        float mxA = -1e30f, mxB = -1e30f;
        #pragma unroll
        for (int nf = 0; nf < 8; ++nf) {
            mxA = fmaxf(mxA, fmaxf(s[nf][0], s[nf][1]));
            mxB = fmaxf(mxB, fmaxf(s[nf][2], s[nf][3]));
        }
        mxA = fmaxf(mxA, __shfl_xor_sync(0xffffffffu, mxA, 1));
        mxA = fmaxf(mxA, __shfl_xor_sync(0xffffffffu, mxA, 2));
        mxB = fmaxf(mxB, __shfl_xor_sync(0xffffffffu, mxB, 1));
        mxB = fmaxf(mxB, __shfl_xor_sync(0xffffffffu, mxB, 2));
        const float mnA = fmaxf(mA, mxA), mnB = fmaxf(mB, mxB);
        const float cA = ex2f(mA - mnA), cB = ex2f(mB - mnB);
        mA = mnA; mB = mnB;
        float sA = 0.f, sB = 0.f;
        #pragma unroll
        for (int nf = 0; nf < 8; ++nf) {
            s[nf][0] = ex2f(s[nf][0] - mnA);
            s[nf][1] = ex2f(s[nf][1] - mnA);
            s[nf][2] = ex2f(s[nf][2] - mnB);
            s[nf][3] = ex2f(s[nf][3] - mnB);
            sA += s[nf][0] + s[nf][1];
            sB += s[nf][2] + s[nf][3];
        }
        sA += __shfl_xor_sync(0xffffffffu, sA, 1);
        sA += __shfl_xor_sync(0xffffffffu, sA, 2);
        sB += __shfl_xor_sync(0xffffffffu, sB, 1);
        sB += __shfl_xor_sync(0xffffffffu, sB, 2);
        lA = lA * cA + sA;
        lB = lB * cB + sB;
        #pragma unroll
        for (int nf = 0; nf < 8; ++nf) {
            o[nf][0] *= cA; o[nf][1] *= cA;
            o[nf][2] *= cB; o[nf][3] *= cB;
        }

        #pragma unroll
        for (int j = 0; j < 4; ++j) {
            uint32_t ph[4];
            ph[0] = pack_h2(s[2*j][0],   s[2*j][1]);
            ph[1] = pack_h2(s[2*j][2],   s[2*j][3]);
            ph[2] = pack_h2(s[2*j+1][0], s[2*j+1][1]);
            ph[3] = pack_h2(s[2*j+1][2], s[2*j+1][3]);
            #pragma unroll
            for (int nf = 0; nf < 8; ++nf) {
                uint32_t bh0, bh1, bl0, bl1;
                const uint32_t off = (uint32_t)((j * 16 + vRow) * PQ + nf * 8) * 2u;
                ldmx2t(bh0, bh1, VH + off);
                ldmx2t(bl0, bl1, VL + off);
                mma_f16(o[nf][0], o[nf][1], o[nf][2], o[nf][3],
                        ph[0], ph[1], ph[2], ph[3], bh0, bh1);
                mma_f16(o[nf][0], o[nf][1], o[nf][2], o[nf][3],
                        ph[0], ph[1], ph[2], ph[3], bl0, bl1);
            }
        }
        __syncthreads();
    }

    const float invA = 1.f / lA, invB = 1.f / lB;
    #pragma unroll
    for (int nf = 0; nf < 8; ++nf) {
        const int col = hc + nf * 8 + tig * 2;
        const size_t iA = (size_t)(rowBase + rA) * C_ + col;
        const size_t iB = iA + (size_t)8 * C_;
        uint32_t hh, ll;
        pack_hl(o[nf][0] * invA, o[nf][1] * invA, hh, ll);
        *(uint32_t*)&g_ah[iA] = hh; *(uint32_t*)&g_al[iA] = ll;
        pack_hl(o[nf][2] * invB, o[nf][3] * invB, hh, ll);
        *(uint32_t*)&g_ah[iB] = hh; *(uint32_t*)&g_al[iB] = ll;
    }
}

// ---------------------------------------------------------------------------
// Launch
// ---------------------------------------------------------------------------
extern "C" void kernel_launch(void* const* d_in, const int* in_sizes, int n_in,
                              void* d_out, int out_size)
{
    const float* x  = (const float*)d_in[0];
    const int*   tm = (const int*)  d_in[1];
    const float* wq = (const float*)d_in[2];
    const float* bq = (const float*)d_in[3];
    const float* wk = (const float*)d_in[4];
    const float* bk = (const float*)d_in[5];
    const float* wv = (const float*)d_in[6];
    const float* bv = (const float*)d_in[7];
    const float* wp = (const float*)d_in[8];
    const float* bp = (const float*)d_in[9];
    float* out = (float*)d_out;

    cudaFuncSetAttribute(qkv_kernel,  cudaFuncAttributeMaxDynamicSharedMemorySize, GSMEM);
    cudaFuncSetAttribute(proj_kernel, cudaFuncAttributeMaxDynamicSharedMemorySize, GSMEM);
    cudaFuncSetAttribute(attn_kernel, cudaFuncAttributeMaxDynamicSharedMemorySize, ATT_SMEM);

    const int nX = M_ * C_;
    const int nW = C_ * C_;
    split_kernel<<<nX / 1024, 256>>>(x,  0, nX);
    split_kernel<<<nW / 1024, 256>>>(wq, 1, nW);
    split_kernel<<<nW / 1024, 256>>>(wk, 2, nW);
    split_kernel<<<nW / 1024, 256>>>(wv, 3, nW);
    split_kernel<<<nW / 1024, 256>>>(wp, 4, nW);
    mask_scan_kernel<<<B_, 256>>>(tm);

    dim3 gGx(T_, B_);
    gather_x_kernel<<<gGx, 256>>>();

    dim3 gQKV(C_/128, M_/128, 3);
    qkv_kernel<<<gQKV, 256, GSMEM>>>(bq, bk, bv);

    dim3 gAtt(T_/128, NH_, B_);
    attn_kernel<<<gAtt, 256, ATT_SMEM>>>();

    dim3 gProj(C_/128, M_/128, 1);
    proj_kernel<<<gProj, 256, GSMEM>>>(bp, out);
}

// round 11
// speedup vs baseline: 3.6999x; 1.0165x over previous
#include <cuda_runtime.h>
#include <cuda_fp16.h>
#include <cstdint>

#define B_  4
#define T_  2048
#define C_  1024
#define NH_ 16
#define D_  64
#define M_  (B_*T_)
#define NX  (M_*C_)
#define NW  (C_*C_)

// ---- GEMM smem (halves, pitch 40): 4 tiles/stage, 2 stages ----
#define PH     40
#define TILEB  10240u
#define STAGEB 40960u
#define GSMEM  81920

// ---- Attention smem: Q(h,l) 128x64 + 2 stages x (Kh,Kl,Vh,Vl) 64x64 ----
#define PQ 72
#define KVTILE 9216u               // 64*PQ*2
#define STAGEA 36864u              // 4 KV tiles
#define QH_OFF 0u
#define QL_OFF 18432u
#define ST_OFF 36864u
#define ATT_SMEM 110592

extern __shared__ char dyn_smem[];

// Scratch (static device globals — no allocation at runtime)
__device__ __half g_qh[M_*C_],  g_ql[M_*C_];
__device__ __half g_ah[M_*C_],  g_al[M_*C_];
__device__ __half g_xh[M_*C_],  g_xl[M_*C_];
__device__ __half g_xch[M_*C_], g_xcl[M_*C_];   // compacted x (valid rows)
__device__ __half g_wqh[C_*C_], g_wql[C_*C_];
__device__ __half g_wkh[C_*C_], g_wkl[C_*C_];
__device__ __half g_wvh[C_*C_], g_wvl[C_*C_];
__device__ __half g_wph[C_*C_], g_wpl[C_*C_];
// mask compaction
__device__ int    g_cnt[B_*T_];            // inclusive count of valid tokens <= t
__device__ int    g_pos[B_*T_];            // compact index j -> original position
// compacted K/V (written directly by K/V GEMM epilogue)
__device__ __half g_kch[M_*C_], g_kcl[M_*C_];
__device__ __half g_vch[M_*C_], g_vcl[M_*C_];

// ---------------------------------------------------------------------------
// helpers
// ---------------------------------------------------------------------------
__device__ __forceinline__ uint32_t smem_to_u32(const void* p) {
    uint32_t a;
    asm("{ .reg .u64 t; cvta.to.shared.u64 t, %1; cvt.u32.u64 %0, t; }"
        : "=r"(a) : "l"(p));
    return a;
}

__device__ __forceinline__ void cp_async16(uint32_t s, const void* g) {
    asm volatile("cp.async.cg.shared.global [%0], [%1], 16;" :: "r"(s), "l"(g));
}
#define CP_COMMIT() asm volatile("cp.async.commit_group;" ::: "memory")

__device__ __forceinline__ void ldmx4(uint32_t& r0, uint32_t& r1,
                                      uint32_t& r2, uint32_t& r3, uint32_t a) {
    asm volatile("ldmatrix.sync.aligned.m8n8.x4.shared.b16 {%0,%1,%2,%3}, [%4];"
                 : "=r"(r0), "=r"(r1), "=r"(r2), "=r"(r3) : "r"(a));
}
__device__ __forceinline__ void ldmx2(uint32_t& r0, uint32_t& r1, uint32_t a) {
    asm volatile("ldmatrix.sync.aligned.m8n8.x2.shared.b16 {%0,%1}, [%2];"
                 : "=r"(r0), "=r"(r1) : "r"(a));
}
__device__ __forceinline__ void ldmx4t(uint32_t& r0, uint32_t& r1,
                                       uint32_t& r2, uint32_t& r3, uint32_t a) {
    asm volatile("ldmatrix.sync.aligned.m8n8.x4.trans.shared.b16 {%0,%1,%2,%3}, [%4];"
                 : "=r"(r0), "=r"(r1), "=r"(r2), "=r"(r3) : "r"(a));
}

__device__ __forceinline__ void mma_f16(float& c0, float& c1, float& c2, float& c3,
                                        uint32_t a0, uint32_t a1, uint32_t a2, uint32_t a3,
                                        uint32_t b0, uint32_t b1) {
    asm volatile(
        "mma.sync.aligned.m16n8k16.row.col.f32.f16.f16.f32 "
        "{%0,%1,%2,%3}, {%4,%5,%6,%7}, {%8,%9}, {%0,%1,%2,%3};\n"
        : "+f"(c0), "+f"(c1), "+f"(c2), "+f"(c3)
        : "r"(a0), "r"(a1), "r"(a2), "r"(a3), "r"(b0), "r"(b1));
}

__device__ __forceinline__ float ex2f(float x) {
    float r;
    asm("ex2.approx.f32 %0, %1;" : "=f"(r) : "f"(x));
    return r;
}

__device__ __forceinline__ uint32_t pack_h2(float x, float y) {
    uint32_t r;
    asm("cvt.rn.f16x2.f32 %0, %1, %2;" : "=r"(r) : "f"(y), "f"(x));
    return r;
}

__device__ __forceinline__ void pack_hl(float x, float y, uint32_t& hh, uint32_t& ll) {
    __half hx = __float2half_rn(x), hy = __float2half_rn(y);
    __half lx = __float2half_rn(x - __half2float(hx));
    __half ly = __float2half_rn(y - __half2float(hy));
    __half2 H = __halves2half2(hx, hy), L = __halves2half2(lx, ly);
    hh = *(uint32_t*)&H; ll = *(uint32_t*)&L;
}

// ---------------------------------------------------------------------------
// fused split prepass: fp32 -> (hi fp16, lo fp16) for x + all 4 weights
// ---------------------------------------------------------------------------
__global__ void __launch_bounds__(256) split_all_kernel(
    const float* __restrict__ x,  const float* __restrict__ wq,
    const float* __restrict__ wk, const float* __restrict__ wv,
    const float* __restrict__ wp)
{
    const long long i4 = ((long long)blockIdx.x * 256 + threadIdx.x) * 4;
    const float* src; __half *dh, *dl; long long off;
    if (i4 < (long long)NX) {
        src = x; dh = g_xh; dl = g_xl; off = i4;
    } else {
        const long long r = i4 - (long long)NX;
        const int wsel = (int)(r >> 20);      // NW == 1<<20
        off = r & (long long)(NW - 1);
        switch (wsel) {
            case 0:  src = wq; dh = g_wqh; dl = g_wql; break;
            case 1:  src = wk; dh = g_wkh; dl = g_wkl; break;
            case 2:  src = wv; dh = g_wvh; dl = g_wvl; break;
            default: src = wp; dh = g_wph; dl = g_wpl; break;
        }
    }
    float4 v = *(const float4*)(src + off);
    uint32_t h0, l0, h1, l1;
    pack_hl(v.x, v.y, h0, l0);
    pack_hl(v.z, v.w, h1, l1);
    *(uint32_t*)(dh + off)     = h0;
    *(uint32_t*)(dh + off + 2) = h1;
    *(uint32_t*)(dl + off)     = l0;
    *(uint32_t*)(dl + off + 2) = l1;
}

// ---------------------------------------------------------------------------
// token-mask scan: per batch, inclusive counts + compact position list
// ---------------------------------------------------------------------------
__global__ void __launch_bounds__(256) mask_scan_kernel(const int* __restrict__ tmask)
{
    __shared__ int wsum[8];
    const int b = blockIdx.x;
    const int tid = threadIdx.x;
    const int lane = tid & 31, wid = tid >> 5;
    const int t0 = tid * 8;

    int v[8]; int s = 0;
    #pragma unroll
    for (int i = 0; i < 8; ++i) { v[i] = (tmask[b*T_ + t0 + i] != 0) ? 1 : 0; s += v[i]; }

    int sc = s;
    #pragma unroll
    for (int off = 1; off < 32; off <<= 1) {
        int n = __shfl_up_sync(0xffffffffu, sc, off);
        if (lane >= off) sc += n;
    }
    if (lane == 31) wsum[wid] = sc;
    __syncthreads();
    if (tid == 0) {
        int acc = 0;
        #pragma unroll
        for (int i = 0; i < 8; ++i) { acc += wsum[i]; wsum[i] = acc; }
    }
    __syncthreads();
    const int wbase = (wid > 0) ? wsum[wid - 1] : 0;
    int run = wbase + sc - s;
    #pragma unroll
    for (int i = 0; i < 8; ++i) {
        run += v[i];
        g_cnt[b*T_ + t0 + i] = run;
        if (v[i]) g_pos[b*T_ + run - 1] = t0 + i;
    }
}

// ---------------------------------------------------------------------------
// gather valid x rows into compacted buffers (input to K/V GEMMs)
// ---------------------------------------------------------------------------
__global__ void __launch_bounds__(256) gather_x_kernel()
{
    const int j = blockIdx.x, b = blockIdx.y;
    if (j >= g_cnt[b*T_ + T_ - 1]) return;
    const int src = g_pos[b*T_ + j];
    const size_t so = (size_t)(b*T_ + src) * C_;
    const size_t dofs = (size_t)(b*T_ + j) * C_;
    for (int u = threadIdx.x; u < 256; u += 256) {
        const int arr = u >> 7, i = u & 127;
        const __half* sa = (arr == 0) ? g_xh : g_xl;
        __half* da       = (arr == 0) ? g_xch : g_xcl;
        ((float4*)(da + dofs))[i] = ((const float4*)(sa + so))[i];
    }
}

// ---------------------------------------------------------------------------
// fp16x3 GEMM: 128x128 tile of A[.,1024] @ W[.,1024]^T + bias  (unchanged)
// ---------------------------------------------------------------------------
__device__ __forceinline__ void tc_gemm_tile(
    const __half* __restrict__ Ah, const __half* __restrict__ Al,
    const __half* __restrict__ Wh, const __half* __restrict__ Wl,
    const float* __restrict__ bias,
    float* __restrict__ outF, __half* __restrict__ outH,
    __half* __restrict__ outL, float scale)
{
    const uint32_t sb = smem_to_u32(dyn_smem);

    const int tid  = threadIdx.x;
    const int wid  = tid >> 5;
    const int lane = tid & 31;
    const int g    = lane >> 2;
    const int tig  = lane & 3;

    const int row0 = blockIdx.y * 128;
    const int col0 = blockIdx.x * 128;
    const int warpM = (wid & 1) * 64;
    const int warpN = (wid >> 1) * 32;

    auto issue_chunk = [&](int st, uint32_t stage) {
        const int k0 = st * 32;
        #pragma unroll
        for (int p = 0; p < 2; ++p) {
            const int gid = tid + p * 256;
            const int r = gid >> 2, c = gid & 3;
            const uint32_t d = stage + (uint32_t)(r * PH + c * 8) * 2u;
            const size_t so = (size_t)(row0 + r) * C_ + k0 + c * 8;
            const size_t wo = (size_t)(col0 + r) * C_ + k0 + c * 8;
            cp_async16(d,             Ah + so);
            cp_async16(d + TILEB,     Al + so);
            cp_async16(d + 2 * TILEB, Wh + wo);
            cp_async16(d + 3 * TILEB, Wl + wo);
        }
        CP_COMMIT();
    };

    float acc[4][4][4];
    #pragma unroll
    for (int mf = 0; mf < 4; ++mf)
        #pragma unroll
        for (int nf = 0; nf < 4; ++nf)
            #pragma unroll
            for (int r = 0; r < 4; ++r) acc[mf][nf][r] = 0.f;

    issue_chunk(0, sb);
    issue_chunk(1, sb + STAGEB);

    const int aRow = (lane & 15);
    const int aCol = (lane >> 4) << 3;
    const int bRow = (lane & 7);
    const int bCol = ((lane >> 3) & 1) << 3;

    for (int st = 0; st < 32; ++st) {
        if (st < 31) { asm volatile("cp.async.wait_group 1;" ::: "memory"); }
        else         { asm volatile("cp.async.wait_group 0;" ::: "memory"); }
        __syncthreads();

        const uint32_t stage = sb + (st & 1) * STAGEB;

        #pragma unroll
        for (int kk = 0; kk < 2; ++kk) {
            const int k16 = kk * 16;

            uint32_t afh[4][4], bfh[4][2];
            #pragma unroll
            for (int mf = 0; mf < 4; ++mf) {
                const uint32_t a = stage +
                    (uint32_t)((warpM + mf * 16 + aRow) * PH + k16 + aCol) * 2u;
                ldmx4(afh[mf][0], afh[mf][1], afh[mf][2], afh[mf][3], a);
            }
            #pragma unroll
            for (int nf = 0; nf < 4; ++nf) {
                const uint32_t a = stage + 2 * TILEB +
                    (uint32_t)((warpN + nf * 8 + bRow) * PH + k16 + bCol) * 2u;
                ldmx2(bfh[nf][0], bfh[nf][1], a);
            }
            #pragma unroll
            for (int mf = 0; mf < 4; ++mf)
                #pragma unroll
                for (int nf = 0; nf < 4; ++nf)
                    mma_f16(acc[mf][nf][0], acc[mf][nf][1], acc[mf][nf][2], acc[mf][nf][3],
                            afh[mf][0], afh[mf][1], afh[mf][2], afh[mf][3],
                            bfh[nf][0], bfh[nf][1]);
            uint32_t bfl[4][2];
            #pragma unroll
            for (int nf = 0; nf < 4; ++nf) {
                const uint32_t a = stage + 3 * TILEB +
                    (uint32_t)((warpN + nf * 8 + bRow) * PH + k16 + bCol) * 2u;
                ldmx2(bfl[nf][0], bfl[nf][1], a);
            }
            #pragma unroll
            for (int mf = 0; mf < 4; ++mf)
                #pragma unroll
                for (int nf = 0; nf < 4; ++nf)
                    mma_f16(acc[mf][nf][0], acc[mf][nf][1], acc[mf][nf][2], acc[mf][nf][3],
                            afh[mf][0], afh[mf][1], afh[mf][2], afh[mf][3],
                            bfl[nf][0], bfl[nf][1]);
            uint32_t afl[4][4];
            #pragma unroll
            for (int mf = 0; mf < 4; ++mf) {
                const uint32_t a = stage + TILEB +
                    (uint32_t)((warpM + mf * 16 + aRow) * PH + k16 + aCol) * 2u;
                ldmx4(afl[mf][0], afl[mf][1], afl[mf][2], afl[mf][3], a);
            }
            #pragma unroll
            for (int mf = 0; mf < 4; ++mf)
                #pragma unroll
                for (int nf = 0; nf < 4; ++nf)
                    mma_f16(acc[mf][nf][0], acc[mf][nf][1], acc[mf][nf][2], acc[mf][nf][3],
                            afl[mf][0], afl[mf][1], afl[mf][2], afl[mf][3],
                            bfh[nf][0], bfh[nf][1]);
        }
        __syncthreads();
        if (st + 2 < 32) issue_chunk(st + 2, sb + (st & 1) * STAGEB);
    }

    #pragma unroll
    for (int nf = 0; nf < 4; ++nf) {
        const int colg = col0 + warpN + nf * 8 + tig * 2;
        const float2 bb = *(const float2*)&bias[colg];
        #pragma unroll
        for (int mf = 0; mf < 4; ++mf) {
            const int rowg = row0 + warpM + mf * 16 + g;
            const float v00 = acc[mf][nf][0] + bb.x, v01 = acc[mf][nf][1] + bb.y;
            const float v10 = acc[mf][nf][2] + bb.x, v11 = acc[mf][nf][3] + bb.y;
            if (outF) {
                *(float2*)&outF[(size_t)rowg * C_ + colg]       = make_float2(v00, v01);
                *(float2*)&outF[(size_t)(rowg + 8) * C_ + colg] = make_float2(v10, v11);
            } else {
                uint32_t hh, ll;
                pack_hl(v00 * scale, v01 * scale, hh, ll);
                *(uint32_t*)&outH[(size_t)rowg * C_ + colg] = hh;
                *(uint32_t*)&outL[(size_t)rowg * C_ + colg] = ll;
                pack_hl(v10 * scale, v11 * scale, hh, ll);
                *(uint32_t*)&outH[(size_t)(rowg + 8) * C_ + colg] = hh;
                *(uint32_t*)&outL[(size_t)(rowg + 8) * C_ + colg] = ll;
            }
        }
    }
}

// Q scaled by (1/sqrt(D)) * log2(e) so softmax runs in exp2 domain
#define QSCALE (0.125f * 1.4426950408889634f)

// sel 0: Q (full rows, from x); sel 1: K, sel 2: V (compacted rows, from xc)
__global__ void __launch_bounds__(256) qkv_kernel(
    const float* __restrict__ bq, const float* __restrict__ bk,
    const float* __restrict__ bv)
{
    const int sel = blockIdx.z;
    if (sel != 0) {
        const int row0 = blockIdx.y * 128;
        const int b = row0 / T_;
        const int local = row0 - b * T_;
        if (local >= g_cnt[b*T_ + T_ - 1]) return;
    }
    const __half* Ah   = (sel == 0) ? g_xh  : g_xch;
    const __half* Al   = (sel == 0) ? g_xl  : g_xcl;
    const __half* Wh   = (sel == 0) ? g_wqh : (sel == 1) ? g_wkh : g_wvh;
    const __half* Wl   = (sel == 0) ? g_wql : (sel == 1) ? g_wkl : g_wvl;
    const float*  bias = (sel == 0) ? bq    : (sel == 1) ? bk    : bv;
    __half* outH       = (sel == 0) ? g_qh  : (sel == 1) ? g_kch : g_vch;
    __half* outL       = (sel == 0) ? g_ql  : (sel == 1) ? g_kcl : g_vcl;
    const float scale  = (sel == 0) ? QSCALE : 1.0f;
    tc_gemm_tile(Ah, Al, Wh, Wl, bias, nullptr, outH, outL, scale);
}

__global__ void __launch_bounds__(256) proj_kernel(
    const float* __restrict__ bp, float* __restrict__ out)
{
    tc_gemm_tile(g_ah, g_al, g_wph, g_wpl, bp, out, nullptr, nullptr, 1.0f);
}

// ---------------------------------------------------------------------------
// fp16x3 flash attention over COMPACTED K/V. B-fragments (K and V) loaded
// two-nf-at-a-time via ldmatrix.x4 / x4.trans (halves LDSM count).
// ---------------------------------------------------------------------------
__global__ void __launch_bounds__(256, 2) attn_kernel()
{
    const uint32_t sb = smem_to_u32(dyn_smem);

    const int qt = (T_ / 128 - 1) - blockIdx.x;
    const int h = blockIdx.y, b = blockIdx.z;
    const int q0 = qt * 128;
    const int tid = threadIdx.x, w = tid >> 5, lane = tid & 31;
    const int g = lane >> 2, tig = lane & 3;
    const int rowBase = b * T_;
    const int hc = h * D_;

    #pragma unroll
    for (int it = 0; it < 4; ++it) {
        const int gr = tid + it * 256;
        const int r = gr >> 3, c8 = (gr & 7) * 8;
        const size_t src = (size_t)(rowBase + q0 + r) * C_ + hc + c8;
        const uint32_t d = sb + (uint32_t)(r * PQ + c8) * 2u;
        cp_async16(d + QH_OFF, g_qh + src);
        cp_async16(d + QL_OFF, g_ql + src);
    }

    auto issueKV = [&](int kt, int buf) {
        const int k0 = kt * 64;
        const uint32_t base = sb + ST_OFF + (uint32_t)buf * STAGEA;
        #pragma unroll
        for (int it = 0; it < 2; ++it) {
            const int gr = tid + it * 256;
            const int r = gr >> 3, c8 = (gr & 7) * 8;
            const size_t src = (size_t)(rowBase + k0 + r) * C_ + hc + c8;
            const uint32_t d = base + (uint32_t)(r * PQ + c8) * 2u;
            cp_async16(d,              g_kch + src);
            cp_async16(d + KVTILE,     g_kcl + src);
            cp_async16(d + 2 * KVTILE, g_vch + src);
            cp_async16(d + 3 * KVTILE, g_vcl + src);
        }
        CP_COMMIT();
    };

    issueKV(0, 0);

    const int rA = q0 + w * 16 + g;
    const int rB = rA + 8;
    const int cntA = g_cnt[rowBase + rA];
    const int cntB = g_cnt[rowBase + rB];
    const int NVq  = g_cnt[rowBase + q0 + 127];
    const int nkt  = (NVq + 63) >> 6;

    float o[8][4];
    #pragma unroll
    for (int nf = 0; nf < 8; ++nf)
        #pragma unroll
        for (int c = 0; c < 4; ++c) o[nf][c] = 0.f;
    float mA = -1e30f, mB = -1e30f, lA = 0.f, lB = 0.f;

    const int aRow = lane & 15, aCol = (lane >> 4) << 3;
    // paired-nf B fragment addressing (ldmatrix.x4: groups 0,1 -> nf even,
    // groups 2,3 -> nf odd)
    const int bR4 = ((lane >> 4) << 3) + (lane & 7);   // K (non-trans)
    const int bC4 = ((lane >> 3) & 1) << 3;
    const int vR  = lane & 15;                          // V (trans)
    const int vC4 = (lane >> 4) << 3;

    for (int kt = 0; kt < nkt; ++kt) {
        const int buf = kt & 1;
        if (kt + 1 < nkt) {
            issueKV(kt + 1, buf ^ 1);
            asm volatile("cp.async.wait_group 1;" ::: "memory");
        } else {
            asm volatile("cp.async.wait_group 0;" ::: "memory");
        }
        __syncthreads();

        const int k0 = kt * 64;
        const uint32_t KH = sb + ST_OFF + (uint32_t)buf * STAGEA;
        const uint32_t KL = KH + KVTILE;
        const uint32_t VH = KH + 2 * KVTILE;
        const uint32_t VL = KH + 3 * KVTILE;

        // ---- S = Q K^T (fp16x3), K frags paired via ldmx4 ----
        float s[8][4];
        #pragma unroll
        for (int nf = 0; nf < 8; ++nf)
            #pragma unroll
            for (int c = 0; c < 4; ++c) s[nf][c] = 0.f;

        #pragma unroll
        for (int kk = 0; kk < 4; ++kk) {
            const int k16 = kk * 16;
            uint32_t aqh[4], aql[4];
            ldmx4(aqh[0], aqh[1], aqh[2], aqh[3],
                  sb + QH_OFF + (uint32_t)((w * 16 + aRow) * PQ + k16 + aCol) * 2u);
            ldmx4(aql[0], aql[1], aql[2], aql[3],
                  sb + QL_OFF + (uint32_t)((w * 16 + aRow) * PQ + k16 + aCol) * 2u);
            #pragma unroll
            for (int np = 0; np < 4; ++np) {
                uint32_t bh[4], bl[4];
                const uint32_t off = (uint32_t)((np * 16 + bR4) * PQ + k16 + bC4) * 2u;
                ldmx4(bh[0], bh[1], bh[2], bh[3], KH + off);
                ldmx4(bl[0], bl[1], bl[2], bl[3], KL + off);
                mma_f16(s[2*np][0], s[2*np][1], s[2*np][2], s[2*np][3],
                        aqh[0], aqh[1], aqh[2], aqh[3], bh[0], bh[1]);
                mma_f16(s[2*np][0], s[2*np][1], s[2*np][2], s[2*np][3],
                        aqh[0], aqh[1], aqh[2], aqh[3], bl[0], bl[1]);
                mma_f16(s[2*np][0], s[2*np][1], s[2*np][2], s[2*np][3],
                        aql[0], aql[1], aql[2], aql[3], bh[0], bh[1]);
                mma_f16(s[2*np+1][0], s[2*np+1][1], s[2*np+1][2], s[2*np+1][3],
                        aqh[0], aqh[1], aqh[2], aqh[3], bh[2], bh[3]);
                mma_f16(s[2*np+1][0], s[2*np+1][1], s[2*np+1][2], s[2*np+1][3],
                        aqh[0], aqh[1], aqh[2], aqh[3], bl[2], bl[3]);
                mma_f16(s[2*np+1][0], s[2*np+1][1], s[2*np+1][2], s[2*np+1][3],
                        aql[0], aql[1], aql[2], aql[3], bh[2], bh[3]);
            }
        }

        // ---- unified mask: compact column index < cnt(row) ----
        #pragma unroll
        for (int nf = 0; nf < 8; ++nf) {
            const int c0 = k0 + nf * 8 + tig * 2;
            s[nf][0] = (c0     < cntA) ? s[nf][0] : -1e30f;
            s[nf][1] = (c0 + 1 < cntA) ? s[nf][1] : -1e30f;
            s[nf][2] = (c0     < cntB) ? s[nf][2] : -1e30f;
            s[nf][3] = (c0 + 1 < cntB) ? s[nf][3] : -1e30f;
        }

        // ---- online softmax (exp2 domain) ----
        float mxA = -1e30f, mxB = -1e30f;
        #pragma unroll
        for (int nf = 0; nf < 8; ++nf) {
            mxA = fmaxf(mxA, fmaxf(s[nf][0], s[nf][1]));
            mxB = fmaxf(mxB, fmaxf(s[nf][2], s[nf][3]));
        }
        mxA = fmaxf(mxA, __shfl_xor_sync(0xffffffffu, mxA, 1));
        mxA = fmaxf(mxA, __shfl_xor_sync(0xffffffffu, mxA, 2));
        mxB = fmaxf(mxB, __shfl_xor_sync(0xffffffffu, mxB, 1));
        mxB = fmaxf(mxB, __shfl_xor_sync(0xffffffffu, mxB, 2));
        const float mnA = fmaxf(mA, mxA), mnB = fmaxf(mB, mxB);
        const float cA = ex2f(mA - mnA), cB = ex2f(mB - mnB);
        mA = mnA; mB = mnB;
        float sA = 0.f, sB = 0.f;
        #pragma unroll
        for (int nf = 0; nf < 8; ++nf) {
            s[nf][0] = ex2f(s[nf][0] - mnA);
            s[nf][1] = ex2f(s[nf][1] - mnA);
            s[nf][2] = ex2f(s[nf][2] - mnB);
            s[nf][3] = ex2f(s[nf][3] - mnB);
            sA += s[nf][0] + s[nf][1];
            sB += s[nf][2] + s[nf][3];
        }
        sA += __shfl_xor_sync(0xffffffffu, sA, 1);
        sA += __shfl_xor_sync(0xffffffffu, sA, 2);
        sB += __shfl_xor_sync(0xffffffffu, sB, 1);
        sB += __shfl_xor_sync(0xffffffffu, sB, 2);
        lA = lA * cA + sA;
        lB = lB * cB + sB;
        #pragma unroll
        for (int nf = 0; nf < 8; ++nf) {
            o[nf][0] *= cA; o[nf][1] *= cA;
            o[nf][2] *= cB; o[nf][3] *= cB;
        }

        // ---- O += Ph (Vh + Vl): V frags paired via ldmx4.trans ----
        #pragma unroll
        for (int j = 0; j < 4; ++j) {
            uint32_t ph[4];
            ph[0] = pack_h2(s[2*j][0],   s[2*j][1]);
            ph[1] = pack_h2(s[2*j][2],   s[2*j][3]);
            ph[2] = pack_h2(s[2*j+1][0], s[2*j+1][1]);
            ph[3] = pack_h2(s[2*j+1][2], s[2*j+1][3]);
            #pragma unroll
            for (int np = 0; np < 4; ++np) {
                uint32_t bh[4], bl[4];
                const uint32_t off = (uint32_t)((j * 16 + vR) * PQ + np * 16 + vC4) * 2u;
                ldmx4t(bh[0], bh[1], bh[2], bh[3], VH + off);
                ldmx4t(bl[0], bl[1], bl[2], bl[3], VL + off);
                mma_f16(o[2*np][0], o[2*np][1], o[2*np][2], o[2*np][3],
                        ph[0], ph[1], ph[2], ph[3], bh[0], bh[1]);
                mma_f16(o[2*np][0], o[2*np][1], o[2*np][2], o[2*np][3],
                        ph[0], ph[1], ph[2], ph[3], bl[0], bl[1]);
                mma_f16(o[2*np+1][0], o[2*np+1][1], o[2*np+1][2], o[2*np+1][3],
                        ph[0], ph[1], ph[2], ph[3], bh[2], bh[3]);
                mma_f16(o[2*np+1][0], o[2*np+1][1], o[2*np+1][2], o[2*np+1][3],
                        ph[0], ph[1], ph[2], ph[3], bl[2], bl[3]);
            }
        }
        __syncthreads();
    }

    const float invA = 1.f / lA, invB = 1.f / lB;
    #pragma unroll
    for (int nf = 0; nf < 8; ++nf) {
        const int col = hc + nf * 8 + tig * 2;
        const size_t iA = (size_t)(rowBase + rA) * C_ + col;
        const size_t iB = iA + (size_t)8 * C_;
        uint32_t hh, ll;
        pack_hl(o[nf][0] * invA, o[nf][1] * invA, hh, ll);
        *(uint32_t*)&g_ah[iA] = hh; *(uint32_t*)&g_al[iA] = ll;
        pack_hl(o[nf][2] * invB, o[nf][3] * invB, hh, ll);
        *(uint32_t*)&g_ah[iB] = hh; *(uint32_t*)&g_al[iB] = ll;
    }
}

// ---------------------------------------------------------------------------
// Launch
// ---------------------------------------------------------------------------
extern "C" void kernel_launch(void* const* d_in, const int* in_sizes, int n_in,
                              void* d_out, int out_size)
{
    const float* x  = (const float*)d_in[0];
    const int*   tm = (const int*)  d_in[1];
    const float* wq = (const float*)d_in[2];
    const float* bq = (const float*)d_in[3];
    const float* wk = (const float*)d_in[4];
    const float* bk = (const float*)d_in[5];
    const float* wv = (const float*)d_in[6];
    const float* bv = (const float*)d_in[7];
    const float* wp = (const float*)d_in[8];
    const float* bp = (const float*)d_in[9];
    float* out = (float*)d_out;

    cudaFuncSetAttribute(qkv_kernel,  cudaFuncAttributeMaxDynamicSharedMemorySize, GSMEM);
    cudaFuncSetAttribute(proj_kernel, cudaFuncAttributeMaxDynamicSharedMemorySize, GSMEM);
    cudaFuncSetAttribute(attn_kernel, cudaFuncAttributeMaxDynamicSharedMemorySize, ATT_SMEM);

    const int nTot = (NX + 4 * NW) / 1024;   // quads per block = 256
    split_all_kernel<<<nTot, 256>>>(x, wq, wk, wv, wp);
    mask_scan_kernel<<<B_, 256>>>(tm);

    dim3 gGx(T_, B_);
    gather_x_kernel<<<gGx, 256>>>();

    dim3 gQKV(C_/128, M_/128, 3);
    qkv_kernel<<<gQKV, 256, GSMEM>>>(bq, bk, bv);

    dim3 gAtt(T_/128, NH_, B_);
    attn_kernel<<<gAtt, 256, ATT_SMEM>>>();

    dim3 gProj(C_/128, M_/128, 1);
    proj_kernel<<<gProj, 256, GSMEM>>>(bp, out);
}

// round 12
// speedup vs baseline: 4.1225x; 1.1142x over previous
#include <cuda_runtime.h>
#include <cuda_fp16.h>
#include <cstdint>

#define B_  4
#define T_  2048
#define C_  1024
#define NH_ 16
#define D_  64
#define M_  (B_*T_)
#define NX  (M_*C_)
#define NW  (C_*C_)

// ---- GEMM smem (halves, pitch 40): 4 tiles/stage, 2 stages ----
#define PH     40
#define TILEB  10240u
#define STAGEB 40960u
#define GSMEM  81920

// ---- Attention smem: Q(h,l) 128x64 + 2 stages x (Kh,Kl,Vh,Vl) 64x64 ----
#define PQ 72
#define KVTILE 9216u               // 64*PQ*2
#define STAGEA 36864u              // 4 KV tiles
#define QH_OFF 0u
#define QL_OFF 18432u
#define ST_OFF 36864u
#define ATT_SMEM 110592

extern __shared__ char dyn_smem[];

// Scratch (static device globals — no allocation at runtime)
__device__ __half g_qh[M_*C_],  g_ql[M_*C_];
__device__ __half g_ah[M_*C_],  g_al[M_*C_];
__device__ __half g_xh[M_*C_],  g_xl[M_*C_];
__device__ __half g_xch[M_*C_], g_xcl[M_*C_];   // compacted x (valid rows)
__device__ __half g_wqh[C_*C_], g_wql[C_*C_];
__device__ __half g_wkh[C_*C_], g_wkl[C_*C_];
__device__ __half g_wvh[C_*C_], g_wvl[C_*C_];
__device__ __half g_wph[C_*C_], g_wpl[C_*C_];
// mask compaction
__device__ int    g_cnt[B_*T_];            // inclusive count of valid tokens <= t
__device__ int    g_pos[B_*T_];            // compact index j -> original position
// compacted K/V (written directly by K/V GEMM epilogue)
__device__ __half g_kch[M_*C_], g_kcl[M_*C_];
__device__ __half g_vch[M_*C_], g_vcl[M_*C_];

// ---------------------------------------------------------------------------
// helpers
// ---------------------------------------------------------------------------
__device__ __forceinline__ uint32_t smem_to_u32(const void* p) {
    uint32_t a;
    asm("{ .reg .u64 t; cvta.to.shared.u64 t, %1; cvt.u32.u64 %0, t; }"
        : "=r"(a) : "l"(p));
    return a;
}

__device__ __forceinline__ void cp_async16(uint32_t s, const void* g) {
    asm volatile("cp.async.cg.shared.global [%0], [%1], 16;" :: "r"(s), "l"(g));
}
#define CP_COMMIT() asm volatile("cp.async.commit_group;" ::: "memory")

__device__ __forceinline__ void ldmx4(uint32_t& r0, uint32_t& r1,
                                      uint32_t& r2, uint32_t& r3, uint32_t a) {
    asm volatile("ldmatrix.sync.aligned.m8n8.x4.shared.b16 {%0,%1,%2,%3}, [%4];"
                 : "=r"(r0), "=r"(r1), "=r"(r2), "=r"(r3) : "r"(a));
}
__device__ __forceinline__ void ldmx2(uint32_t& r0, uint32_t& r1, uint32_t a) {
    asm volatile("ldmatrix.sync.aligned.m8n8.x2.shared.b16 {%0,%1}, [%2];"
                 : "=r"(r0), "=r"(r1) : "r"(a));
}
__device__ __forceinline__ void ldmx4t(uint32_t& r0, uint32_t& r1,
                                       uint32_t& r2, uint32_t& r3, uint32_t a) {
    asm volatile("ldmatrix.sync.aligned.m8n8.x4.trans.shared.b16 {%0,%1,%2,%3}, [%4];"
                 : "=r"(r0), "=r"(r1), "=r"(r2), "=r"(r3) : "r"(a));
}

__device__ __forceinline__ void mma_f16(float& c0, float& c1, float& c2, float& c3,
                                        uint32_t a0, uint32_t a1, uint32_t a2, uint32_t a3,
                                        uint32_t b0, uint32_t b1) {
    asm volatile(
        "mma.sync.aligned.m16n8k16.row.col.f32.f16.f16.f32 "
        "{%0,%1,%2,%3}, {%4,%5,%6,%7}, {%8,%9}, {%0,%1,%2,%3};\n"
        : "+f"(c0), "+f"(c1), "+f"(c2), "+f"(c3)
        : "r"(a0), "r"(a1), "r"(a2), "r"(a3), "r"(b0), "r"(b1));
}

__device__ __forceinline__ float ex2f(float x) {
    float r;
    asm("ex2.approx.f32 %0, %1;" : "=f"(r) : "f"(x));
    return r;
}

__device__ __forceinline__ uint32_t pack_h2(float x, float y) {
    uint32_t r;
    asm("cvt.rn.f16x2.f32 %0, %1, %2;" : "=r"(r) : "f"(y), "f"(x));
    return r;
}

__device__ __forceinline__ void pack_hl(float x, float y, uint32_t& hh, uint32_t& ll) {
    __half hx = __float2half_rn(x), hy = __float2half_rn(y);
    __half lx = __float2half_rn(x - __half2float(hx));
    __half ly = __float2half_rn(y - __half2float(hy));
    __half2 H = __halves2half2(hx, hy), L = __halves2half2(lx, ly);
    hh = *(uint32_t*)&H; ll = *(uint32_t*)&L;
}

// ---------------------------------------------------------------------------
// fused split prepass: fp32 -> (hi fp16, lo fp16) for x + all 4 weights
// ---------------------------------------------------------------------------
__global__ void __launch_bounds__(256) split_all_kernel(
    const float* __restrict__ x,  const float* __restrict__ wq,
    const float* __restrict__ wk, const float* __restrict__ wv,
    const float* __restrict__ wp)
{
    const long long i4 = ((long long)blockIdx.x * 256 + threadIdx.x) * 4;
    const float* src; __half *dh, *dl; long long off;
    if (i4 < (long long)NX) {
        src = x; dh = g_xh; dl = g_xl; off = i4;
    } else {
        const long long r = i4 - (long long)NX;
        const int wsel = (int)(r >> 20);      // NW == 1<<20
        off = r & (long long)(NW - 1);
        switch (wsel) {
            case 0:  src = wq; dh = g_wqh; dl = g_wql; break;
            case 1:  src = wk; dh = g_wkh; dl = g_wkl; break;
            case 2:  src = wv; dh = g_wvh; dl = g_wvl; break;
            default: src = wp; dh = g_wph; dl = g_wpl; break;
        }
    }
    float4 v = *(const float4*)(src + off);
    uint32_t h0, l0, h1, l1;
    pack_hl(v.x, v.y, h0, l0);
    pack_hl(v.z, v.w, h1, l1);
    *(uint32_t*)(dh + off)     = h0;
    *(uint32_t*)(dh + off + 2) = h1;
    *(uint32_t*)(dl + off)     = l0;
    *(uint32_t*)(dl + off + 2) = l1;
}

// ---------------------------------------------------------------------------
// token-mask scan: per batch, inclusive counts + compact position list
// ---------------------------------------------------------------------------
__global__ void __launch_bounds__(256) mask_scan_kernel(const int* __restrict__ tmask)
{
    __shared__ int wsum[8];
    const int b = blockIdx.x;
    const int tid = threadIdx.x;
    const int lane = tid & 31, wid = tid >> 5;
    const int t0 = tid * 8;

    int v[8]; int s = 0;
    #pragma unroll
    for (int i = 0; i < 8; ++i) { v[i] = (tmask[b*T_ + t0 + i] != 0) ? 1 : 0; s += v[i]; }

    int sc = s;
    #pragma unroll
    for (int off = 1; off < 32; off <<= 1) {
        int n = __shfl_up_sync(0xffffffffu, sc, off);
        if (lane >= off) sc += n;
    }
    if (lane == 31) wsum[wid] = sc;
    __syncthreads();
    if (tid == 0) {
        int acc = 0;
        #pragma unroll
        for (int i = 0; i < 8; ++i) { acc += wsum[i]; wsum[i] = acc; }
    }
    __syncthreads();
    const int wbase = (wid > 0) ? wsum[wid - 1] : 0;
    int run = wbase + sc - s;
    #pragma unroll
    for (int i = 0; i < 8; ++i) {
        run += v[i];
        g_cnt[b*T_ + t0 + i] = run;
        if (v[i]) g_pos[b*T_ + run - 1] = t0 + i;
    }
}

// ---------------------------------------------------------------------------
// gather valid x rows into compacted buffers (input to K/V GEMMs)
// ---------------------------------------------------------------------------
__global__ void __launch_bounds__(256) gather_x_kernel()
{
    const int j = blockIdx.x, b = blockIdx.y;
    if (j >= g_cnt[b*T_ + T_ - 1]) return;
    const int src = g_pos[b*T_ + j];
    const size_t so = (size_t)(b*T_ + src) * C_;
    const size_t dofs = (size_t)(b*T_ + j) * C_;
    for (int u = threadIdx.x; u < 256; u += 256) {
        const int arr = u >> 7, i = u & 127;
        const __half* sa = (arr == 0) ? g_xh : g_xl;
        __half* da       = (arr == 0) ? g_xch : g_xcl;
        ((float4*)(da + dofs))[i] = ((const float4*)(sa + so))[i];
    }
}

// ---------------------------------------------------------------------------
// fp16x3 GEMM: 128x128 tile of A[.,1024] @ W[.,1024]^T + bias
// ---------------------------------------------------------------------------
__device__ __forceinline__ void tc_gemm_tile(
    const __half* __restrict__ Ah, const __half* __restrict__ Al,
    const __half* __restrict__ Wh, const __half* __restrict__ Wl,
    const float* __restrict__ bias,
    float* __restrict__ outF, __half* __restrict__ outH,
    __half* __restrict__ outL, float scale)
{
    const uint32_t sb = smem_to_u32(dyn_smem);

    const int tid  = threadIdx.x;
    const int wid  = tid >> 5;
    const int lane = tid & 31;
    const int g    = lane >> 2;
    const int tig  = lane & 3;

    const int row0 = blockIdx.y * 128;
    const int col0 = blockIdx.x * 128;
    const int warpM = (wid & 1) * 64;
    const int warpN = (wid >> 1) * 32;

    auto issue_chunk = [&](int st, uint32_t stage) {
        const int k0 = st * 32;
        #pragma unroll
        for (int p = 0; p < 2; ++p) {
            const int gid = tid + p * 256;
            const int r = gid >> 2, c = gid & 3;
            const uint32_t d = stage + (uint32_t)(r * PH + c * 8) * 2u;
            const size_t so = (size_t)(row0 + r) * C_ + k0 + c * 8;
            const size_t wo = (size_t)(col0 + r) * C_ + k0 + c * 8;
            cp_async16(d,             Ah + so);
            cp_async16(d + TILEB,     Al + so);
            cp_async16(d + 2 * TILEB, Wh + wo);
            cp_async16(d + 3 * TILEB, Wl + wo);
        }
        CP_COMMIT();
    };

    float acc[4][4][4];
    #pragma unroll
    for (int mf = 0; mf < 4; ++mf)
        #pragma unroll
        for (int nf = 0; nf < 4; ++nf)
            #pragma unroll
            for (int r = 0; r < 4; ++r) acc[mf][nf][r] = 0.f;

    issue_chunk(0, sb);
    issue_chunk(1, sb + STAGEB);

    const int aRow = (lane & 15);
    const int aCol = (lane >> 4) << 3;
    const int bRow = (lane & 7);
    const int bCol = ((lane >> 3) & 1) << 3;

    for (int st = 0; st < 32; ++st) {
        if (st < 31) { asm volatile("cp.async.wait_group 1;" ::: "memory"); }
        else         { asm volatile("cp.async.wait_group 0;" ::: "memory"); }
        __syncthreads();

        const uint32_t stage = sb + (st & 1) * STAGEB;

        #pragma unroll
        for (int kk = 0; kk < 2; ++kk) {
            const int k16 = kk * 16;

            uint32_t afh[4][4], bfh[4][2];
            #pragma unroll
            for (int mf = 0; mf < 4; ++mf) {
                const uint32_t a = stage +
                    (uint32_t)((warpM + mf * 16 + aRow) * PH + k16 + aCol) * 2u;
                ldmx4(afh[mf][0], afh[mf][1], afh[mf][2], afh[mf][3], a);
            }
            #pragma unroll
            for (int nf = 0; nf < 4; ++nf) {
                const uint32_t a = stage + 2 * TILEB +
                    (uint32_t)((warpN + nf * 8 + bRow) * PH + k16 + bCol) * 2u;
                ldmx2(bfh[nf][0], bfh[nf][1], a);
            }
            #pragma unroll
            for (int mf = 0; mf < 4; ++mf)
                #pragma unroll
                for (int nf = 0; nf < 4; ++nf)
                    mma_f16(acc[mf][nf][0], acc[mf][nf][1], acc[mf][nf][2], acc[mf][nf][3],
                            afh[mf][0], afh[mf][1], afh[mf][2], afh[mf][3],
                            bfh[nf][0], bfh[nf][1]);
            uint32_t bfl[4][2];
            #pragma unroll
            for (int nf = 0; nf < 4; ++nf) {
                const uint32_t a = stage + 3 * TILEB +
                    (uint32_t)((warpN + nf * 8 + bRow) * PH + k16 + bCol) * 2u;
                ldmx2(bfl[nf][0], bfl[nf][1], a);
            }
            #pragma unroll
            for (int mf = 0; mf < 4; ++mf)
                #pragma unroll
                for (int nf = 0; nf < 4; ++nf)
                    mma_f16(acc[mf][nf][0], acc[mf][nf][1], acc[mf][nf][2], acc[mf][nf][3],
                            afh[mf][0], afh[mf][1], afh[mf][2], afh[mf][3],
                            bfl[nf][0], bfl[nf][1]);
            uint32_t afl[4][4];
            #pragma unroll
            for (int mf = 0; mf < 4; ++mf) {
                const uint32_t a = stage + TILEB +
                    (uint32_t)((warpM + mf * 16 + aRow) * PH + k16 + aCol) * 2u;
                ldmx4(afl[mf][0], afl[mf][1], afl[mf][2], afl[mf][3], a);
            }
            #pragma unroll
            for (int mf = 0; mf < 4; ++mf)
                #pragma unroll
                for (int nf = 0; nf < 4; ++nf)
                    mma_f16(acc[mf][nf][0], acc[mf][nf][1], acc[mf][nf][2], acc[mf][nf][3],
                            afl[mf][0], afl[mf][1], afl[mf][2], afl[mf][3],
                            bfh[nf][0], bfh[nf][1]);
        }
        __syncthreads();
        if (st + 2 < 32) issue_chunk(st + 2, sb + (st & 1) * STAGEB);
    }

    #pragma unroll
    for (int nf = 0; nf < 4; ++nf) {
        const int colg = col0 + warpN + nf * 8 + tig * 2;
        const float2 bb = *(const float2*)&bias[colg];
        #pragma unroll
        for (int mf = 0; mf < 4; ++mf) {
            const int rowg = row0 + warpM + mf * 16 + g;
            const float v00 = acc[mf][nf][0] + bb.x, v01 = acc[mf][nf][1] + bb.y;
            const float v10 = acc[mf][nf][2] + bb.x, v11 = acc[mf][nf][3] + bb.y;
            if (outF) {
                *(float2*)&outF[(size_t)rowg * C_ + colg]       = make_float2(v00, v01);
                *(float2*)&outF[(size_t)(rowg + 8) * C_ + colg] = make_float2(v10, v11);
            } else {
                uint32_t hh, ll;
                pack_hl(v00 * scale, v01 * scale, hh, ll);
                *(uint32_t*)&outH[(size_t)rowg * C_ + colg] = hh;
                *(uint32_t*)&outL[(size_t)rowg * C_ + colg] = ll;
                pack_hl(v10 * scale, v11 * scale, hh, ll);
                *(uint32_t*)&outH[(size_t)(rowg + 8) * C_ + colg] = hh;
                *(uint32_t*)&outL[(size_t)(rowg + 8) * C_ + colg] = ll;
            }
        }
    }
}

// Q scaled by (1/sqrt(D)) * log2(e) so softmax runs in exp2 domain
#define QSCALE (0.125f * 1.4426950408889634f)

// sel 0: Q (full rows, from x); sel 1: K, sel 2: V (compacted rows, from xc)
// __launch_bounds__(256, 2): cap regs at 128 so 2 CTAs co-reside per SM
__global__ void __launch_bounds__(256, 2) qkv_kernel(
    const float* __restrict__ bq, const float* __restrict__ bk,
    const float* __restrict__ bv)
{
    const int sel = blockIdx.z;
    if (sel != 0) {
        const int row0 = blockIdx.y * 128;
        const int b = row0 / T_;
        const int local = row0 - b * T_;
        if (local >= g_cnt[b*T_ + T_ - 1]) return;
    }
    const __half* Ah   = (sel == 0) ? g_xh  : g_xch;
    const __half* Al   = (sel == 0) ? g_xl  : g_xcl;
    const __half* Wh   = (sel == 0) ? g_wqh : (sel == 1) ? g_wkh : g_wvh;
    const __half* Wl   = (sel == 0) ? g_wql : (sel == 1) ? g_wkl : g_wvl;
    const float*  bias = (sel == 0) ? bq    : (sel == 1) ? bk    : bv;
    __half* outH       = (sel == 0) ? g_qh  : (sel == 1) ? g_kch : g_vch;
    __half* outL       = (sel == 0) ? g_ql  : (sel == 1) ? g_kcl : g_vcl;
    const float scale  = (sel == 0) ? QSCALE : 1.0f;
    tc_gemm_tile(Ah, Al, Wh, Wl, bias, nullptr, outH, outL, scale);
}

__global__ void __launch_bounds__(256, 2) proj_kernel(
    const float* __restrict__ bp, float* __restrict__ out)
{
    tc_gemm_tile(g_ah, g_al, g_wph, g_wpl, bp, out, nullptr, nullptr, 1.0f);
}

// ---------------------------------------------------------------------------
// fp16x3 flash attention over COMPACTED K/V (unchanged from R10)
// ---------------------------------------------------------------------------
__global__ void __launch_bounds__(256, 2) attn_kernel()
{
    const uint32_t sb = smem_to_u32(dyn_smem);

    const int qt = (T_ / 128 - 1) - blockIdx.x;
    const int h = blockIdx.y, b = blockIdx.z;
    const int q0 = qt * 128;
    const int tid = threadIdx.x, w = tid >> 5, lane = tid & 31;
    const int g = lane >> 2, tig = lane & 3;
    const int rowBase = b * T_;
    const int hc = h * D_;

    #pragma unroll
    for (int it = 0; it < 4; ++it) {
        const int gr = tid + it * 256;
        const int r = gr >> 3, c8 = (gr & 7) * 8;
        const size_t src = (size_t)(rowBase + q0 + r) * C_ + hc + c8;
        const uint32_t d = sb + (uint32_t)(r * PQ + c8) * 2u;
        cp_async16(d + QH_OFF, g_qh + src);
        cp_async16(d + QL_OFF, g_ql + src);
    }

    auto issueKV = [&](int kt, int buf) {
        const int k0 = kt * 64;
        const uint32_t base = sb + ST_OFF + (uint32_t)buf * STAGEA;
        #pragma unroll
        for (int it = 0; it < 2; ++it) {
            const int gr = tid + it * 256;
            const int r = gr >> 3, c8 = (gr & 7) * 8;
            const size_t src = (size_t)(rowBase + k0 + r) * C_ + hc + c8;
            const uint32_t d = base + (uint32_t)(r * PQ + c8) * 2u;
            cp_async16(d,              g_kch + src);
            cp_async16(d + KVTILE,     g_kcl + src);
            cp_async16(d + 2 * KVTILE, g_vch + src);
            cp_async16(d + 3 * KVTILE, g_vcl + src);
        }
        CP_COMMIT();
    };

    issueKV(0, 0);

    const int rA = q0 + w * 16 + g;
    const int rB = rA + 8;
    const int cntA = g_cnt[rowBase + rA];
    const int cntB = g_cnt[rowBase + rB];
    const int NVq  = g_cnt[rowBase + q0 + 127];
    const int nkt  = (NVq + 63) >> 6;

    float o[8][4];
    #pragma unroll
    for (int nf = 0; nf < 8; ++nf)
        #pragma unroll
        for (int c = 0; c < 4; ++c) o[nf][c] = 0.f;
    float mA = -1e30f, mB = -1e30f, lA = 0.f, lB = 0.f;

    const int aRow = lane & 15, aCol = (lane >> 4) << 3;
    const int bR4 = ((lane >> 4) << 3) + (lane & 7);   // K (non-trans)
    const int bC4 = ((lane >> 3) & 1) << 3;
    const int vR  = lane & 15;                          // V (trans)
    const int vC4 = (lane >> 4) << 3;

    for (int kt = 0; kt < nkt; ++kt) {
        const int buf = kt & 1;
        if (kt + 1 < nkt) {
            issueKV(kt + 1, buf ^ 1);
            asm volatile("cp.async.wait_group 1;" ::: "memory");
        } else {
            asm volatile("cp.async.wait_group 0;" ::: "memory");
        }
        __syncthreads();

        const int k0 = kt * 64;
        const uint32_t KH = sb + ST_OFF + (uint32_t)buf * STAGEA;
        const uint32_t KL = KH + KVTILE;
        const uint32_t VH = KH + 2 * KVTILE;
        const uint32_t VL = KH + 3 * KVTILE;

        float s[8][4];
        #pragma unroll
        for (int nf = 0; nf < 8; ++nf)
            #pragma unroll
            for (int c = 0; c < 4; ++c) s[nf][c] = 0.f;

        #pragma unroll
        for (int kk = 0; kk < 4; ++kk) {
            const int k16 = kk * 16;
            uint32_t aqh[4], aql[4];
            ldmx4(aqh[0], aqh[1], aqh[2], aqh[3],
                  sb + QH_OFF + (uint32_t)((w * 16 + aRow) * PQ + k16 + aCol) * 2u);
            ldmx4(aql[0], aql[1], aql[2], aql[3],
                  sb + QL_OFF + (uint32_t)((w * 16 + aRow) * PQ + k16 + aCol) * 2u);
            #pragma unroll
            for (int np = 0; np < 4; ++np) {
                uint32_t bh[4], bl[4];
                const uint32_t off = (uint32_t)((np * 16 + bR4) * PQ + k16 + bC4) * 2u;
                ldmx4(bh[0], bh[1], bh[2], bh[3], KH + off);
                ldmx4(bl[0], bl[1], bl[2], bl[3], KL + off);
                mma_f16(s[2*np][0], s[2*np][1], s[2*np][2], s[2*np][3],
                        aqh[0], aqh[1], aqh[2], aqh[3], bh[0], bh[1]);
                mma_f16(s[2*np][0], s[2*np][1], s[2*np][2], s[2*np][3],
                        aqh[0], aqh[1], aqh[2], aqh[3], bl[0], bl[1]);
                mma_f16(s[2*np][0], s[2*np][1], s[2*np][2], s[2*np][3],
                        aql[0], aql[1], aql[2], aql[3], bh[0], bh[1]);
                mma_f16(s[2*np+1][0], s[2*np+1][1], s[2*np+1][2], s[2*np+1][3],
                        aqh[0], aqh[1], aqh[2], aqh[3], bh[2], bh[3]);
                mma_f16(s[2*np+1][0], s[2*np+1][1], s[2*np+1][2], s[2*np+1][3],
                        aqh[0], aqh[1], aqh[2], aqh[3], bl[2], bl[3]);
                mma_f16(s[2*np+1][0], s[2*np+1][1], s[2*np+1][2], s[2*np+1][3],
                        aql[0], aql[1], aql[2], aql[3], bh[2], bh[3]);
            }
        }

        #pragma unroll
        for (int nf = 0; nf < 8; ++nf) {
            const int c0 = k0 + nf * 8 + tig * 2;
            s[nf][0] = (c0     < cntA) ? s[nf][0] : -1e30f;
            s[nf][1] = (c0 + 1 < cntA) ? s[nf][1] : -1e30f;
            s[nf][2] = (c0     < cntB) ? s[nf][2] : -1e30f;
            s[nf][3] = (c0 + 1 < cntB) ? s[nf][3] : -1e30f;
        }

        float mxA = -1e30f, mxB = -1e30f;
        #pragma unroll
        for (int nf = 0; nf < 8; ++nf) {
            mxA = fmaxf(mxA, fmaxf(s[nf][0], s[nf][1]));
            mxB = fmaxf(mxB, fmaxf(s[nf][2], s[nf][3]));
        }
        mxA = fmaxf(mxA, __shfl_xor_sync(0xffffffffu, mxA, 1));
        mxA = fmaxf(mxA, __shfl_xor_sync(0xffffffffu, mxA, 2));
        mxB = fmaxf(mxB, __shfl_xor_sync(0xffffffffu, mxB, 1));
        mxB = fmaxf(mxB, __shfl_xor_sync(0xffffffffu, mxB, 2));
        const float mnA = fmaxf(mA, mxA), mnB = fmaxf(mB, mxB);
        const float cA = ex2f(mA - mnA), cB = ex2f(mB - mnB);
        mA = mnA; mB = mnB;
        float sA = 0.f, sB = 0.f;
        #pragma unroll
        for (int nf = 0; nf < 8; ++nf) {
            s[nf][0] = ex2f(s[nf][0] - mnA);
            s[nf][1] = ex2f(s[nf][1] - mnA);
            s[nf][2] = ex2f(s[nf][2] - mnB);
            s[nf][3] = ex2f(s[nf][3] - mnB);
            sA += s[nf][0] + s[nf][1];
            sB += s[nf][2] + s[nf][3];
        }
        sA += __shfl_xor_sync(0xffffffffu, sA, 1);
        sA += __shfl_xor_sync(0xffffffffu, sA, 2);
        sB += __shfl_xor_sync(0xffffffffu, sB, 1);
        sB += __shfl_xor_sync(0xffffffffu, sB, 2);
        lA = lA * cA + sA;
        lB = lB * cB + sB;
        #pragma unroll
        for (int nf = 0; nf < 8; ++nf) {
            o[nf][0] *= cA; o[nf][1] *= cA;
            o[nf][2] *= cB; o[nf][3] *= cB;
        }

        #pragma unroll
        for (int j = 0; j < 4; ++j) {
            uint32_t ph[4];
            ph[0] = pack_h2(s[2*j][0],   s[2*j][1]);
            ph[1] = pack_h2(s[2*j][2],   s[2*j][3]);
            ph[2] = pack_h2(s[2*j+1][0], s[2*j+1][1]);
            ph[3] = pack_h2(s[2*j+1][2], s[2*j+1][3]);
            #pragma unroll
            for (int np = 0; np < 4; ++np) {
                uint32_t bh[4], bl[4];
                const uint32_t off = (uint32_t)((j * 16 + vR) * PQ + np * 16 + vC4) * 2u;
                ldmx4t(bh[0], bh[1], bh[2], bh[3], VH + off);
                ldmx4t(bl[0], bl[1], bl[2], bl[3], VL + off);
                mma_f16(o[2*np][0], o[2*np][1], o[2*np][2], o[2*np][3],
                        ph[0], ph[1], ph[2], ph[3], bh[0], bh[1]);
                mma_f16(o[2*np][0], o[2*np][1], o[2*np][2], o[2*np][3],
                        ph[0], ph[1], ph[2], ph[3], bl[0], bl[1]);
                mma_f16(o[2*np+1][0], o[2*np+1][1], o[2*np+1][2], o[2*np+1][3],
                        ph[0], ph[1], ph[2], ph[3], bh[2], bh[3]);
                mma_f16(o[2*np+1][0], o[2*np+1][1], o[2*np+1][2], o[2*np+1][3],
                        ph[0], ph[1], ph[2], ph[3], bl[2], bl[3]);
            }
        }
        __syncthreads();
    }

    const float invA = 1.f / lA, invB = 1.f / lB;
    #pragma unroll
    for (int nf = 0; nf < 8; ++nf) {
        const int col = hc + nf * 8 + tig * 2;
        const size_t iA = (size_t)(rowBase + rA) * C_ + col;
        const size_t iB = iA + (size_t)8 * C_;
        uint32_t hh, ll;
        pack_hl(o[nf][0] * invA, o[nf][1] * invA, hh, ll);
        *(uint32_t*)&g_ah[iA] = hh; *(uint32_t*)&g_al[iA] = ll;
        pack_hl(o[nf][2] * invB, o[nf][3] * invB, hh, ll);
        *(uint32_t*)&g_ah[iB] = hh; *(uint32_t*)&g_al[iB] = ll;
    }
}

// ---------------------------------------------------------------------------
// Launch
// ---------------------------------------------------------------------------
extern "C" void kernel_launch(void* const* d_in, const int* in_sizes, int n_in,
                              void* d_out, int out_size)
{
    const float* x  = (const float*)d_in[0];
    const int*   tm = (const int*)  d_in[1];
    const float* wq = (const float*)d_in[2];
    const float* bq = (const float*)d_in[3];
    const float* wk = (const float*)d_in[4];
    const float* bk = (const float*)d_in[5];
    const float* wv = (const float*)d_in[6];
    const float* bv = (const float*)d_in[7];
    const float* wp = (const float*)d_in[8];
    const float* bp = (const float*)d_in[9];
    float* out = (float*)d_out;

    cudaFuncSetAttribute(qkv_kernel,  cudaFuncAttributeMaxDynamicSharedMemorySize, GSMEM);
    cudaFuncSetAttribute(proj_kernel, cudaFuncAttributeMaxDynamicSharedMemorySize, GSMEM);
    cudaFuncSetAttribute(attn_kernel, cudaFuncAttributeMaxDynamicSharedMemorySize, ATT_SMEM);

    const int nTot = (NX + 4 * NW) / 1024;
    split_all_kernel<<<nTot, 256>>>(x, wq, wk, wv, wp);
    mask_scan_kernel<<<B_, 256>>>(tm);

    dim3 gGx(T_, B_);
    gather_x_kernel<<<gGx, 256>>>();

    dim3 gQKV(C_/128, M_/128, 3);
    qkv_kernel<<<gQKV, 256, GSMEM>>>(bq, bk, bv);

    dim3 gAtt(T_/128, NH_, B_);
    attn_kernel<<<gAtt, 256, ATT_SMEM>>>();

    dim3 gProj(C_/128, M_/128, 1);
    proj_kernel<<<gProj, 256, GSMEM>>>(bp, out);
}

// round 13
// speedup vs baseline: 5.2947x; 1.2843x over previous
#include <cuda_runtime.h>
#include <cuda_fp16.h>
#include <cstdint>

#define B_  4
#define T_  2048
#define C_  1024
#define NH_ 16
#define D_  64
#define M_  (B_*T_)
#define NX  (M_*C_)
#define NW  (C_*C_)

// ---- GEMM smem (halves, pitch 40): 3 tiles/stage (Ah, Wh, Wl), 2 stages ----
#define PH     40
#define TILEB  10240u
#define STAGEB 30720u
#define GSMEM  61440

// ---- Attention smem: Q(h,l) 128x64 + 2 stages x (Kh,Kl,Vh,Vl) 64x64 ----
#define PQ 72
#define KVTILE 9216u               // 64*PQ*2
#define STAGEA 36864u              // 4 KV tiles
#define QH_OFF 0u
#define QL_OFF 18432u
#define ST_OFF 36864u
#define ATT_SMEM 110592

extern __shared__ char dyn_smem[];

// Scratch (static device globals — no allocation at runtime)
__device__ __half g_qh[M_*C_],  g_ql[M_*C_];
__device__ __half g_ah[M_*C_];                  // attention out (hi only)
__device__ __half g_xh[M_*C_];                  // x hi
__device__ __half g_xch[M_*C_];                 // compacted x hi
__device__ __half g_wqh[C_*C_], g_wql[C_*C_];
__device__ __half g_wkh[C_*C_], g_wkl[C_*C_];
__device__ __half g_wvh[C_*C_], g_wvl[C_*C_];
__device__ __half g_wph[C_*C_], g_wpl[C_*C_];
// mask compaction
__device__ int    g_cnt[B_*T_];
__device__ int    g_pos[B_*T_];
// compacted K/V (written directly by K/V GEMM epilogue)
__device__ __half g_kch[M_*C_], g_kcl[M_*C_];
__device__ __half g_vch[M_*C_], g_vcl[M_*C_];

// ---------------------------------------------------------------------------
// helpers
// ---------------------------------------------------------------------------
__device__ __forceinline__ uint32_t smem_to_u32(const void* p) {
    uint32_t a;
    asm("{ .reg .u64 t; cvta.to.shared.u64 t, %1; cvt.u32.u64 %0, t; }"
        : "=r"(a) : "l"(p));
    return a;
}

__device__ __forceinline__ void cp_async16(uint32_t s, const void* g) {
    asm volatile("cp.async.cg.shared.global [%0], [%1], 16;" :: "r"(s), "l"(g));
}
#define CP_COMMIT() asm volatile("cp.async.commit_group;" ::: "memory")

__device__ __forceinline__ void ldmx4(uint32_t& r0, uint32_t& r1,
                                      uint32_t& r2, uint32_t& r3, uint32_t a) {
    asm volatile("ldmatrix.sync.aligned.m8n8.x4.shared.b16 {%0,%1,%2,%3}, [%4];"
                 : "=r"(r0), "=r"(r1), "=r"(r2), "=r"(r3) : "r"(a));
}
__device__ __forceinline__ void ldmx4t(uint32_t& r0, uint32_t& r1,
                                       uint32_t& r2, uint32_t& r3, uint32_t a) {
    asm volatile("ldmatrix.sync.aligned.m8n8.x4.trans.shared.b16 {%0,%1,%2,%3}, [%4];"
                 : "=r"(r0), "=r"(r1), "=r"(r2), "=r"(r3) : "r"(a));
}

__device__ __forceinline__ void mma_f16(float& c0, float& c1, float& c2, float& c3,
                                        uint32_t a0, uint32_t a1, uint32_t a2, uint32_t a3,
                                        uint32_t b0, uint32_t b1) {
    asm volatile(
        "mma.sync.aligned.m16n8k16.row.col.f32.f16.f16.f32 "
        "{%0,%1,%2,%3}, {%4,%5,%6,%7}, {%8,%9}, {%0,%1,%2,%3};\n"
        : "+f"(c0), "+f"(c1), "+f"(c2), "+f"(c3)
        : "r"(a0), "r"(a1), "r"(a2), "r"(a3), "r"(b0), "r"(b1));
}

__device__ __forceinline__ float ex2f(float x) {
    float r;
    asm("ex2.approx.f32 %0, %1;" : "=f"(r) : "f"(x));
    return r;
}

__device__ __forceinline__ uint32_t pack_h2(float x, float y) {
    uint32_t r;
    asm("cvt.rn.f16x2.f32 %0, %1, %2;" : "=r"(r) : "f"(y), "f"(x));
    return r;
}

__device__ __forceinline__ void pack_hl(float x, float y, uint32_t& hh, uint32_t& ll) {
    __half hx = __float2half_rn(x), hy = __float2half_rn(y);
    __half lx = __float2half_rn(x - __half2float(hx));
    __half ly = __float2half_rn(y - __half2float(hy));
    __half2 H = __halves2half2(hx, hy), L = __halves2half2(lx, ly);
    hh = *(uint32_t*)&H; ll = *(uint32_t*)&L;
}

// ---------------------------------------------------------------------------
// fused split prepass: x -> hi only; weights -> (hi, lo)
// ---------------------------------------------------------------------------
__global__ void __launch_bounds__(256) split_all_kernel(
    const float* __restrict__ x,  const float* __restrict__ wq,
    const float* __restrict__ wk, const float* __restrict__ wv,
    const float* __restrict__ wp)
{
    const long long i4 = ((long long)blockIdx.x * 256 + threadIdx.x) * 4;
    if (i4 < (long long)NX) {
        float4 v = *(const float4*)(x + i4);
        *(uint32_t*)(g_xh + i4)     = pack_h2(v.x, v.y);
        *(uint32_t*)(g_xh + i4 + 2) = pack_h2(v.z, v.w);
        return;
    }
    const long long r = i4 - (long long)NX;
    const int wsel = (int)(r >> 20);          // NW == 1<<20
    const long long off = r & (long long)(NW - 1);
    const float* src; __half *dh, *dl;
    switch (wsel) {
        case 0:  src = wq; dh = g_wqh; dl = g_wql; break;
        case 1:  src = wk; dh = g_wkh; dl = g_wkl; break;
        case 2:  src = wv; dh = g_wvh; dl = g_wvl; break;
        default: src = wp; dh = g_wph; dl = g_wpl; break;
    }
    float4 v = *(const float4*)(src + off);
    uint32_t h0, l0, h1, l1;
    pack_hl(v.x, v.y, h0, l0);
    pack_hl(v.z, v.w, h1, l1);
    *(uint32_t*)(dh + off)     = h0;
    *(uint32_t*)(dh + off + 2) = h1;
    *(uint32_t*)(dl + off)     = l0;
    *(uint32_t*)(dl + off + 2) = l1;
}

// ---------------------------------------------------------------------------
// token-mask scan: per batch, inclusive counts + compact position list
// ---------------------------------------------------------------------------
__global__ void __launch_bounds__(256) mask_scan_kernel(const int* __restrict__ tmask)
{
    __shared__ int wsum[8];
    const int b = blockIdx.x;
    const int tid = threadIdx.x;
    const int lane = tid & 31, wid = tid >> 5;
    const int t0 = tid * 8;

    int v[8]; int s = 0;
    #pragma unroll
    for (int i = 0; i < 8; ++i) { v[i] = (tmask[b*T_ + t0 + i] != 0) ? 1 : 0; s += v[i]; }

    int sc = s;
    #pragma unroll
    for (int off = 1; off < 32; off <<= 1) {
        int n = __shfl_up_sync(0xffffffffu, sc, off);
        if (lane >= off) sc += n;
    }
    if (lane == 31) wsum[wid] = sc;
    __syncthreads();
    if (tid == 0) {
        int acc = 0;
        #pragma unroll
        for (int i = 0; i < 8; ++i) { acc += wsum[i]; wsum[i] = acc; }
    }
    __syncthreads();
    const int wbase = (wid > 0) ? wsum[wid - 1] : 0;
    int run = wbase + sc - s;
    #pragma unroll
    for (int i = 0; i < 8; ++i) {
        run += v[i];
        g_cnt[b*T_ + t0 + i] = run;
        if (v[i]) g_pos[b*T_ + run - 1] = t0 + i;
    }
}

// ---------------------------------------------------------------------------
// gather valid x rows (hi) into compacted buffer
// ---------------------------------------------------------------------------
__global__ void __launch_bounds__(128) gather_x_kernel()
{
    const int j = blockIdx.x, b = blockIdx.y;
    if (j >= g_cnt[b*T_ + T_ - 1]) return;
    const int src = g_pos[b*T_ + j];
    const size_t so = (size_t)(b*T_ + src) * C_;
    const size_t dofs = (size_t)(b*T_ + j) * C_;
    ((float4*)(g_xch + dofs))[threadIdx.x] = ((const float4*)(g_xh + so))[threadIdx.x];
}

// ---------------------------------------------------------------------------
// fp16x2 GEMM: 128x128 tile, acc = Ah Wh^T + Ah Wl^T + bias
// (activation-lo dropped; weight split kept). B-frags paired via ldmx4.
// ---------------------------------------------------------------------------
__device__ __forceinline__ void tc_gemm_tile(
    const __half* __restrict__ Ah,
    const __half* __restrict__ Wh, const __half* __restrict__ Wl,
    const float* __restrict__ bias,
    float* __restrict__ outF, __half* __restrict__ outH,
    __half* __restrict__ outL, float scale)
{
    const uint32_t sb = smem_to_u32(dyn_smem);

    const int tid  = threadIdx.x;
    const int wid  = tid >> 5;
    const int lane = tid & 31;
    const int g    = lane >> 2;
    const int tig  = lane & 3;

    const int row0 = blockIdx.y * 128;
    const int col0 = blockIdx.x * 128;
    const int warpM = (wid & 1) * 64;
    const int warpN = (wid >> 1) * 32;

    auto issue_chunk = [&](int st, uint32_t stage) {
        const int k0 = st * 32;
        #pragma unroll
        for (int p = 0; p < 2; ++p) {
            const int gid = tid + p * 256;
            const int r = gid >> 2, c = gid & 3;
            const uint32_t d = stage + (uint32_t)(r * PH + c * 8) * 2u;
            const size_t so = (size_t)(row0 + r) * C_ + k0 + c * 8;
            const size_t wo = (size_t)(col0 + r) * C_ + k0 + c * 8;
            cp_async16(d,             Ah + so);
            cp_async16(d + TILEB,     Wh + wo);
            cp_async16(d + 2 * TILEB, Wl + wo);
        }
        CP_COMMIT();
    };

    float acc[4][4][4];
    #pragma unroll
    for (int mf = 0; mf < 4; ++mf)
        #pragma unroll
        for (int nf = 0; nf < 4; ++nf)
            #pragma unroll
            for (int r = 0; r < 4; ++r) acc[mf][nf][r] = 0.f;

    issue_chunk(0, sb);
    issue_chunk(1, sb + STAGEB);

    const int aRow = (lane & 15);
    const int aCol = (lane >> 4) << 3;
    const int bR4  = ((lane >> 4) << 3) + (lane & 7);
    const int bC4  = ((lane >> 3) & 1) << 3;

    for (int st = 0; st < 32; ++st) {
        if (st < 31) { asm volatile("cp.async.wait_group 1;" ::: "memory"); }
        else         { asm volatile("cp.async.wait_group 0;" ::: "memory"); }
        __syncthreads();

        const uint32_t stage = sb + (st & 1) * STAGEB;

        #pragma unroll
        for (int kk = 0; kk < 2; ++kk) {
            const int k16 = kk * 16;

            uint32_t af[4][4];
            #pragma unroll
            for (int mf = 0; mf < 4; ++mf) {
                const uint32_t a = stage +
                    (uint32_t)((warpM + mf * 16 + aRow) * PH + k16 + aCol) * 2u;
                ldmx4(af[mf][0], af[mf][1], af[mf][2], af[mf][3], a);
            }
            uint32_t bh[2][4], bl[2][4];
            #pragma unroll
            for (int np = 0; np < 2; ++np) {
                const uint32_t off =
                    (uint32_t)((warpN + np * 16 + bR4) * PH + k16 + bC4) * 2u;
                ldmx4(bh[np][0], bh[np][1], bh[np][2], bh[np][3],
                      stage + TILEB + off);
                ldmx4(bl[np][0], bl[np][1], bl[np][2], bl[np][3],
                      stage + 2 * TILEB + off);
            }
            #pragma unroll
            for (int mf = 0; mf < 4; ++mf)
                #pragma unroll
                for (int np = 0; np < 2; ++np) {
                    mma_f16(acc[mf][2*np][0], acc[mf][2*np][1],
                            acc[mf][2*np][2], acc[mf][2*np][3],
                            af[mf][0], af[mf][1], af[mf][2], af[mf][3],
                            bh[np][0], bh[np][1]);
                    mma_f16(acc[mf][2*np+1][0], acc[mf][2*np+1][1],
                            acc[mf][2*np+1][2], acc[mf][2*np+1][3],
                            af[mf][0], af[mf][1], af[mf][2], af[mf][3],
                            bh[np][2], bh[np][3]);
                    mma_f16(acc[mf][2*np][0], acc[mf][2*np][1],
                            acc[mf][2*np][2], acc[mf][2*np][3],
                            af[mf][0], af[mf][1], af[mf][2], af[mf][3],
                            bl[np][0], bl[np][1]);
                    mma_f16(acc[mf][2*np+1][0], acc[mf][2*np+1][1],
                            acc[mf][2*np+1][2], acc[mf][2*np+1][3],
                            af[mf][0], af[mf][1], af[mf][2], af[mf][3],
                            bl[np][2], bl[np][3]);
                }
        }
        __syncthreads();
        if (st + 2 < 32) issue_chunk(st + 2, sb + (st & 1) * STAGEB);
    }

    #pragma unroll
    for (int nf = 0; nf < 4; ++nf) {
        const int colg = col0 + warpN + nf * 8 + tig * 2;
        const float2 bb = *(const float2*)&bias[colg];
        #pragma unroll
        for (int mf = 0; mf < 4; ++mf) {
            const int rowg = row0 + warpM + mf * 16 + g;
            const float v00 = acc[mf][nf][0] + bb.x, v01 = acc[mf][nf][1] + bb.y;
            const float v10 = acc[mf][nf][2] + bb.x, v11 = acc[mf][nf][3] + bb.y;
            if (outF) {
                *(float2*)&outF[(size_t)rowg * C_ + colg]       = make_float2(v00, v01);
                *(float2*)&outF[(size_t)(rowg + 8) * C_ + colg] = make_float2(v10, v11);
            } else if (outL) {
                uint32_t hh, ll;
                pack_hl(v00 * scale, v01 * scale, hh, ll);
                *(uint32_t*)&outH[(size_t)rowg * C_ + colg] = hh;
                *(uint32_t*)&outL[(size_t)rowg * C_ + colg] = ll;
                pack_hl(v10 * scale, v11 * scale, hh, ll);
                *(uint32_t*)&outH[(size_t)(rowg + 8) * C_ + colg] = hh;
                *(uint32_t*)&outL[(size_t)(rowg + 8) * C_ + colg] = ll;
            } else {
                *(uint32_t*)&outH[(size_t)rowg * C_ + colg] =
                    pack_h2(v00 * scale, v01 * scale);
                *(uint32_t*)&outH[(size_t)(rowg + 8) * C_ + colg] =
                    pack_h2(v10 * scale, v11 * scale);
            }
        }
    }
}

// Q scaled by (1/sqrt(D)) * log2(e) so softmax runs in exp2 domain
#define QSCALE (0.125f * 1.4426950408889634f)

__global__ void __launch_bounds__(256, 2) qkv_kernel(
    const float* __restrict__ bq, const float* __restrict__ bk,
    const float* __restrict__ bv)
{
    const int sel = blockIdx.z;
    if (sel != 0) {
        const int row0 = blockIdx.y * 128;
        const int b = row0 / T_;
        const int local = row0 - b * T_;
        if (local >= g_cnt[b*T_ + T_ - 1]) return;
    }
    const __half* Ah   = (sel == 0) ? g_xh  : g_xch;
    const __half* Wh   = (sel == 0) ? g_wqh : (sel == 1) ? g_wkh : g_wvh;
    const __half* Wl   = (sel == 0) ? g_wql : (sel == 1) ? g_wkl : g_wvl;
    const float*  bias = (sel == 0) ? bq    : (sel == 1) ? bk    : bv;
    __half* outH       = (sel == 0) ? g_qh  : (sel == 1) ? g_kch : g_vch;
    __half* outL       = (sel == 0) ? g_ql  : (sel == 1) ? g_kcl : g_vcl;
    const float scale  = (sel == 0) ? QSCALE : 1.0f;
    tc_gemm_tile(Ah, Wh, Wl, bias, nullptr, outH, outL, scale);
}

__global__ void __launch_bounds__(256, 2) proj_kernel(
    const float* __restrict__ bp, float* __restrict__ out)
{
    tc_gemm_tile(g_ah, g_wph, g_wpl, bp, out, nullptr, nullptr, 1.0f);
}

// ---------------------------------------------------------------------------
// fp16x3 flash attention over COMPACTED K/V (S path full fp16x3; unchanged)
// ---------------------------------------------------------------------------
__global__ void __launch_bounds__(256, 2) attn_kernel()
{
    const uint32_t sb = smem_to_u32(dyn_smem);

    const int qt = (T_ / 128 - 1) - blockIdx.x;
    const int h = blockIdx.y, b = blockIdx.z;
    const int q0 = qt * 128;
    const int tid = threadIdx.x, w = tid >> 5, lane = tid & 31;
    const int g = lane >> 2, tig = lane & 3;
    const int rowBase = b * T_;
    const int hc = h * D_;

    #pragma unroll
    for (int it = 0; it < 4; ++it) {
        const int gr = tid + it * 256;
        const int r = gr >> 3, c8 = (gr & 7) * 8;
        const size_t src = (size_t)(rowBase + q0 + r) * C_ + hc + c8;
        const uint32_t d = sb + (uint32_t)(r * PQ + c8) * 2u;
        cp_async16(d + QH_OFF, g_qh + src);
        cp_async16(d + QL_OFF, g_ql + src);
    }

    auto issueKV = [&](int kt, int buf) {
        const int k0 = kt * 64;
        const uint32_t base = sb + ST_OFF + (uint32_t)buf * STAGEA;
        #pragma unroll
        for (int it = 0; it < 2; ++it) {
            const int gr = tid + it * 256;
            const int r = gr >> 3, c8 = (gr & 7) * 8;
            const size_t src = (size_t)(rowBase + k0 + r) * C_ + hc + c8;
            const uint32_t d = base + (uint32_t)(r * PQ + c8) * 2u;
            cp_async16(d,              g_kch + src);
            cp_async16(d + KVTILE,     g_kcl + src);
            cp_async16(d + 2 * KVTILE, g_vch + src);
            cp_async16(d + 3 * KVTILE, g_vcl + src);
        }
        CP_COMMIT();
    };

    issueKV(0, 0);

    const int rA = q0 + w * 16 + g;
    const int rB = rA + 8;
    const int cntA = g_cnt[rowBase + rA];
    const int cntB = g_cnt[rowBase + rB];
    const int NVq  = g_cnt[rowBase + q0 + 127];
    const int nkt  = (NVq + 63) >> 6;

    float o[8][4];
    #pragma unroll
    for (int nf = 0; nf < 8; ++nf)
        #pragma unroll
        for (int c = 0; c < 4; ++c) o[nf][c] = 0.f;
    float mA = -1e30f, mB = -1e30f, lA = 0.f, lB = 0.f;

    const int aRow = lane & 15, aCol = (lane >> 4) << 3;
    const int bR4 = ((lane >> 4) << 3) + (lane & 7);   // K (non-trans)
    const int bC4 = ((lane >> 3) & 1) << 3;
    const int vR  = lane & 15;                          // V (trans)
    const int vC4 = (lane >> 4) << 3;

    for (int kt = 0; kt < nkt; ++kt) {
        const int buf = kt & 1;
        if (kt + 1 < nkt) {
            issueKV(kt + 1, buf ^ 1);
            asm volatile("cp.async.wait_group 1;" ::: "memory");
        } else {
            asm volatile("cp.async.wait_group 0;" ::: "memory");
        }
        __syncthreads();

        const int k0 = kt * 64;
        const uint32_t KH = sb + ST_OFF + (uint32_t)buf * STAGEA;
        const uint32_t KL = KH + KVTILE;
        const uint32_t VH = KH + 2 * KVTILE;
        const uint32_t VL = KH + 3 * KVTILE;

        float s[8][4];
        #pragma unroll
        for (int nf = 0; nf < 8; ++nf)
            #pragma unroll
            for (int c = 0; c < 4; ++c) s[nf][c] = 0.f;

        #pragma unroll
        for (int kk = 0; kk < 4; ++kk) {
            const int k16 = kk * 16;
            uint32_t aqh[4], aql[4];
            ldmx4(aqh[0], aqh[1], aqh[2], aqh[3],
                  sb + QH_OFF + (uint32_t)((w * 16 + aRow) * PQ + k16 + aCol) * 2u);
            ldmx4(aql[0], aql[1], aql[2], aql[3],
                  sb + QL_OFF + (uint32_t)((w * 16 + aRow) * PQ + k16 + aCol) * 2u);
            #pragma unroll
            for (int np = 0; np < 4; ++np) {
                uint32_t bh[4], bl[4];
                const uint32_t off = (uint32_t)((np * 16 + bR4) * PQ + k16 + bC4) * 2u;
                ldmx4(bh[0], bh[1], bh[2], bh[3], KH + off);
                ldmx4(bl[0], bl[1], bl[2], bl[3], KL + off);
                mma_f16(s[2*np][0], s[2*np][1], s[2*np][2], s[2*np][3],
                        aqh[0], aqh[1], aqh[2], aqh[3], bh[0], bh[1]);
                mma_f16(s[2*np][0], s[2*np][1], s[2*np][2], s[2*np][3],
                        aqh[0], aqh[1], aqh[2], aqh[3], bl[0], bl[1]);
                mma_f16(s[2*np][0], s[2*np][1], s[2*np][2], s[2*np][3],
                        aql[0], aql[1], aql[2], aql[3], bh[0], bh[1]);
                mma_f16(s[2*np+1][0], s[2*np+1][1], s[2*np+1][2], s[2*np+1][3],
                        aqh[0], aqh[1], aqh[2], aqh[3], bh[2], bh[3]);
                mma_f16(s[2*np+1][0], s[2*np+1][1], s[2*np+1][2], s[2*np+1][3],
                        aqh[0], aqh[1], aqh[2], aqh[3], bl[2], bl[3]);
                mma_f16(s[2*np+1][0], s[2*np+1][1], s[2*np+1][2], s[2*np+1][3],
                        aql[0], aql[1], aql[2], aql[3], bh[2], bh[3]);
            }
        }

        #pragma unroll
        for (int nf = 0; nf < 8; ++nf) {
            const int c0 = k0 + nf * 8 + tig * 2;
            s[nf][0] = (c0     < cntA) ? s[nf][0] : -1e30f;
            s[nf][1] = (c0 + 1 < cntA) ? s[nf][1] : -1e30f;
            s[nf][2] = (c0     < cntB) ? s[nf][2] : -1e30f;
            s[nf][3] = (c0 + 1 < cntB) ? s[nf][3] : -1e30f;
        }

        float mxA = -1e30f, mxB = -1e30f;
        #pragma unroll
        for (int nf = 0; nf < 8; ++nf) {
            mxA = fmaxf(mxA, fmaxf(s[nf][0], s[nf][1]));
            mxB = fmaxf(mxB, fmaxf(s[nf][2], s[nf][3]));
        }
        mxA = fmaxf(mxA, __shfl_xor_sync(0xffffffffu, mxA, 1));
        mxA = fmaxf(mxA, __shfl_xor_sync(0xffffffffu, mxA, 2));
        mxB = fmaxf(mxB, __shfl_xor_sync(0xffffffffu, mxB, 1));
        mxB = fmaxf(mxB, __shfl_xor_sync(0xffffffffu, mxB, 2));
        const float mnA = fmaxf(mA, mxA), mnB = fmaxf(mB, mxB);
        const float cA = ex2f(mA - mnA), cB = ex2f(mB - mnB);
        mA = mnA; mB = mnB;
        float sA = 0.f, sB = 0.f;
        #pragma unroll
        for (int nf = 0; nf < 8; ++nf) {
            s[nf][0] = ex2f(s[nf][0] - mnA);
            s[nf][1] = ex2f(s[nf][1] - mnA);
            s[nf][2] = ex2f(s[nf][2] - mnB);
            s[nf][3] = ex2f(s[nf][3] - mnB);
            sA += s[nf][0] + s[nf][1];
            sB += s[nf][2] + s[nf][3];
        }
        sA += __shfl_xor_sync(0xffffffffu, sA, 1);
        sA += __shfl_xor_sync(0xffffffffu, sA, 2);
        sB += __shfl_xor_sync(0xffffffffu, sB, 1);
        sB += __shfl_xor_sync(0xffffffffu, sB, 2);
        lA = lA * cA + sA;
        lB = lB * cB + sB;
        #pragma unroll
        for (int nf = 0; nf < 8; ++nf) {
            o[nf][0] *= cA; o[nf][1] *= cA;
            o[nf][2] *= cB; o[nf][3] *= cB;
        }

        #pragma unroll
        for (int j = 0; j < 4; ++j) {
            uint32_t ph[4];
            ph[0] = pack_h2(s[2*j][0],   s[2*j][1]);
            ph[1] = pack_h2(s[2*j][2],   s[2*j][3]);
            ph[2] = pack_h2(s[2*j+1][0], s[2*j+1][1]);
            ph[3] = pack_h2(s[2*j+1][2], s[2*j+1][3]);
            #pragma unroll
            for (int np = 0; np < 4; ++np) {
                uint32_t bh[4], bl[4];
                const uint32_t off = (uint32_t)((j * 16 + vR) * PQ + np * 16 + vC4) * 2u;
                ldmx4t(bh[0], bh[1], bh[2], bh[3], VH + off);
                ldmx4t(bl[0], bl[1], bl[2], bl[3], VL + off);
                mma_f16(o[2*np][0], o[2*np][1], o[2*np][2], o[2*np][3],
                        ph[0], ph[1], ph[2], ph[3], bh[0], bh[1]);
                mma_f16(o[2*np][0], o[2*np][1], o[2*np][2], o[2*np][3],
                        ph[0], ph[1], ph[2], ph[3], bl[0], bl[1]);
                mma_f16(o[2*np+1][0], o[2*np+1][1], o[2*np+1][2], o[2*np+1][3],
                        ph[0], ph[1], ph[2], ph[3], bh[2], bh[3]);
                mma_f16(o[2*np+1][0], o[2*np+1][1], o[2*np+1][2], o[2*np+1][3],
                        ph[0], ph[1], ph[2], ph[3], bl[2], bl[3]);
            }
        }
        __syncthreads();
    }

    // ---- normalize, fp16-hi output for proj GEMM ----
    const float invA = 1.f / lA, invB = 1.f / lB;
    #pragma unroll
    for (int nf = 0; nf < 8; ++nf) {
        const int col = hc + nf * 8 + tig * 2;
        const size_t iA = (size_t)(rowBase + rA) * C_ + col;
        const size_t iB = iA + (size_t)8 * C_;
        *(uint32_t*)&g_ah[iA] = pack_h2(o[nf][0] * invA, o[nf][1] * invA);
        *(uint32_t*)&g_ah[iB] = pack_h2(o[nf][2] * invB, o[nf][3] * invB);
    }
}

// ---------------------------------------------------------------------------
// Launch
// ---------------------------------------------------------------------------
extern "C" void kernel_launch(void* const* d_in, const int* in_sizes, int n_in,
                              void* d_out, int out_size)
{
    const float* x  = (const float*)d_in[0];
    const int*   tm = (const int*)  d_in[1];
    const float* wq = (const float*)d_in[2];
    const float* bq = (const float*)d_in[3];
    const float* wk = (const float*)d_in[4];
    const float* bk = (const float*)d_in[5];
    const float* wv = (const float*)d_in[6];
    const float* bv = (const float*)d_in[7];
    const float* wp = (const float*)d_in[8];
    const float* bp = (const float*)d_in[9];
    float* out = (float*)d_out;

    cudaFuncSetAttribute(qkv_kernel,  cudaFuncAttributeMaxDynamicSharedMemorySize, GSMEM);
    cudaFuncSetAttribute(proj_kernel, cudaFuncAttributeMaxDynamicSharedMemorySize, GSMEM);
    cudaFuncSetAttribute(attn_kernel, cudaFuncAttributeMaxDynamicSharedMemorySize, ATT_SMEM);

    const int nTot = (NX + 4 * NW) / 1024;
    split_all_kernel<<<nTot, 256>>>(x, wq, wk, wv, wp);
    mask_scan_kernel<<<B_, 256>>>(tm);

    dim3 gGx(T_, B_);
    gather_x_kernel<<<gGx, 128>>>();

    dim3 gQKV(C_/128, M_/128, 3);
    qkv_kernel<<<gQKV, 256, GSMEM>>>(bq, bk, bv);

    dim3 gAtt(T_/128, NH_, B_);
    attn_kernel<<<gAtt, 256, ATT_SMEM>>>();

    dim3 gProj(C_/128, M_/128, 1);
    proj_kernel<<<gProj, 256, GSMEM>>>(bp, out);
}